// round 1
// baseline (speedup 1.0000x reference)
#include <cuda_runtime.h>
#include <math.h>

// ---------------- problem constants ----------------
#define B_      8
#define S_      1043            // 1024 patches + 19 cls tokens
#define NPATCH  1024
#define NCLS    19
#define D_      768
#define NH      12
#define DH      64
#define FF      3072
#define GS      32
#define IMG     512
#define M_      (B_*S_)         // 8344 total rows
#define BHD     (B_*NH)         // 96 (batch,head) pairs

static const size_t S2 = (size_t)S_ * S_;   // 1,087,849

// ---------------- scratch (static device globals; no allocs) ----------------
__device__ float g_x[(size_t)M_ * D_];       // residual stream
__device__ float g_h[(size_t)M_ * D_];       // LN output / temp
__device__ float g_q[(size_t)M_ * D_];
__device__ float g_k[(size_t)M_ * D_];
__device__ float g_v[(size_t)M_ * D_];
__device__ float g_att[(size_t)BHD * 1043 * 1043];   // ~418 MB
__device__ float g_ff[(size_t)M_ * FF];              // ~102 MB
__device__ float g_patches[(size_t)B_ * NPATCH * D_];
__device__ float g_cls[(size_t)B_ * NCLS * D_];
__device__ float g_masks[(size_t)B_ * NPATCH * NCLS];
__device__ float g_mln[(size_t)B_ * NCLS * GS * GS];

// ---------------- generic tiled GEMM: C[M,N] = A[M,K] @ W[K,N] (+epilogue) ---
// requires N % 128 == 0, K % 8 == 0. grid = (N/128, ceil(M/128), batches)
// flags: 1 = +bias, 2 = exact GELU, 4 = += existing C
__global__ void __launch_bounds__(256) gemm_kernel(
    const float* __restrict__ A, const float* __restrict__ W,
    const float* __restrict__ bias, float* __restrict__ C,
    int M, int N, int K, long strideA, long strideC, int flags)
{
    __shared__ float As[8][128];
    __shared__ float Bs[8][128];
    A += (long)blockIdx.z * strideA;
    C += (long)blockIdx.z * strideC;
    const int tid = threadIdx.x;
    const int m0 = blockIdx.y * 128;
    const int n0 = blockIdx.x * 128;
    const int tx = tid & 15, ty = tid >> 4;
    const int arow = tid >> 1, aseg = (tid & 1) * 4;
    const int brow = tid >> 5, bcol = (tid & 31) * 4;

    float acc[8][8];
#pragma unroll
    for (int i = 0; i < 8; i++)
#pragma unroll
        for (int j = 0; j < 8; j++) acc[i][j] = 0.f;

    const int gm_a = m0 + arow;
    const float* Aptr = A + (long)gm_a * K + aseg;
    const float* Wptr = W + (long)brow * N + n0 + bcol;

    for (int k0 = 0; k0 < K; k0 += 8) {
        float4 av = make_float4(0.f, 0.f, 0.f, 0.f);
        if (gm_a < M) av = *(const float4*)(Aptr + k0);
        As[aseg + 0][arow] = av.x; As[aseg + 1][arow] = av.y;
        As[aseg + 2][arow] = av.z; As[aseg + 3][arow] = av.w;
        *(float4*)&Bs[brow][bcol] = *(const float4*)(Wptr + (long)k0 * N);
        __syncthreads();
#pragma unroll
        for (int kk = 0; kk < 8; kk++) {
            float a[8], b[8];
            *(float4*)&a[0] = *(const float4*)&As[kk][ty * 8];
            *(float4*)&a[4] = *(const float4*)&As[kk][ty * 8 + 4];
            *(float4*)&b[0] = *(const float4*)&Bs[kk][tx * 8];
            *(float4*)&b[4] = *(const float4*)&Bs[kk][tx * 8 + 4];
#pragma unroll
            for (int i = 0; i < 8; i++)
#pragma unroll
                for (int j = 0; j < 8; j++)
                    acc[i][j] = fmaf(a[i], b[j], acc[i][j]);
        }
        __syncthreads();
    }

#pragma unroll
    for (int i = 0; i < 8; i++) {
        int gm = m0 + ty * 8 + i;
        if (gm >= M) continue;
#pragma unroll
        for (int j = 0; j < 8; j++) {
            int gn = n0 + tx * 8 + j;
            float v = acc[i][j];
            if (flags & 1) v += bias[gn];
            if (flags & 2) v = 0.5f * v * (1.f + erff(v * 0.70710678118654752f));
            float* cp = C + (long)gm * N + gn;
            if (flags & 4) v += *cp;
            *cp = v;
        }
    }
}

// ---------------- per-head QKV projection --------------------------------
// out[m, h*64+e] = sum_d in[m, h*64+d] * W[h,d,e] + b[h,e]
// grid = (ceil(M/64), 12 heads, 3 {q,k,v}), block 256
__global__ void __launch_bounds__(256) qkv_kernel(
    const float* __restrict__ h,
    const float* __restrict__ qW, const float* __restrict__ kW, const float* __restrict__ vW,
    const float* __restrict__ qb, const float* __restrict__ kb, const float* __restrict__ vb)
{
    __shared__ float in_s[64][65];
    __shared__ float w_s[64][64];
    const int hd = blockIdx.y;
    const int z = blockIdx.z;
    const float* W    = (z == 0 ? qW : z == 1 ? kW : vW) + hd * DH * DH;
    const float* bias = (z == 0 ? qb : z == 1 ? kb : vb) + hd * DH;
    float* out        = (z == 0 ? g_q : z == 1 ? g_k : g_v);
    const int m0 = blockIdx.x * 64;
    const int tid = threadIdx.x;

#pragma unroll
    for (int i = 0; i < 4; i++) {
        int f = i * 256 + tid;            // float4 index, 0..1023
        int row = f >> 4;
        int c4 = (f & 15) * 4;
        float4 v = make_float4(0.f, 0.f, 0.f, 0.f);
        int gm = m0 + row;
        if (gm < M_) v = *(const float4*)(h + (long)gm * D_ + hd * DH + c4);
        in_s[row][c4 + 0] = v.x; in_s[row][c4 + 1] = v.y;
        in_s[row][c4 + 2] = v.z; in_s[row][c4 + 3] = v.w;
        *(float4*)&w_s[row][c4] = *(const float4*)(W + row * DH + c4);
    }
    __syncthreads();

    const int tx = tid & 15, ty = tid >> 4;
    float acc[4][4];
#pragma unroll
    for (int i = 0; i < 4; i++)
#pragma unroll
        for (int j = 0; j < 4; j++) acc[i][j] = 0.f;

#pragma unroll 8
    for (int d = 0; d < 64; d++) {
        float a[4], b[4];
#pragma unroll
        for (int i = 0; i < 4; i++) a[i] = in_s[ty * 4 + i][d];
        *(float4*)&b[0] = *(const float4*)&w_s[d][tx * 4];
#pragma unroll
        for (int i = 0; i < 4; i++)
#pragma unroll
            for (int j = 0; j < 4; j++)
                acc[i][j] = fmaf(a[i], b[j], acc[i][j]);
    }

#pragma unroll
    for (int i = 0; i < 4; i++) {
        int gm = m0 + ty * 4 + i;
        if (gm >= M_) continue;
#pragma unroll
        for (int j = 0; j < 4; j++)
            out[(long)gm * D_ + hd * DH + tx * 4 + j] = acc[i][j] + bias[tx * 4 + j];
    }
}

// ---------------- attention scores: att[bh,q,k] = (Q·K)/8 ----------------
// grid = (17 k-tiles, 17 q-tiles, 96 bh)
__global__ void __launch_bounds__(256) attn_scores_kernel()
{
    __shared__ float qs[64][65];
    __shared__ float ks[64][65];
    const int z = blockIdx.z;
    const int b = z / NH, hd = z % NH;
    const int q0 = blockIdx.y * 64;
    const int k0 = blockIdx.x * 64;
    const int tid = threadIdx.x;

#pragma unroll
    for (int i = 0; i < 4; i++) {
        int f = i * 256 + tid;
        int row = f >> 4;
        int c4 = (f & 15) * 4;
        float4 qv = make_float4(0.f, 0.f, 0.f, 0.f);
        float4 kv = make_float4(0.f, 0.f, 0.f, 0.f);
        int gq = q0 + row, gk = k0 + row;
        if (gq < S_) qv = *(const float4*)(g_q + (long)(b * S_ + gq) * D_ + hd * DH + c4);
        if (gk < S_) kv = *(const float4*)(g_k + (long)(b * S_ + gk) * D_ + hd * DH + c4);
        qs[row][c4 + 0] = qv.x; qs[row][c4 + 1] = qv.y;
        qs[row][c4 + 2] = qv.z; qs[row][c4 + 3] = qv.w;
        ks[row][c4 + 0] = kv.x; ks[row][c4 + 1] = kv.y;
        ks[row][c4 + 2] = kv.z; ks[row][c4 + 3] = kv.w;
    }
    __syncthreads();

    const int tx = tid & 15, ty = tid >> 4;
    float acc[4][4];
#pragma unroll
    for (int i = 0; i < 4; i++)
#pragma unroll
        for (int j = 0; j < 4; j++) acc[i][j] = 0.f;

#pragma unroll 8
    for (int d = 0; d < 64; d++) {
        float a[4], b[4];
#pragma unroll
        for (int i = 0; i < 4; i++) a[i] = qs[ty * 4 + i][d];
#pragma unroll
        for (int j = 0; j < 4; j++) b[j] = ks[tx * 4 + j][d];
#pragma unroll
        for (int i = 0; i < 4; i++)
#pragma unroll
            for (int j = 0; j < 4; j++)
                acc[i][j] = fmaf(a[i], b[j], acc[i][j]);
    }

    float* outp = g_att + (size_t)z * S2;
#pragma unroll
    for (int i = 0; i < 4; i++) {
        int gq = q0 + ty * 4 + i;
        if (gq >= S_) continue;
#pragma unroll
        for (int j = 0; j < 4; j++) {
            int gk = k0 + tx * 4 + j;
            if (gk < S_) outp[(size_t)gq * S_ + gk] = acc[i][j] * 0.125f;
        }
    }
}

// ---------------- row softmax over g_att ---------------------------------
// grid = (1043 rows, 96 bh), block 256
__global__ void __launch_bounds__(256) softmax_kernel()
{
    const int z = blockIdx.y;
    float* p = g_att + (size_t)z * S2 + (size_t)blockIdx.x * S_;
    __shared__ float red[256];
    const int tid = threadIdx.x;

    float m = -1e30f;
    for (int i = tid; i < S_; i += 256) m = fmaxf(m, p[i]);
    red[tid] = m; __syncthreads();
    for (int s = 128; s > 0; s >>= 1) {
        if (tid < s) red[tid] = fmaxf(red[tid], red[tid + s]);
        __syncthreads();
    }
    m = red[0]; __syncthreads();

    float sum = 0.f;
    for (int i = tid; i < S_; i += 256) {
        float e = __expf(p[i] - m);
        p[i] = e;
        sum += e;
    }
    red[tid] = sum; __syncthreads();
    for (int s = 128; s > 0; s >>= 1) {
        if (tid < s) red[tid] += red[tid + s];
        __syncthreads();
    }
    float inv = 1.f / red[0];
    for (int i = tid; i < S_; i += 256) p[i] *= inv;
}

// ---------------- AV + residual add into g_x -----------------------------
// grid = (17 q-tiles, 96 bh)
__global__ void __launch_bounds__(256) attn_av_kernel()
{
    __shared__ float ps[64][65];
    __shared__ float vs[64][64];
    const int z = blockIdx.y;
    const int b = z / NH, hd = z % NH;
    const int q0 = blockIdx.x * 64;
    const int tid = threadIdx.x;
    const int tx = tid & 15, ty = tid >> 4;
    const float* attp = g_att + (size_t)z * S2;

    float acc[4][4];
#pragma unroll
    for (int i = 0; i < 4; i++)
#pragma unroll
        for (int j = 0; j < 4; j++) acc[i][j] = 0.f;

    for (int k0 = 0; k0 < S_; k0 += 64) {
#pragma unroll
        for (int i = 0; i < 16; i++) {          // 64x64 P tile, scalar coalesced
            int f = i * 256 + tid;
            int row = f >> 6, col = f & 63;
            int gq = q0 + row, gk = k0 + col;
            float v = 0.f;
            if (gq < S_ && gk < S_) v = attp[(size_t)gq * S_ + gk];
            ps[row][col] = v;
        }
#pragma unroll
        for (int i = 0; i < 4; i++) {           // 64x64 V tile, float4
            int f = i * 256 + tid;
            int row = f >> 4, c4 = (f & 15) * 4;
            float4 v = make_float4(0.f, 0.f, 0.f, 0.f);
            int gk = k0 + row;
            if (gk < S_) v = *(const float4*)(g_v + (long)(b * S_ + gk) * D_ + hd * DH + c4);
            *(float4*)&vs[row][c4] = v;
        }
        __syncthreads();
#pragma unroll 8
        for (int kk = 0; kk < 64; kk++) {
            float a[4], bb[4];
#pragma unroll
            for (int i = 0; i < 4; i++) a[i] = ps[ty * 4 + i][kk];
            *(float4*)&bb[0] = *(const float4*)&vs[kk][tx * 4];
#pragma unroll
            for (int i = 0; i < 4; i++)
#pragma unroll
                for (int j = 0; j < 4; j++)
                    acc[i][j] = fmaf(a[i], bb[j], acc[i][j]);
        }
        __syncthreads();
    }

#pragma unroll
    for (int i = 0; i < 4; i++) {
        int gq = q0 + ty * 4 + i;
        if (gq >= S_) continue;
#pragma unroll
        for (int j = 0; j < 4; j++) {
            float* xp = g_x + (long)(b * S_ + gq) * D_ + hd * DH + tx * 4 + j;
            *xp += acc[i][j];
        }
    }
}

// ---------------- LayerNorm over d=768 -----------------------------------
// grid = num_rows, block 256
__global__ void __launch_bounds__(256) ln_kernel(
    const float* __restrict__ x, const float* __restrict__ g,
    const float* __restrict__ bta, float* __restrict__ out)
{
    const long r = blockIdx.x;
    const float* xr = x + r * D_;
    float* orow = out + r * D_;
    __shared__ float red[256];
    __shared__ float red2[256];
    const int tid = threadIdx.x;
    float v0 = xr[tid], v1 = xr[tid + 256], v2 = xr[tid + 512];
    red[tid]  = v0 + v1 + v2;
    red2[tid] = v0 * v0 + v1 * v1 + v2 * v2;
    __syncthreads();
    for (int s = 128; s > 0; s >>= 1) {
        if (tid < s) { red[tid] += red[tid + s]; red2[tid] += red2[tid + s]; }
        __syncthreads();
    }
    float mean = red[0] * (1.f / 768.f);
    float var  = red2[0] * (1.f / 768.f) - mean * mean;
    float inv  = rsqrtf(var + 1e-5f);
    orow[tid]       = (v0 - mean) * inv * g[tid]       + bta[tid];
    orow[tid + 256] = (v1 - mean) * inv * g[tid + 256] + bta[tid + 256];
    orow[tid + 512] = (v2 - mean) * inv * g[tid + 512] + bta[tid + 512];
}

// ---------------- L2 row normalize (in place), d=768 ----------------------
__global__ void __launch_bounds__(256) l2norm_kernel(float* __restrict__ x)
{
    const long r = blockIdx.x;
    float* xr = x + r * D_;
    __shared__ float red[256];
    const int tid = threadIdx.x;
    float v0 = xr[tid], v1 = xr[tid + 256], v2 = xr[tid + 512];
    red[tid] = v0 * v0 + v1 * v1 + v2 * v2;
    __syncthreads();
    for (int s = 128; s > 0; s >>= 1) {
        if (tid < s) red[tid] += red[tid + s];
        __syncthreads();
    }
    float inv = rsqrtf(red[0]);
    xr[tid] = v0 * inv; xr[tid + 256] = v1 * inv; xr[tid + 512] = v2 * inv;
}

// ---------------- broadcast cls_emb into g_x cls rows ----------------------
__global__ void fill_cls_kernel(const float* __restrict__ cls_emb)
{
    int idx = blockIdx.x * 256 + threadIdx.x;    // over NCLS*D_
    if (idx >= NCLS * D_) return;
    float v = cls_emb[idx];
    int c = idx / D_, d = idx % D_;
#pragma unroll
    for (int b = 0; b < B_; b++)
        g_x[(long)(b * S_ + NPATCH + c) * D_ + d] = v;
}

// ---------------- masks[b,n,c] = patches[b,n,:] . cls[b,c,:] --------------
// grid = (16 token-tiles, 8 batches), block 256
__global__ void __launch_bounds__(256) masks_kernel()
{
    __shared__ float pt[64][128];
    __shared__ float cs[NCLS][128];
    const int b = blockIdx.y;
    const int t0 = blockIdx.x * 64;
    const int tid = threadIdx.x;
    float acc[5];
#pragma unroll
    for (int i = 0; i < 5; i++) acc[i] = 0.f;

    for (int d0 = 0; d0 < D_; d0 += 128) {
#pragma unroll
        for (int i = 0; i < 8; i++) {
            int f = i * 256 + tid;
            int row = f >> 5, c4 = (f & 31) * 4;
            *(float4*)&pt[row][c4] =
                *(const float4*)(g_patches + (long)(b * NPATCH + t0 + row) * D_ + d0 + c4);
        }
        for (int f = tid; f < NCLS * 32; f += 256) {
            int row = f >> 5, c4 = (f & 31) * 4;
            *(float4*)&cs[row][c4] =
                *(const float4*)(g_cls + (long)(b * NCLS + row) * D_ + d0 + c4);
        }
        __syncthreads();
#pragma unroll
        for (int i = 0; i < 5; i++) {
            int p = i * 256 + tid;
            if (p < 64 * NCLS) {
                int tok = p / NCLS, c = p % NCLS;
                float s = acc[i];
#pragma unroll 8
                for (int d = 0; d < 128; d++)
                    s = fmaf(pt[tok][d], cs[c][d], s);
                acc[i] = s;
            }
        }
        __syncthreads();
    }
#pragma unroll
    for (int i = 0; i < 5; i++) {
        int p = i * 256 + tid;
        if (p < 64 * NCLS) {
            int tok = p / NCLS, c = p % NCLS;
            g_masks[((long)b * NPATCH + t0 + tok) * NCLS + c] = acc[i];
        }
    }
}

// ---------------- mask LN over 19 classes + layout to [b,c,gy,gx] ---------
// one warp per token; grid = 8192/8 = 1024, block 256
__global__ void __launch_bounds__(256) maskln_kernel(
    const float* __restrict__ mg, const float* __restrict__ mb)
{
    const int warp = threadIdx.x >> 5, lane = threadIdx.x & 31;
    const int token = blockIdx.x * 8 + warp;     // 0..8191
    const int b = token >> 10, n = token & 1023;
    float v = 0.f;
    if (lane < NCLS) v = g_masks[(long)token * NCLS + lane];
    float s = v;
#pragma unroll
    for (int o = 16; o > 0; o >>= 1) s += __shfl_xor_sync(0xffffffff, s, o);
    float mean = s * (1.f / (float)NCLS);
    float d = (lane < NCLS) ? v - mean : 0.f;
    float s2 = d * d;
#pragma unroll
    for (int o = 16; o > 0; o >>= 1) s2 += __shfl_xor_sync(0xffffffff, s2, o);
    float inv = rsqrtf(s2 * (1.f / (float)NCLS) + 1e-5f);
    if (lane < NCLS) {
        float o = d * inv * mg[lane] + mb[lane];
        int gy = n >> 5, gx = n & 31;
        g_mln[(((long)b * NCLS + lane) * GS + gy) * GS + gx] = o;
    }
}

// ---------------- bilinear 32x32 -> 512x512 (jax half-pixel) --------------
// grid = (512*512/256, 19, 8), block 256
__global__ void __launch_bounds__(256) resize_kernel(float* __restrict__ out)
{
    const int pix = blockIdx.x * 256 + threadIdx.x;   // < 262144
    const int c = blockIdx.y, b = blockIdx.z;
    const int ox = pix & 511, oy = pix >> 9;
    float fx = (ox + 0.5f) * 0.0625f - 0.5f;
    float fy = (oy + 0.5f) * 0.0625f - 0.5f;
    int ix0 = (int)floorf(fx), iy0 = (int)floorf(fy);
    float wx = fx - (float)ix0, wy = fy - (float)iy0;
    int x0 = max(ix0, 0), x1 = min(ix0 + 1, GS - 1);
    int y0 = max(iy0, 0), y1 = min(iy0 + 1, GS - 1);
    const float* m = g_mln + ((long)b * NCLS + c) * GS * GS;
    float v00 = m[y0 * GS + x0], v01 = m[y0 * GS + x1];
    float v10 = m[y1 * GS + x0], v11 = m[y1 * GS + x1];
    float v = (1.f - wy) * ((1.f - wx) * v00 + wx * v01)
            +        wy  * ((1.f - wx) * v10 + wx * v11);
    out[(((long)b * NCLS + c) * IMG + oy) * IMG + ox] = v;
}

// ---------------- host orchestration --------------------------------------
static float* sym_addr(const void* sym)
{
    void* p = nullptr;
    cudaGetSymbolAddress(&p, sym);
    return (float*)p;
}

extern "C" void kernel_launch(void* const* d_in, const int* in_sizes, int n_in,
                              void* d_out, int out_size)
{
    (void)in_sizes; (void)n_in; (void)out_size;
    const float* x    = (const float*)d_in[0];
    const float* pdW  = (const float*)d_in[1];
    const float* pdb  = (const float*)d_in[2];
    const float* cls  = (const float*)d_in[3];
    const float* l1g  = (const float*)d_in[4];
    const float* l1b  = (const float*)d_in[5];
    const float* qW   = (const float*)d_in[6];
    const float* qb   = (const float*)d_in[7];
    const float* kW   = (const float*)d_in[8];
    const float* kb   = (const float*)d_in[9];
    const float* vW   = (const float*)d_in[10];
    const float* vb   = (const float*)d_in[11];
    const float* l2g  = (const float*)d_in[12];
    const float* l2b  = (const float*)d_in[13];
    const float* w1   = (const float*)d_in[14];
    const float* b1   = (const float*)d_in[15];
    const float* w2   = (const float*)d_in[16];
    const float* b2   = (const float*)d_in[17];
    const float* ppW  = (const float*)d_in[18];
    const float* pcW  = (const float*)d_in[19];
    const float* dg   = (const float*)d_in[20];
    const float* db   = (const float*)d_in[21];
    const float* mg   = (const float*)d_in[22];
    const float* mb   = (const float*)d_in[23];
    float* out = (float*)d_out;

    float* gx  = sym_addr(g_x);
    float* gh  = sym_addr(g_h);
    float* gff = sym_addr(g_ff);
    float* gpt = sym_addr(g_patches);
    float* gcl = sym_addr(g_cls);

    const dim3 blk(256);
    const int mtiles = (M_ + 127) / 128;   // 66

    // x @ proj_dec_W + b  -> g_x patch rows (batched over 8 images)
    gemm_kernel<<<dim3(D_ / 128, NPATCH / 128, B_), blk>>>(
        x, pdW, pdb, gx, NPATCH, D_, D_,
        (long)NPATCH * D_, (long)S_ * D_, 1);
    fill_cls_kernel<<<(NCLS * D_ + 255) / 256, 256>>>(cls);

    for (int l = 0; l < 2; l++) {
        ln_kernel<<<M_, blk>>>(gx, l1g + l * D_, l1b + l * D_, gh);
        qkv_kernel<<<dim3((M_ + 63) / 64, NH, 3), blk>>>(
            gh,
            qW + (long)l * NH * DH * DH, kW + (long)l * NH * DH * DH, vW + (long)l * NH * DH * DH,
            qb + (long)l * NH * DH,      kb + (long)l * NH * DH,      vb + (long)l * NH * DH);
        attn_scores_kernel<<<dim3(17, 17, BHD), blk>>>();
        softmax_kernel<<<dim3(S_, BHD), blk>>>();
        attn_av_kernel<<<dim3(17, BHD), blk>>>();     // += into g_x

        ln_kernel<<<M_, blk>>>(gx, l2g + l * D_, l2b + l * D_, gh);
        gemm_kernel<<<dim3(FF / 128, mtiles, 1), blk>>>(
            gh, w1 + (long)l * D_ * FF, b1 + (long)l * FF, gff,
            M_, FF, D_, 0, 0, 1 | 2);                 // bias + GELU
        gemm_kernel<<<dim3(D_ / 128, mtiles, 1), blk>>>(
            gff, w2 + (long)l * FF * D_, b2 + (long)l * D_, gx,
            M_, D_, FF, 0, 0, 1 | 4);                 // bias + residual add
    }

    // decoder LN
    ln_kernel<<<M_, blk>>>(gx, dg, db, gh);

    // patches @ proj_patch (per batch), cls_feat @ proj_classes (per batch)
    gemm_kernel<<<dim3(D_ / 128, NPATCH / 128, B_), blk>>>(
        gh, ppW, nullptr, gpt, NPATCH, D_, D_,
        (long)S_ * D_, (long)NPATCH * D_, 0);
    gemm_kernel<<<dim3(D_ / 128, 1, B_), blk>>>(
        gh + (long)NPATCH * D_, pcW, nullptr, gcl, NCLS, D_, D_,
        (long)S_ * D_, (long)NCLS * D_, 0);

    l2norm_kernel<<<B_ * NPATCH, blk>>>(gpt);
    l2norm_kernel<<<B_ * NCLS, blk>>>(gcl);

    masks_kernel<<<dim3(NPATCH / 64, B_), blk>>>();
    maskln_kernel<<<(B_ * NPATCH) / 8, blk>>>(mg, mb);
    resize_kernel<<<dim3(IMG * IMG / 256, NCLS, B_), blk>>>(out);
}

// round 2
// speedup vs baseline: 1.7742x; 1.7742x over previous
#include <cuda_runtime.h>
#include <math.h>

// ---------------- problem constants ----------------
#define B_      8
#define S_      1043            // 1024 patches + 19 cls tokens
#define SP      1044            // padded row stride for attention matrix
#define NPATCH  1024
#define NCLS    19
#define D_      768
#define NH      12
#define DH      64
#define FF      3072
#define GS      32
#define IMG     512
#define M_      (B_*S_)         // 8344 total rows
#define BHD     (B_*NH)         // 96 (batch,head) pairs
#define KC      16              // k-chunk for mma gemm

static const size_t S2P = (size_t)S_ * SP;   // padded score-matrix size per (b,h)

// ---------------- scratch (static device globals; no allocs) ----------------
__device__ float g_x[(size_t)M_ * D_];       // residual stream
__device__ float g_h[(size_t)M_ * D_];       // LN output / temp
__device__ float g_q[(size_t)M_ * D_];
__device__ float g_k[(size_t)M_ * D_];
__device__ float g_v[(size_t)M_ * D_];
__device__ float g_att[(size_t)BHD * S_ * SP];       // ~418 MB
__device__ float g_ff[(size_t)M_ * FF];              // ~102 MB
__device__ float g_patches[(size_t)B_ * NPATCH * D_];
__device__ float g_cls[(size_t)B_ * NCLS * D_];
__device__ float g_masks[(size_t)B_ * NPATCH * NCLS];
__device__ float g_mln[(size_t)B_ * NCLS * GS * GS];

// ---------------- helpers --------------------------------------------------
__device__ __forceinline__ unsigned f2tf(float x) {
    unsigned r;
    asm("cvt.rna.tf32.f32 %0, %1;" : "=r"(r) : "f"(x));
    return r;
}
__device__ __forceinline__ float gelu_exact(float v) {
    return 0.5f * v * (1.f + erff(v * 0.70710678118654752f));
}

// ---------------- TF32 tensor-core GEMM ------------------------------------
// C[M,N] = A[M,K] @ B[K,N] (TB=false)   or   A[M,K] @ Bm[N,K]^T (TB=true)
// block tile: 128 x BN (BN = 128 or 64), 8 warps, warp tile 32 x (BN/2)
// grid = (ceil(N/BN), ceil(M/128), Z). per-Z offsets: z -> (z/HZ, z%HZ) two-level.
// flags: 1 = +bias, 2 = exact GELU, 4 = += existing C
template<int BN, bool TB>
__global__ void __launch_bounds__(256) mma_gemm(
    const float* __restrict__ A, const float* __restrict__ Bm,
    const float* __restrict__ bias, float* __restrict__ C,
    int M, int N, int K, int lda, int ldb, int ldc,
    int HZ, long sA, long hA, long sB, long hB, long sC, long hC,
    int flags)
{
    constexpr int NT   = BN / 16;     // n-tiles (of 8) per warp
    constexpr int BSTR = BN + 4;
    constexpr int EB   = BN / 16;     // B elements per thread per chunk

    __shared__ float As[128][KC + 1];
    __shared__ float Bs[KC][BSTR];

    const int z = blockIdx.z;
    A  += (long)(z / HZ) * sA + (long)(z % HZ) * hA;
    Bm += (long)(z / HZ) * sB + (long)(z % HZ) * hB;
    C  += (long)(z / HZ) * sC + (long)(z % HZ) * hC;

    const int tid  = threadIdx.x;
    const int warp = tid >> 5, lane = tid & 31;
    const int wm = warp & 3, wn = warp >> 2;      // 4 x 2 warp grid
    const int l4 = lane >> 2, lm = lane & 3;
    const int m0 = blockIdx.y * 128, n0 = blockIdx.x * BN;

    float areg[8], breg[EB];
    float acc[2][NT][4];
#pragma unroll
    for (int i = 0; i < 2; i++)
#pragma unroll
        for (int j = 0; j < NT; j++)
#pragma unroll
            for (int c = 0; c < 4; c++) acc[i][j][c] = 0.f;

    auto loadA = [&](int k0) {
#pragma unroll
        for (int i = 0; i < 8; i++) {
            int idx = i * 256 + tid;
            int m = idx >> 4, k = idx & 15;
            int gm = m0 + m, gk = k0 + k;
            areg[i] = (gm < M && gk < K) ? A[(long)gm * lda + gk] : 0.f;
        }
    };
    auto loadB = [&](int k0) {
#pragma unroll
        for (int i = 0; i < EB; i++) {
            int idx = i * 256 + tid;
            if (TB) {
                int n = idx >> 4, k = idx & 15;
                int gn = n0 + n, gk = k0 + k;
                breg[i] = (gn < N && gk < K) ? Bm[(long)gn * ldb + gk] : 0.f;
            } else {
                int k = idx / BN, n = idx % BN;
                int gk = k0 + k, gn = n0 + n;
                breg[i] = (gk < K && gn < N) ? Bm[(long)gk * ldb + gn] : 0.f;
            }
        }
    };
    auto store_smem = [&]() {
#pragma unroll
        for (int i = 0; i < 8; i++) {
            int idx = i * 256 + tid;
            int m = idx >> 4, k = idx & 15;
            As[m][k] = __uint_as_float(f2tf(areg[i]));
        }
#pragma unroll
        for (int i = 0; i < EB; i++) {
            int idx = i * 256 + tid;
            int k, n;
            if (TB) { n = idx >> 4; k = idx & 15; }
            else    { k = idx / BN; n = idx % BN; }
            Bs[k][n] = __uint_as_float(f2tf(breg[i]));
        }
    };
    auto compute = [&]() {
#pragma unroll
        for (int kk = 0; kk < KC; kk += 8) {
            unsigned af[2][4];
#pragma unroll
            for (int i = 0; i < 2; i++) {
                int r = wm * 32 + i * 16 + l4;
                af[i][0] = __float_as_uint(As[r][kk + lm]);
                af[i][1] = __float_as_uint(As[r + 8][kk + lm]);
                af[i][2] = __float_as_uint(As[r][kk + lm + 4]);
                af[i][3] = __float_as_uint(As[r + 8][kk + lm + 4]);
            }
            unsigned bf[NT][2];
#pragma unroll
            for (int j = 0; j < NT; j++) {
                int n = wn * (BN / 2) + j * 8 + l4;
                bf[j][0] = __float_as_uint(Bs[kk + lm][n]);
                bf[j][1] = __float_as_uint(Bs[kk + lm + 4][n]);
            }
#pragma unroll
            for (int i = 0; i < 2; i++)
#pragma unroll
                for (int j = 0; j < NT; j++) {
                    asm volatile(
                        "mma.sync.aligned.m16n8k8.row.col.f32.tf32.tf32.f32 "
                        "{%0,%1,%2,%3},{%4,%5,%6,%7},{%8,%9},{%0,%1,%2,%3};"
                        : "+f"(acc[i][j][0]), "+f"(acc[i][j][1]),
                          "+f"(acc[i][j][2]), "+f"(acc[i][j][3])
                        : "r"(af[i][0]), "r"(af[i][1]), "r"(af[i][2]), "r"(af[i][3]),
                          "r"(bf[j][0]), "r"(bf[j][1]));
                }
        }
    };

    loadA(0); loadB(0);
    store_smem();
    __syncthreads();
    for (int k0 = KC;; k0 += KC) {
        bool more = k0 < K;
        if (more) { loadA(k0); loadB(k0); }   // prefetch overlaps compute
        compute();
        if (!more) break;
        __syncthreads();
        store_smem();
        __syncthreads();
    }

    // epilogue
    const bool even_ldc = ((ldc & 1) == 0);
#pragma unroll
    for (int i = 0; i < 2; i++)
#pragma unroll
        for (int j = 0; j < NT; j++)
#pragma unroll
            for (int h = 0; h < 2; h++) {
                int row = m0 + wm * 32 + i * 16 + l4 + h * 8;
                if (row >= M) continue;
                int col = n0 + wn * (BN / 2) + j * 8 + lm * 2;
                if (col >= N) continue;
                float v0 = acc[i][j][h * 2 + 0];
                float v1 = acc[i][j][h * 2 + 1];
                bool pair = even_ldc && (col + 1 < N);
                if (flags & 1) {
                    v0 += bias[col];
                    if (col + 1 < N) v1 += bias[col + 1];
                }
                if (flags & 2) { v0 = gelu_exact(v0); v1 = gelu_exact(v1); }
                float* cp = C + (long)row * ldc + col;
                if (pair) {
                    if (flags & 4) { float2 old = *(float2*)cp; v0 += old.x; v1 += old.y; }
                    float2 st; st.x = v0; st.y = v1;
                    *(float2*)cp = st;
                } else {
                    if (flags & 4) v0 += cp[0];
                    cp[0] = v0;
                    if (col + 1 < N) {
                        if (flags & 4) v1 += cp[1];
                        cp[1] = v1;
                    }
                }
            }
}

// ---------------- per-head QKV projection (q pre-scaled by 1/8) ------------
__global__ void __launch_bounds__(256) qkv_kernel(
    const float* __restrict__ h,
    const float* __restrict__ qW, const float* __restrict__ kW, const float* __restrict__ vW,
    const float* __restrict__ qb, const float* __restrict__ kb, const float* __restrict__ vb)
{
    __shared__ float in_s[64][65];
    __shared__ float w_s[64][64];
    const int hd = blockIdx.y;
    const int z = blockIdx.z;
    const float* W    = (z == 0 ? qW : z == 1 ? kW : vW) + hd * DH * DH;
    const float* bias = (z == 0 ? qb : z == 1 ? kb : vb) + hd * DH;
    float* out        = (z == 0 ? g_q : z == 1 ? g_k : g_v);
    const float scale = (z == 0) ? 0.125f : 1.f;
    const int m0 = blockIdx.x * 64;
    const int tid = threadIdx.x;

#pragma unroll
    for (int i = 0; i < 4; i++) {
        int f = i * 256 + tid;
        int row = f >> 4;
        int c4 = (f & 15) * 4;
        float4 v = make_float4(0.f, 0.f, 0.f, 0.f);
        int gm = m0 + row;
        if (gm < M_) v = *(const float4*)(h + (long)gm * D_ + hd * DH + c4);
        in_s[row][c4 + 0] = v.x; in_s[row][c4 + 1] = v.y;
        in_s[row][c4 + 2] = v.z; in_s[row][c4 + 3] = v.w;
        *(float4*)&w_s[row][c4] = *(const float4*)(W + row * DH + c4);
    }
    __syncthreads();

    const int tx = tid & 15, ty = tid >> 4;
    float acc[4][4];
#pragma unroll
    for (int i = 0; i < 4; i++)
#pragma unroll
        for (int j = 0; j < 4; j++) acc[i][j] = 0.f;

#pragma unroll 8
    for (int d = 0; d < 64; d++) {
        float a[4], b[4];
#pragma unroll
        for (int i = 0; i < 4; i++) a[i] = in_s[ty * 4 + i][d];
        *(float4*)&b[0] = *(const float4*)&w_s[d][tx * 4];
#pragma unroll
        for (int i = 0; i < 4; i++)
#pragma unroll
            for (int j = 0; j < 4; j++)
                acc[i][j] = fmaf(a[i], b[j], acc[i][j]);
    }

#pragma unroll
    for (int i = 0; i < 4; i++) {
        int gm = m0 + ty * 4 + i;
        if (gm >= M_) continue;
#pragma unroll
        for (int j = 0; j < 4; j++)
            out[(long)gm * D_ + hd * DH + tx * 4 + j] =
                (acc[i][j] + bias[tx * 4 + j]) * scale;
    }
}

// ---------------- single-pass smem row softmax over g_att -------------------
// grid = (1043 rows, 96 bh), block 256
__global__ void __launch_bounds__(256) softmax_kernel()
{
    __shared__ float row[S_];
    __shared__ float red[256];
    const int z = blockIdx.y;
    float* p = g_att + (size_t)z * S2P + (size_t)blockIdx.x * SP;
    const int tid = threadIdx.x;

    float m = -1e30f;
    for (int i = tid; i < S_; i += 256) {
        float v = p[i];
        row[i] = v;
        m = fmaxf(m, v);
    }
    red[tid] = m; __syncthreads();
    for (int s = 128; s > 0; s >>= 1) {
        if (tid < s) red[tid] = fmaxf(red[tid], red[tid + s]);
        __syncthreads();
    }
    m = red[0]; __syncthreads();

    float sum = 0.f;
    for (int i = tid; i < S_; i += 256) {
        float e = __expf(row[i] - m);
        row[i] = e;
        sum += e;
    }
    red[tid] = sum; __syncthreads();
    for (int s = 128; s > 0; s >>= 1) {
        if (tid < s) red[tid] += red[tid + s];
        __syncthreads();
    }
    float inv = 1.f / red[0];
    for (int i = tid; i < S_; i += 256) p[i] = row[i] * inv;
}

// ---------------- LayerNorm over d=768 -------------------------------------
__global__ void __launch_bounds__(256) ln_kernel(
    const float* __restrict__ x, const float* __restrict__ g,
    const float* __restrict__ bta, float* __restrict__ out)
{
    const long r = blockIdx.x;
    const float* xr = x + r * D_;
    float* orow = out + r * D_;
    __shared__ float red[256];
    __shared__ float red2[256];
    const int tid = threadIdx.x;
    float v0 = xr[tid], v1 = xr[tid + 256], v2 = xr[tid + 512];
    red[tid]  = v0 + v1 + v2;
    red2[tid] = v0 * v0 + v1 * v1 + v2 * v2;
    __syncthreads();
    for (int s = 128; s > 0; s >>= 1) {
        if (tid < s) { red[tid] += red[tid + s]; red2[tid] += red2[tid + s]; }
        __syncthreads();
    }
    float mean = red[0] * (1.f / 768.f);
    float var  = red2[0] * (1.f / 768.f) - mean * mean;
    float inv  = rsqrtf(var + 1e-5f);
    orow[tid]       = (v0 - mean) * inv * g[tid]       + bta[tid];
    orow[tid + 256] = (v1 - mean) * inv * g[tid + 256] + bta[tid + 256];
    orow[tid + 512] = (v2 - mean) * inv * g[tid + 512] + bta[tid + 512];
}

// ---------------- L2 row normalize (in place), d=768 ------------------------
__global__ void __launch_bounds__(256) l2norm_kernel(float* __restrict__ x)
{
    const long r = blockIdx.x;
    float* xr = x + r * D_;
    __shared__ float red[256];
    const int tid = threadIdx.x;
    float v0 = xr[tid], v1 = xr[tid + 256], v2 = xr[tid + 512];
    red[tid] = v0 * v0 + v1 * v1 + v2 * v2;
    __syncthreads();
    for (int s = 128; s > 0; s >>= 1) {
        if (tid < s) red[tid] += red[tid + s];
        __syncthreads();
    }
    float inv = rsqrtf(red[0]);
    xr[tid] = v0 * inv; xr[tid + 256] = v1 * inv; xr[tid + 512] = v2 * inv;
}

// ---------------- broadcast cls_emb into g_x cls rows -----------------------
__global__ void fill_cls_kernel(const float* __restrict__ cls_emb)
{
    int idx = blockIdx.x * 256 + threadIdx.x;
    if (idx >= NCLS * D_) return;
    float v = cls_emb[idx];
    int c = idx / D_, d = idx % D_;
#pragma unroll
    for (int b = 0; b < B_; b++)
        g_x[(long)(b * S_ + NPATCH + c) * D_ + d] = v;
}

// ---------------- masks[b,n,c] = patches[b,n,:] . cls[b,c,:] (fp32) ---------
__global__ void __launch_bounds__(256) masks_kernel()
{
    __shared__ float pt[64][128];
    __shared__ float cs[NCLS][128];
    const int b = blockIdx.y;
    const int t0 = blockIdx.x * 64;
    const int tid = threadIdx.x;
    float acc[5];
#pragma unroll
    for (int i = 0; i < 5; i++) acc[i] = 0.f;

    for (int d0 = 0; d0 < D_; d0 += 128) {
#pragma unroll
        for (int i = 0; i < 8; i++) {
            int f = i * 256 + tid;
            int row = f >> 5, c4 = (f & 31) * 4;
            *(float4*)&pt[row][c4] =
                *(const float4*)(g_patches + (long)(b * NPATCH + t0 + row) * D_ + d0 + c4);
        }
        for (int f = tid; f < NCLS * 32; f += 256) {
            int row = f >> 5, c4 = (f & 31) * 4;
            *(float4*)&cs[row][c4] =
                *(const float4*)(g_cls + (long)(b * NCLS + row) * D_ + d0 + c4);
        }
        __syncthreads();
#pragma unroll
        for (int i = 0; i < 5; i++) {
            int p = i * 256 + tid;
            if (p < 64 * NCLS) {
                int tok = p / NCLS, c = p % NCLS;
                float s = acc[i];
#pragma unroll 8
                for (int d = 0; d < 128; d++)
                    s = fmaf(pt[tok][d], cs[c][d], s);
                acc[i] = s;
            }
        }
        __syncthreads();
    }
#pragma unroll
    for (int i = 0; i < 5; i++) {
        int p = i * 256 + tid;
        if (p < 64 * NCLS) {
            int tok = p / NCLS, c = p % NCLS;
            g_masks[((long)b * NPATCH + t0 + tok) * NCLS + c] = acc[i];
        }
    }
}

// ---------------- mask LN over 19 classes + layout to [b,c,gy,gx] -----------
__global__ void __launch_bounds__(256) maskln_kernel(
    const float* __restrict__ mg, const float* __restrict__ mb)
{
    const int warp = threadIdx.x >> 5, lane = threadIdx.x & 31;
    const int token = blockIdx.x * 8 + warp;
    const int b = token >> 10, n = token & 1023;
    float v = 0.f;
    if (lane < NCLS) v = g_masks[(long)token * NCLS + lane];
    float s = v;
#pragma unroll
    for (int o = 16; o > 0; o >>= 1) s += __shfl_xor_sync(0xffffffff, s, o);
    float mean = s * (1.f / (float)NCLS);
    float d = (lane < NCLS) ? v - mean : 0.f;
    float s2 = d * d;
#pragma unroll
    for (int o = 16; o > 0; o >>= 1) s2 += __shfl_xor_sync(0xffffffff, s2, o);
    float inv = rsqrtf(s2 * (1.f / (float)NCLS) + 1e-5f);
    if (lane < NCLS) {
        float o = d * inv * mg[lane] + mb[lane];
        int gy = n >> 5, gx = n & 31;
        g_mln[(((long)b * NCLS + lane) * GS + gy) * GS + gx] = o;
    }
}

// ---------------- bilinear 32x32 -> 512x512 (jax half-pixel) ----------------
__global__ void __launch_bounds__(256) resize_kernel(float* __restrict__ out)
{
    const int pix = blockIdx.x * 256 + threadIdx.x;
    const int c = blockIdx.y, b = blockIdx.z;
    const int ox = pix & 511, oy = pix >> 9;
    float fx = (ox + 0.5f) * 0.0625f - 0.5f;
    float fy = (oy + 0.5f) * 0.0625f - 0.5f;
    int ix0 = (int)floorf(fx), iy0 = (int)floorf(fy);
    float wx = fx - (float)ix0, wy = fy - (float)iy0;
    int x0 = max(ix0, 0), x1 = min(ix0 + 1, GS - 1);
    int y0 = max(iy0, 0), y1 = min(iy0 + 1, GS - 1);
    const float* m = g_mln + ((long)b * NCLS + c) * GS * GS;
    float v00 = m[y0 * GS + x0], v01 = m[y0 * GS + x1];
    float v10 = m[y1 * GS + x0], v11 = m[y1 * GS + x1];
    float v = (1.f - wy) * ((1.f - wx) * v00 + wx * v01)
            +        wy  * ((1.f - wx) * v10 + wx * v11);
    out[(((long)b * NCLS + c) * IMG + oy) * IMG + ox] = v;
}

// ---------------- host orchestration ----------------------------------------
static float* sym_addr(const void* sym)
{
    void* p = nullptr;
    cudaGetSymbolAddress(&p, sym);
    return (float*)p;
}

extern "C" void kernel_launch(void* const* d_in, const int* in_sizes, int n_in,
                              void* d_out, int out_size)
{
    (void)in_sizes; (void)n_in; (void)out_size;
    const float* x    = (const float*)d_in[0];
    const float* pdW  = (const float*)d_in[1];
    const float* pdb  = (const float*)d_in[2];
    const float* cls  = (const float*)d_in[3];
    const float* l1g  = (const float*)d_in[4];
    const float* l1b  = (const float*)d_in[5];
    const float* qW   = (const float*)d_in[6];
    const float* qb   = (const float*)d_in[7];
    const float* kW   = (const float*)d_in[8];
    const float* kb   = (const float*)d_in[9];
    const float* vW   = (const float*)d_in[10];
    const float* vb   = (const float*)d_in[11];
    const float* l2g  = (const float*)d_in[12];
    const float* l2b  = (const float*)d_in[13];
    const float* w1   = (const float*)d_in[14];
    const float* b1   = (const float*)d_in[15];
    const float* w2   = (const float*)d_in[16];
    const float* b2   = (const float*)d_in[17];
    const float* ppW  = (const float*)d_in[18];
    const float* pcW  = (const float*)d_in[19];
    const float* dg   = (const float*)d_in[20];
    const float* db   = (const float*)d_in[21];
    const float* mg   = (const float*)d_in[22];
    const float* mb   = (const float*)d_in[23];
    float* out = (float*)d_out;

    float* gx   = sym_addr(g_x);
    float* gh   = sym_addr(g_h);
    float* gq   = sym_addr(g_q);
    float* gk   = sym_addr(g_k);
    float* gv   = sym_addr(g_v);
    float* gatt = sym_addr(g_att);
    float* gff  = sym_addr(g_ff);
    float* gpt  = sym_addr(g_patches);
    float* gcl  = sym_addr(g_cls);

    const dim3 blk(256);
    const int mtiles = (M_ + 127) / 128;      // 66
    const int stiles = (S_ + 127) / 128;      // 9
    const long S2Pl = (long)S_ * SP;

    // x @ proj_dec_W + b  -> g_x patch rows (batched over 8 images)
    mma_gemm<128, false><<<dim3(6, 8, B_), blk>>>(
        x, pdW, pdb, gx, NPATCH, D_, D_, D_, D_, D_,
        1, (long)NPATCH * D_, 0, 0, 0, (long)S_ * D_, 0, 1);
    fill_cls_kernel<<<(NCLS * D_ + 255) / 256, 256>>>(cls);

    for (int l = 0; l < 2; l++) {
        ln_kernel<<<M_, blk>>>(gx, l1g + l * D_, l1b + l * D_, gh);
        qkv_kernel<<<dim3((M_ + 63) / 64, NH, 3), blk>>>(
            gh,
            qW + (long)l * NH * DH * DH, kW + (long)l * NH * DH * DH, vW + (long)l * NH * DH * DH,
            qb + (long)l * NH * DH,      kb + (long)l * NH * DH,      vb + (long)l * NH * DH);

        // scores: (Q/8) @ K^T  -> g_att   (A,B are head slices, lda/ldb=768)
        mma_gemm<128, true><<<dim3(stiles, stiles, BHD), blk>>>(
            gq, gk, nullptr, gatt, S_, S_, DH, D_, D_, SP,
            NH, (long)S_ * D_, DH, (long)S_ * D_, DH,
            (long)NH * S2Pl, S2Pl, 0);

        softmax_kernel<<<dim3(S_, BHD), blk>>>();

        // AV: P @ V  -> += g_x head slice
        mma_gemm<64, false><<<dim3(1, stiles, BHD), blk>>>(
            gatt, gv, nullptr, gx, S_, DH, S_, SP, D_, D_,
            NH, (long)NH * S2Pl, S2Pl, (long)S_ * D_, DH,
            (long)S_ * D_, DH, 4);

        ln_kernel<<<M_, blk>>>(gx, l2g + l * D_, l2b + l * D_, gh);
        mma_gemm<128, false><<<dim3(FF / 128, mtiles, 1), blk>>>(
            gh, w1 + (long)l * D_ * FF, b1 + (long)l * FF, gff,
            M_, FF, D_, D_, FF, FF, 1, 0, 0, 0, 0, 0, 0, 1 | 2);
        mma_gemm<128, false><<<dim3(D_ / 128, mtiles, 1), blk>>>(
            gff, w2 + (long)l * FF * D_, b2 + (long)l * D_, gx,
            M_, D_, FF, FF, D_, D_, 1, 0, 0, 0, 0, 0, 0, 1 | 4);
    }

    // decoder LN
    ln_kernel<<<M_, blk>>>(gx, dg, db, gh);

    // patches @ proj_patch, cls_feat @ proj_classes (per batch)
    mma_gemm<128, false><<<dim3(6, 8, B_), blk>>>(
        gh, ppW, nullptr, gpt, NPATCH, D_, D_, D_, D_, D_,
        1, (long)S_ * D_, 0, 0, 0, (long)NPATCH * D_, 0, 0);
    mma_gemm<128, false><<<dim3(6, 1, B_), blk>>>(
        gh + (long)NPATCH * D_, pcW, nullptr, gcl, NCLS, D_, D_, D_, D_, D_,
        1, (long)S_ * D_, 0, 0, 0, (long)NCLS * D_, 0, 0);

    l2norm_kernel<<<B_ * NPATCH, blk>>>(gpt);
    l2norm_kernel<<<B_ * NCLS, blk>>>(gcl);

    masks_kernel<<<dim3(NPATCH / 64, B_), blk>>>();
    maskln_kernel<<<(B_ * NPATCH) / 8, blk>>>(mg, mb);
    resize_kernel<<<dim3(IMG * IMG / 256, NCLS, B_), blk>>>(out);
}

// round 6
// speedup vs baseline: 2.4035x; 1.3547x over previous
// R6: identical resubmission of R5 — "container failed twice" shown to occur
// independent of kernel content (R0 empty stub, R3 vs R4 identical-source
// divergence). Hang/oob/alignment audit of this source found nothing.
#include <cuda_runtime.h>
#include <math.h>
#include <stdint.h>

// ---------------- problem constants ----------------
#define B_      8
#define S_      1043            // 1024 patches + 19 cls tokens
#define SQ      1056            // padded token stride (rows per batch) for q/k/v
#define SP      1056            // padded col stride of attention matrix
#define NPATCH  1024
#define NCLS    19
#define D_      768
#define NH      12
#define DH      64
#define FF      3072
#define GS      32
#define IMG     512
#define M_      (B_*S_)         // 8344
#define BHD     (B_*NH)         // 96
#define MPAD    8576            // row slack for m-edge tile reads

#define SLICE   ((long)SP * SP) // g_att slice per (b,h): 1056 x 1056

// ---------------- scratch (static device globals; no allocs) ----------------
__device__ float g_x[(size_t)M_ * D_];
__device__ float g_h[(size_t)MPAD * D_];
__device__ float g_q[(size_t)B_ * SQ * D_ + 128 * D_];
__device__ float g_k[(size_t)B_ * SQ * D_ + 128 * D_];
__device__ float g_v[(size_t)B_ * SQ * D_];
__device__ float g_vt[(size_t)B_ * D_ * SQ];
__device__ float g_att[(size_t)BHD * SLICE + 128 * SP];
__device__ float g_ff[(size_t)MPAD * FF];
__device__ float g_patches[(size_t)B_ * NPATCH * D_];
__device__ float g_cls[(size_t)B_ * NCLS * D_];
__device__ float g_masks[(size_t)B_ * NPATCH * NCLS];
__device__ float g_mln[(size_t)B_ * NCLS * GS * GS];

// transposed + tf32-rounded weights [N,K] fp32
#define WTOT 11206656
__device__ float g_wt[WTOT];
#define OFF_W1_0 0
#define OFF_W1_1 2359296
#define OFF_W2_0 4718592
#define OFF_W2_1 7077888
#define OFF_PD   9437184
#define OFF_PP   10027008
#define OFF_PC   10616832

// ---------------- helpers ---------------------------------------------------
__device__ __forceinline__ unsigned f2tf(float x) {
    unsigned r;
    asm("cvt.rna.tf32.f32 %0, %1;" : "=r"(r) : "f"(x));
    return r;
}
__device__ __forceinline__ float rtf(float x) { return __uint_as_float(f2tf(x)); }
__device__ __forceinline__ float gelu_exact(float v) {
    return 0.5f * v * (1.f + erff(v * 0.70710678118654752f));
}
__device__ __forceinline__ uint32_t smem_to_u32(const void* p) {
    uint32_t a;
    asm("{ .reg .u64 t; cvta.to.shared.u64 t, %1; cvt.u32.u64 %0, t; }"
        : "=r"(a) : "l"(p));
    return a;
}
#define CP16(dst, src) \
    asm volatile("cp.async.cg.shared.global [%0], [%1], 16;" :: "r"(dst), "l"(src))
#define CPCOMMIT() asm volatile("cp.async.commit_group;")
#define CPWAIT2()  asm volatile("cp.async.wait_group 2;")

// ---------------- unified tf32 tensor-core GEMM -----------------------------
// C[M, n0:...] = A[M,K] @ B[N,K]^T.  KC=32, 4-stage cp.async pipeline.
// smem row stride 36 floats -> conflict-free fragment LDS.
// All tile loads unconditional (callers guarantee padded/slack memory).
// flags: 1 = +bias, 2 = exact GELU, 4 = += C, 8 = tf32-round stored output.
template<int BN, bool CVTA>
__global__ void __launch_bounds__(256) tf32_gemm(
    const float* __restrict__ A, const float* __restrict__ Bm,
    const float* __restrict__ bias, float* __restrict__ C,
    int M, int Nlim, int K, int lda, int ldb, int ldc,
    int HZ, long sA, long hA, long sB, long hB, long sC, long hC, int flags)
{
    constexpr int NT  = BN / 16;       // n-tiles (of 8) per warp
    constexpr int AST = 128 * 36;      // floats per A stage
    constexpr int BST = BN * 36;       // floats per B stage
    constexpr int STF = AST + BST;
    extern __shared__ float sm[];

    const int z = blockIdx.z;
    A  += (long)(z / HZ) * sA + (long)(z % HZ) * hA;
    Bm += (long)(z / HZ) * sB + (long)(z % HZ) * hB;
    C  += (long)(z / HZ) * sC + (long)(z % HZ) * hC;

    const int tid = threadIdx.x, warp = tid >> 5, lane = tid & 31;
    const int wm = warp & 3, wn = warp >> 2;
    const int l4 = lane >> 2, lm = lane & 3;
    const int m0 = blockIdx.y * 128, n0 = blockIdx.x * BN;
    const uint32_t sb = smem_to_u32(sm);
    const int nch = K >> 5;

    auto issue = [&](int kc) {
        if (kc < nch) {
            const int st = kc & 3;
            const uint32_t ab = sb + (uint32_t)(st * STF) * 4u;
            const uint32_t bb = ab + (uint32_t)AST * 4u;
            const int k0 = kc << 5;
            const float* Ap = A + (long)m0 * lda + k0;
#pragma unroll
            for (int i = 0; i < 4; i++) {
                int q = i * 256 + tid;
                int row = q >> 3, kq = q & 7;
                CP16(ab + (uint32_t)(row * 36 + kq * 4) * 4u,
                     Ap + (long)row * lda + kq * 4);
            }
            const float* Bp = Bm + (long)n0 * ldb + k0;
#pragma unroll
            for (int i = 0; i < BN / 32; i++) {
                int q = i * 256 + tid;
                int row = q >> 3, kq = q & 7;
                CP16(bb + (uint32_t)(row * 36 + kq * 4) * 4u,
                     Bp + (long)row * ldb + kq * 4);
            }
        }
        CPCOMMIT();
    };

    float acc[2][NT][4];
#pragma unroll
    for (int i = 0; i < 2; i++)
#pragma unroll
        for (int j = 0; j < NT; j++)
#pragma unroll
            for (int c = 0; c < 4; c++) acc[i][j][c] = 0.f;

    issue(0); issue(1); issue(2);

    for (int c = 0; c < nch; c++) {
        CPWAIT2();               // groups 0..c complete (3+c committed, <=2 pending)
        __syncthreads();         // visibility + buffer (c+3)&3 free for rewrite
        issue(c + 3);            // real or empty commit (keeps group accounting)

        const float* As = sm + (c & 3) * STF;
        const float* Bs = As + AST;
#pragma unroll
        for (int kk = 0; kk < 32; kk += 8) {
            unsigned af[2][4];
#pragma unroll
            for (int i = 0; i < 2; i++) {
                int r = wm * 32 + i * 16 + l4;
                float a0 = As[r * 36 + kk + lm];
                float a1 = As[(r + 8) * 36 + kk + lm];
                float a2 = As[r * 36 + kk + lm + 4];
                float a3 = As[(r + 8) * 36 + kk + lm + 4];
                if (CVTA) {
                    af[i][0] = f2tf(a0); af[i][1] = f2tf(a1);
                    af[i][2] = f2tf(a2); af[i][3] = f2tf(a3);
                } else {
                    af[i][0] = __float_as_uint(a0); af[i][1] = __float_as_uint(a1);
                    af[i][2] = __float_as_uint(a2); af[i][3] = __float_as_uint(a3);
                }
            }
            unsigned bf[NT][2];
#pragma unroll
            for (int j = 0; j < NT; j++) {
                int n = wn * (BN / 2) + j * 8 + l4;
                bf[j][0] = __float_as_uint(Bs[n * 36 + kk + lm]);
                bf[j][1] = __float_as_uint(Bs[n * 36 + kk + lm + 4]);
            }
#pragma unroll
            for (int i = 0; i < 2; i++)
#pragma unroll
                for (int j = 0; j < NT; j++) {
                    asm volatile(
                        "mma.sync.aligned.m16n8k8.row.col.f32.tf32.tf32.f32 "
                        "{%0,%1,%2,%3},{%4,%5,%6,%7},{%8,%9},{%0,%1,%2,%3};"
                        : "+f"(acc[i][j][0]), "+f"(acc[i][j][1]),
                          "+f"(acc[i][j][2]), "+f"(acc[i][j][3])
                        : "r"(af[i][0]), "r"(af[i][1]), "r"(af[i][2]), "r"(af[i][3]),
                          "r"(bf[j][0]), "r"(bf[j][1]));
                }
        }
    }

    // epilogue
#pragma unroll
    for (int i = 0; i < 2; i++)
#pragma unroll
        for (int j = 0; j < NT; j++)
#pragma unroll
            for (int h = 0; h < 2; h++) {
                int row = m0 + wm * 32 + i * 16 + l4 + h * 8;
                if (row >= M) continue;
                int col = n0 + wn * (BN / 2) + j * 8 + lm * 2;
                if (col >= Nlim) continue;
                float v0 = acc[i][j][h * 2 + 0];
                float v1 = acc[i][j][h * 2 + 1];
                bool has1 = (col + 1 < Nlim);
                if (flags & 1) {
                    v0 += bias[col];
                    if (has1) v1 += bias[col + 1];
                }
                if (flags & 2) { v0 = gelu_exact(v0); v1 = gelu_exact(v1); }
                if (flags & 8) { v0 = rtf(v0); v1 = rtf(v1); }
                float* cp = C + (long)row * ldc + col;
                if (has1) {
                    if (flags & 4) { float2 o = *(float2*)cp; v0 += o.x; v1 += o.y; }
                    float2 st; st.x = v0; st.y = v1;
                    *(float2*)cp = st;
                } else {
                    if (flags & 4) v0 += cp[0];
                    cp[0] = v0;
                }
            }
}

// ---------------- weight transpose + tf32 round: [K,N] -> [N,K] -------------
__global__ void wtrans_kernel(const float* __restrict__ src, int K, int N,
                              float* __restrict__ dst)
{
    __shared__ float t[32][33];
    int n0 = blockIdx.x * 32, k0 = blockIdx.y * 32;
    int tx = threadIdx.x, ty = threadIdx.y;
#pragma unroll
    for (int i = 0; i < 32; i += 8)
        t[ty + i][tx] = src[(long)(k0 + ty + i) * N + n0 + tx];   // t[k][n]
    __syncthreads();
#pragma unroll
    for (int i = 0; i < 32; i += 8)
        dst[(long)(n0 + ty + i) * K + k0 + tx] = rtf(t[tx][ty + i]);
}

// ---------------- V transpose per batch: [SQ tok][768] -> [768][SQ tok] -----
// rounds to tf32; token >= S_ -> 0 (zero K-pad for AV gemm)
__global__ void vtrans_kernel()
{
    __shared__ float t[32][33];
    const int d0 = blockIdx.x * 32, s0 = blockIdx.y * 32, b = blockIdx.z;
    const int tx = threadIdx.x, ty = threadIdx.y;
#pragma unroll
    for (int i = 0; i < 32; i += 8) {
        int s = s0 + ty + i;
        float v = (s < S_) ? g_v[(long)(b * SQ + s) * D_ + d0 + tx] : 0.f;
        t[ty + i][tx] = v;                       // t[s][d]
    }
    __syncthreads();
#pragma unroll
    for (int i = 0; i < 32; i += 8)
        g_vt[(long)(b * D_ + d0 + ty + i) * SQ + s0 + tx] = rtf(t[tx][ty + i]);
}

// ---------------- zero pad cols [1043,1056) of g_att live rows --------------
__global__ void zpad_att_kernel()
{
    long idx = (long)blockIdx.x * 256 + threadIdx.x;
    if (idx >= (long)BHD * S_ * (SP - S_)) return;
    int c = (int)(idx % (SP - S_));
    long r = idx / (SP - S_);
    int row = (int)(r % S_);
    int z = (int)(r / S_);
    g_att[(long)z * SLICE + (long)row * SP + S_ + c] = 0.f;
}

// ---------------- per-head QKV projection (q scaled 1/8; q,k tf32-rounded) --
__global__ void __launch_bounds__(256) qkv_kernel(
    const float* __restrict__ h,
    const float* __restrict__ qW, const float* __restrict__ kW, const float* __restrict__ vW,
    const float* __restrict__ qb, const float* __restrict__ kb, const float* __restrict__ vb)
{
    __shared__ float in_s[64][65];
    __shared__ float w_s[64][64];
    const int hd = blockIdx.y;
    const int z = blockIdx.z;
    const float* W    = (z == 0 ? qW : z == 1 ? kW : vW) + hd * DH * DH;
    const float* bias = (z == 0 ? qb : z == 1 ? kb : vb) + hd * DH;
    float* out        = (z == 0 ? g_q : z == 1 ? g_k : g_v);
    const float scale = (z == 0) ? 0.125f : 1.f;
    const int m0 = blockIdx.x * 64;
    const int tid = threadIdx.x;

#pragma unroll
    for (int i = 0; i < 4; i++) {
        int f = i * 256 + tid;
        int row = f >> 4;
        int c4 = (f & 15) * 4;
        float4 v = make_float4(0.f, 0.f, 0.f, 0.f);
        int gm = m0 + row;
        if (gm < M_) v = *(const float4*)(h + (long)gm * D_ + hd * DH + c4);
        in_s[row][c4 + 0] = v.x; in_s[row][c4 + 1] = v.y;
        in_s[row][c4 + 2] = v.z; in_s[row][c4 + 3] = v.w;
        *(float4*)&w_s[row][c4] = *(const float4*)(W + row * DH + c4);
    }
    __syncthreads();

    const int tx = tid & 15, ty = tid >> 4;
    float acc[4][4];
#pragma unroll
    for (int i = 0; i < 4; i++)
#pragma unroll
        for (int j = 0; j < 4; j++) acc[i][j] = 0.f;

#pragma unroll 8
    for (int d = 0; d < 64; d++) {
        float a[4], b[4];
#pragma unroll
        for (int i = 0; i < 4; i++) a[i] = in_s[ty * 4 + i][d];
        *(float4*)&b[0] = *(const float4*)&w_s[d][tx * 4];
#pragma unroll
        for (int i = 0; i < 4; i++)
#pragma unroll
            for (int j = 0; j < 4; j++)
                acc[i][j] = fmaf(a[i], b[j], acc[i][j]);
    }

#pragma unroll
    for (int i = 0; i < 4; i++) {
        int gm = m0 + ty * 4 + i;
        if (gm >= M_) continue;
        int b = gm / S_;
        long orow = (long)gm + (long)b * (SQ - S_);   // padded batch stride
#pragma unroll
        for (int j = 0; j < 4; j++) {
            float o = (acc[i][j] + bias[tx * 4 + j]) * scale;
            out[orow * D_ + hd * DH + tx * 4 + j] = (z == 2) ? o : rtf(o);
        }
    }
}

// ---------------- single-pass smem row softmax (rounds output) --------------
__global__ void __launch_bounds__(256) softmax_kernel()
{
    __shared__ float row[S_];
    __shared__ float red[256];
    const int z = blockIdx.y;
    float* p = g_att + (long)z * SLICE + (long)blockIdx.x * SP;
    const int tid = threadIdx.x;

    float m = -1e30f;
    for (int i = tid; i < S_; i += 256) {
        float v = p[i];
        row[i] = v;
        m = fmaxf(m, v);
    }
    red[tid] = m; __syncthreads();
    for (int s = 128; s > 0; s >>= 1) {
        if (tid < s) red[tid] = fmaxf(red[tid], red[tid + s]);
        __syncthreads();
    }
    m = red[0]; __syncthreads();

    float sum = 0.f;
    for (int i = tid; i < S_; i += 256) {
        float e = __expf(row[i] - m);
        row[i] = e;
        sum += e;
    }
    red[tid] = sum; __syncthreads();
    for (int s = 128; s > 0; s >>= 1) {
        if (tid < s) red[tid] += red[tid + s];
        __syncthreads();
    }
    float inv = 1.f / red[0];
    for (int i = tid; i < S_; i += 256) p[i] = rtf(row[i] * inv);
}

// ---------------- LayerNorm over d=768 --------------------------------------
__global__ void __launch_bounds__(256) ln_kernel(
    const float* __restrict__ x, const float* __restrict__ g,
    const float* __restrict__ bta, float* __restrict__ out)
{
    const long r = blockIdx.x;
    const float* xr = x + r * D_;
    float* orow = out + r * D_;
    __shared__ float red[256];
    __shared__ float red2[256];
    const int tid = threadIdx.x;
    float v0 = xr[tid], v1 = xr[tid + 256], v2 = xr[tid + 512];
    red[tid]  = v0 + v1 + v2;
    red2[tid] = v0 * v0 + v1 * v1 + v2 * v2;
    __syncthreads();
    for (int s = 128; s > 0; s >>= 1) {
        if (tid < s) { red[tid] += red[tid + s]; red2[tid] += red2[tid + s]; }
        __syncthreads();
    }
    float mean = red[0] * (1.f / 768.f);
    float var  = red2[0] * (1.f / 768.f) - mean * mean;
    float inv  = rsqrtf(var + 1e-5f);
    orow[tid]       = (v0 - mean) * inv * g[tid]       + bta[tid];
    orow[tid + 256] = (v1 - mean) * inv * g[tid + 256] + bta[tid + 256];
    orow[tid + 512] = (v2 - mean) * inv * g[tid + 512] + bta[tid + 512];
}

// ---------------- L2 row normalize (in place), d=768 ------------------------
__global__ void __launch_bounds__(256) l2norm_kernel(float* __restrict__ x)
{
    const long r = blockIdx.x;
    float* xr = x + r * D_;
    __shared__ float red[256];
    const int tid = threadIdx.x;
    float v0 = xr[tid], v1 = xr[tid + 256], v2 = xr[tid + 512];
    red[tid] = v0 * v0 + v1 * v1 + v2 * v2;
    __syncthreads();
    for (int s = 128; s > 0; s >>= 1) {
        if (tid < s) red[tid] += red[tid + s];
        __syncthreads();
    }
    float inv = rsqrtf(red[0]);
    xr[tid] = v0 * inv; xr[tid + 256] = v1 * inv; xr[tid + 512] = v2 * inv;
}

// ---------------- broadcast cls_emb into g_x cls rows -----------------------
__global__ void fill_cls_kernel(const float* __restrict__ cls_emb)
{
    int idx = blockIdx.x * 256 + threadIdx.x;
    if (idx >= NCLS * D_) return;
    float v = cls_emb[idx];
    int c = idx / D_, d = idx % D_;
#pragma unroll
    for (int b = 0; b < B_; b++)
        g_x[(long)(b * S_ + NPATCH + c) * D_ + d] = v;
}

// ---------------- masks[b,n,c] = patches[b,n,:] . cls[b,c,:] (fp32) ---------
__global__ void __launch_bounds__(256) masks_kernel()
{
    __shared__ float pt[64][128];
    __shared__ float cs[NCLS][128];
    const int b = blockIdx.y;
    const int t0 = blockIdx.x * 64;
    const int tid = threadIdx.x;
    float acc[5];
#pragma unroll
    for (int i = 0; i < 5; i++) acc[i] = 0.f;

    for (int d0 = 0; d0 < D_; d0 += 128) {
#pragma unroll
        for (int i = 0; i < 8; i++) {
            int f = i * 256 + tid;
            int row = f >> 5, c4 = (f & 31) * 4;
            *(float4*)&pt[row][c4] =
                *(const float4*)(g_patches + (long)(b * NPATCH + t0 + row) * D_ + d0 + c4);
        }
        for (int f = tid; f < NCLS * 32; f += 256) {
            int row = f >> 5, c4 = (f & 31) * 4;
            *(float4*)&cs[row][c4] =
                *(const float4*)(g_cls + (long)(b * NCLS + row) * D_ + d0 + c4);
        }
        __syncthreads();
#pragma unroll
        for (int i = 0; i < 5; i++) {
            int p = i * 256 + tid;
            if (p < 64 * NCLS) {
                int tok = p / NCLS, c = p % NCLS;
                float s = acc[i];
#pragma unroll 8
                for (int d = 0; d < 128; d++)
                    s = fmaf(pt[tok][d], cs[c][d], s);
                acc[i] = s;
            }
        }
        __syncthreads();
    }
#pragma unroll
    for (int i = 0; i < 5; i++) {
        int p = i * 256 + tid;
        if (p < 64 * NCLS) {
            int tok = p / NCLS, c = p % NCLS;
            g_masks[((long)b * NPATCH + t0 + tok) * NCLS + c] = acc[i];
        }
    }
}

// ---------------- mask LN over 19 classes + layout to [b,c,gy,gx] -----------
__global__ void __launch_bounds__(256) maskln_kernel(
    const float* __restrict__ mg, const float* __restrict__ mb)
{
    const int warp = threadIdx.x >> 5, lane = threadIdx.x & 31;
    const int token = blockIdx.x * 8 + warp;
    const int b = token >> 10, n = token & 1023;
    float v = 0.f;
    if (lane < NCLS) v = g_masks[(long)token * NCLS + lane];
    float s = v;
#pragma unroll
    for (int o = 16; o > 0; o >>= 1) s += __shfl_xor_sync(0xffffffff, s, o);
    float mean = s * (1.f / (float)NCLS);
    float d = (lane < NCLS) ? v - mean : 0.f;
    float s2 = d * d;
#pragma unroll
    for (int o = 16; o > 0; o >>= 1) s2 += __shfl_xor_sync(0xffffffff, s2, o);
    float inv = rsqrtf(s2 * (1.f / (float)NCLS) + 1e-5f);
    if (lane < NCLS) {
        float o = d * inv * mg[lane] + mb[lane];
        int gy = n >> 5, gx = n & 31;
        g_mln[(((long)b * NCLS + lane) * GS + gy) * GS + gx] = o;
    }
}

// ---------------- bilinear 32x32 -> 512x512 (jax half-pixel) ----------------
__global__ void __launch_bounds__(256) resize_kernel(float* __restrict__ out)
{
    const int pix = blockIdx.x * 256 + threadIdx.x;
    const int c = blockIdx.y, b = blockIdx.z;
    const int ox = pix & 511, oy = pix >> 9;
    float fx = (ox + 0.5f) * 0.0625f - 0.5f;
    float fy = (oy + 0.5f) * 0.0625f - 0.5f;
    int ix0 = (int)floorf(fx), iy0 = (int)floorf(fy);
    float wx = fx - (float)ix0, wy = fy - (float)iy0;
    int x0 = max(ix0, 0), x1 = min(ix0 + 1, GS - 1);
    int y0 = max(iy0, 0), y1 = min(iy0 + 1, GS - 1);
    const float* m = g_mln + ((long)b * NCLS + c) * GS * GS;
    float v00 = m[y0 * GS + x0], v01 = m[y0 * GS + x1];
    float v10 = m[y1 * GS + x0], v11 = m[y1 * GS + x1];
    float v = (1.f - wy) * ((1.f - wx) * v00 + wx * v01)
            +        wy  * ((1.f - wx) * v10 + wx * v11);
    out[(((long)b * NCLS + c) * IMG + oy) * IMG + ox] = v;
}

// ---------------- host orchestration ----------------------------------------
static float* sym_addr(const void* sym)
{
    void* p = nullptr;
    cudaGetSymbolAddress(&p, sym);
    return (float*)p;
}

#define SMEM_G128 ((128 * 36 + 128 * 36) * 4 * 4)   // 147456
#define SMEM_G64  ((128 * 36 + 64 * 36) * 4 * 4)    // 110592

extern "C" void kernel_launch(void* const* d_in, const int* in_sizes, int n_in,
                              void* d_out, int out_size)
{
    (void)in_sizes; (void)n_in; (void)out_size;
    const float* x    = (const float*)d_in[0];
    const float* pdW  = (const float*)d_in[1];
    const float* pdb  = (const float*)d_in[2];
    const float* cls  = (const float*)d_in[3];
    const float* l1g  = (const float*)d_in[4];
    const float* l1b  = (const float*)d_in[5];
    const float* qW   = (const float*)d_in[6];
    const float* qb   = (const float*)d_in[7];
    const float* kW   = (const float*)d_in[8];
    const float* kb   = (const float*)d_in[9];
    const float* vW   = (const float*)d_in[10];
    const float* vb   = (const float*)d_in[11];
    const float* l2g  = (const float*)d_in[12];
    const float* l2b  = (const float*)d_in[13];
    const float* w1   = (const float*)d_in[14];
    const float* b1   = (const float*)d_in[15];
    const float* w2   = (const float*)d_in[16];
    const float* b2   = (const float*)d_in[17];
    const float* ppW  = (const float*)d_in[18];
    const float* pcW  = (const float*)d_in[19];
    const float* dg   = (const float*)d_in[20];
    const float* db   = (const float*)d_in[21];
    const float* mg   = (const float*)d_in[22];
    const float* mb   = (const float*)d_in[23];
    float* out = (float*)d_out;

    float* gx   = sym_addr(g_x);
    float* gh   = sym_addr(g_h);
    float* gq   = sym_addr(g_q);
    float* gk   = sym_addr(g_k);
    float* gvt  = sym_addr(g_vt);
    float* gatt = sym_addr(g_att);
    float* gff  = sym_addr(g_ff);
    float* gpt  = sym_addr(g_patches);
    float* gcl  = sym_addr(g_cls);
    float* wt   = sym_addr(g_wt);

    cudaFuncSetAttribute(tf32_gemm<128, false>,
                         cudaFuncAttributeMaxDynamicSharedMemorySize, SMEM_G128);
    cudaFuncSetAttribute(tf32_gemm<128, true>,
                         cudaFuncAttributeMaxDynamicSharedMemorySize, SMEM_G128);
    cudaFuncSetAttribute(tf32_gemm<64, false>,
                         cudaFuncAttributeMaxDynamicSharedMemorySize, SMEM_G64);

    const dim3 blk(256);
    const dim3 tsb(32, 8);
    const int mtiles = (M_ + 127) / 128;      // 66
    const int stiles = (S_ + 127) / 128;      // 9

    // ---- one-time per launch: transpose+round weights, zero att pad cols ---
    wtrans_kernel<<<dim3(FF / 32, D_ / 32), tsb>>>(w1,                 D_, FF, wt + OFF_W1_0);
    wtrans_kernel<<<dim3(FF / 32, D_ / 32), tsb>>>(w1 + (long)D_ * FF, D_, FF, wt + OFF_W1_1);
    wtrans_kernel<<<dim3(D_ / 32, FF / 32), tsb>>>(w2,                 FF, D_, wt + OFF_W2_0);
    wtrans_kernel<<<dim3(D_ / 32, FF / 32), tsb>>>(w2 + (long)FF * D_, FF, D_, wt + OFF_W2_1);
    wtrans_kernel<<<dim3(D_ / 32, D_ / 32), tsb>>>(pdW, D_, D_, wt + OFF_PD);
    wtrans_kernel<<<dim3(D_ / 32, D_ / 32), tsb>>>(ppW, D_, D_, wt + OFF_PP);
    wtrans_kernel<<<dim3(D_ / 32, D_ / 32), tsb>>>(pcW, D_, D_, wt + OFF_PC);
    {
        long n = (long)BHD * S_ * (SP - S_);
        zpad_att_kernel<<<(unsigned)((n + 255) / 256), 256>>>();
    }

    // ---- x @ proj_dec + b -> g_x patch rows (per batch) ----
    tf32_gemm<128, true><<<dim3(6, 8, B_), blk, SMEM_G128>>>(
        x, wt + OFF_PD, pdb, gx,
        NPATCH, D_, D_, D_, D_, D_,
        1, (long)NPATCH * D_, 0, 0, 0, (long)S_ * D_, 0, 1);
    fill_cls_kernel<<<(NCLS * D_ + 255) / 256, 256>>>(cls);

    for (int l = 0; l < 2; l++) {
        ln_kernel<<<M_, blk>>>(gx, l1g + l * D_, l1b + l * D_, gh);
        qkv_kernel<<<dim3((M_ + 63) / 64, NH, 3), blk>>>(
            gh,
            qW + (long)l * NH * DH * DH, kW + (long)l * NH * DH * DH, vW + (long)l * NH * DH * DH,
            qb + (long)l * NH * DH,      kb + (long)l * NH * DH,      vb + (long)l * NH * DH);
        vtrans_kernel<<<dim3(D_ / 32, SQ / 32, B_), tsb>>>();

        // scores: (Q/8) @ K^T -> g_att  (A,B pre-rounded)
        tf32_gemm<128, false><<<dim3(stiles, stiles, BHD), blk, SMEM_G128>>>(
            gq, gk, nullptr, gatt,
            S_, S_, DH, D_, D_, SP,
            NH, (long)SQ * D_, DH, (long)SQ * D_, DH,
            (long)NH * SLICE, SLICE, 0);

        softmax_kernel<<<dim3(S_, BHD), blk>>>();

        // AV: P @ Vt^T -> += g_x head slice  (K padded to 1056, pads zeroed)
        tf32_gemm<64, false><<<dim3(1, stiles, BHD), blk, SMEM_G64>>>(
            gatt, gvt, nullptr, gx,
            S_, DH, SP, SP, SQ, D_,
            NH, (long)NH * SLICE, SLICE,
            (long)D_ * SQ, (long)DH * SQ,
            (long)S_ * D_, DH, 4);

        ln_kernel<<<M_, blk>>>(gx, l2g + l * D_, l2b + l * D_, gh);

        // MLP: W1 (bias+gelu+round for W2's A), W2 (bias+residual)
        tf32_gemm<128, true><<<dim3(FF / 128, mtiles, 1), blk, SMEM_G128>>>(
            gh, wt + (l ? OFF_W1_1 : OFF_W1_0), b1 + (long)l * FF, gff,
            M_, FF, D_, D_, D_, FF,
            1, 0, 0, 0, 0, 0, 0, 1 | 2 | 8);
        tf32_gemm<128, false><<<dim3(D_ / 128, mtiles, 1), blk, SMEM_G128>>>(
            gff, wt + (l ? OFF_W2_1 : OFF_W2_0), b2 + (long)l * D_, gx,
            M_, D_, FF, FF, FF, D_,
            1, 0, 0, 0, 0, 0, 0, 1 | 4);
    }

    // decoder LN
    ln_kernel<<<M_, blk>>>(gx, dg, db, gh);

    // patches @ proj_patch, cls_feat @ proj_classes (per batch)
    tf32_gemm<128, true><<<dim3(6, 8, B_), blk, SMEM_G128>>>(
        gh, wt + OFF_PP, nullptr, gpt,
        NPATCH, D_, D_, D_, D_, D_,
        1, (long)S_ * D_, 0, 0, 0, (long)NPATCH * D_, 0, 0);
    tf32_gemm<128, true><<<dim3(6, 1, B_), blk, SMEM_G128>>>(
        gh + (long)NPATCH * D_, wt + OFF_PC, nullptr, gcl,
        NCLS, D_, D_, D_, D_, D_,
        1, (long)S_ * D_, 0, 0, 0, (long)NCLS * D_, 0, 0);

    l2norm_kernel<<<B_ * NPATCH, blk>>>(gpt);
    l2norm_kernel<<<B_ * NCLS, blk>>>(gcl);

    masks_kernel<<<dim3(NPATCH / 64, B_), blk>>>();
    maskln_kernel<<<(B_ * NPATCH) / 8, blk>>>(mg, mb);
    resize_kernel<<<dim3(IMG * IMG / 256, NCLS, B_), blk>>>(out);
}

// round 7
// speedup vs baseline: 3.5759x; 1.4878x over previous
#include <cuda_runtime.h>
#include <cuda_fp16.h>
#include <math.h>
#include <stdint.h>

// ---------------- problem constants ----------------
#define B_      8
#define S_      1043
#define SQ      1056            // padded token stride for q/k/vt
#define SP      1056            // padded col stride of attention matrix
#define NPATCH  1024
#define NCLS    19
#define D_      768
#define NH      12
#define DH      64
#define FF      3072
#define GS      32
#define IMG     512
#define M_      (B_*S_)         // 8344
#define BHD     (B_*NH)         // 96
#define MPAD    8576

#define SLICE   ((long)SP * SP)

// ---------------- scratch ----------------------------------------------------
__device__ float g_x[(size_t)M_ * D_];
__device__ float g_h[(size_t)MPAD * D_];
__device__ __align__(128) __half g_hh[(size_t)MPAD * D_];     // half shadow of LN out / x
__device__ __align__(128) __half g_qh[(size_t)B_ * SQ * D_ + 128 * D_];
__device__ __align__(128) __half g_kh[(size_t)B_ * SQ * D_ + 128 * D_];
__device__ float g_v[(size_t)B_ * SQ * D_];
__device__ __align__(128) __half g_vth[(size_t)B_ * D_ * SQ];
__device__ float g_att[(size_t)BHD * SLICE];                  // scores (fp32)
__device__ __align__(128) __half g_attp[(size_t)BHD * SLICE + 128 * SP];  // probs (half)
__device__ __align__(128) __half g_ff[(size_t)MPAD * FF];
__device__ float g_patches[(size_t)B_ * NPATCH * D_];
__device__ float g_cls[(size_t)B_ * NCLS * D_];
__device__ float g_masks[(size_t)B_ * NPATCH * NCLS];
__device__ float g_mln[(size_t)B_ * NCLS * GS * GS];

#define WTOT 11206656
__device__ __align__(128) __half g_wt[WTOT];
#define OFF_W1_0 0
#define OFF_W1_1 2359296
#define OFF_W2_0 4718592
#define OFF_W2_1 7077888
#define OFF_PD   9437184
#define OFF_PP   10027008
#define OFF_PC   10616832

// ---------------- helpers ----------------------------------------------------
__device__ __forceinline__ float gelu_exact(float v) {
    return 0.5f * v * (1.f + erff(v * 0.70710678118654752f));
}
__device__ __forceinline__ uint32_t smem_to_u32(const void* p) {
    uint32_t a;
    asm("{ .reg .u64 t; cvta.to.shared.u64 t, %1; cvt.u32.u64 %0, t; }"
        : "=r"(a) : "l"(p));
    return a;
}
#define CP16(dst, src) \
    asm volatile("cp.async.cg.shared.global [%0], [%1], 16;" :: "r"(dst), "l"(src))
#define CPCOMMIT() asm volatile("cp.async.commit_group;")
#define CPWAIT2()  asm volatile("cp.async.wait_group 2;")

// ---------------- fp16 tensor-core GEMM --------------------------------------
// C[M,*] = A[M,K] @ B[N,K]^T, A/B half, acc fp32. KC=32 halfs, 4-stage cp.async.
// smem row stride 40 halfs (80B) -> conflict-free .b32 fragment loads.
// flags: 1 bias, 2 gelu, 4 +=C(fp32), 8 unused, 16 C is half (no accum read).
template<int BN>
__global__ void __launch_bounds__(256) hgemm(
    const __half* __restrict__ A, const __half* __restrict__ Bm,
    const float* __restrict__ bias, void* __restrict__ Cv,
    int M, int Nlim, int K, int lda, int ldb, int ldc,
    int HZ, long sA, long hA, long sB, long hB, long sC, long hC, int flags)
{
    constexpr int NT   = BN / 16;
    constexpr int ASTH = 128 * 40;      // halfs per A stage
    constexpr int BSTH = BN * 40;
    constexpr int STH  = ASTH + BSTH;
    extern __shared__ __half smh[];

    const int z = blockIdx.z;
    A  += (long)(z / HZ) * sA + (long)(z % HZ) * hA;
    Bm += (long)(z / HZ) * sB + (long)(z % HZ) * hB;

    const int tid = threadIdx.x, warp = tid >> 5, lane = tid & 31;
    const int wm = warp & 3, wn = warp >> 2;
    const int l4 = lane >> 2, lm = lane & 3;
    const int m0 = blockIdx.y * 128, n0 = blockIdx.x * BN;
    const uint32_t sb = smem_to_u32(smh);
    const int nch = K >> 5;

    auto issue = [&](int kc) {
        if (kc < nch) {
            const int st = kc & 3;
            const uint32_t ab = sb + (uint32_t)(st * STH) * 2u;
            const uint32_t bb = ab + (uint32_t)ASTH * 2u;
            const int k0 = kc << 5;
            const __half* Ap = A + (long)m0 * lda + k0;
#pragma unroll
            for (int i = 0; i < 2; i++) {
                int q = i * 256 + tid;
                int row = q >> 2, seg = (q & 3) * 8;
                CP16(ab + (uint32_t)(row * 40 + seg) * 2u,
                     Ap + (long)row * lda + seg);
            }
            const __half* Bp = Bm + (long)n0 * ldb + k0;
#pragma unroll
            for (int i = 0; i < BN / 64; i++) {
                int q = i * 256 + tid;
                int row = q >> 2, seg = (q & 3) * 8;
                CP16(bb + (uint32_t)(row * 40 + seg) * 2u,
                     Bp + (long)row * ldb + seg);
            }
        }
        CPCOMMIT();
    };

    float acc[2][NT][4];
#pragma unroll
    for (int i = 0; i < 2; i++)
#pragma unroll
        for (int j = 0; j < NT; j++)
#pragma unroll
            for (int c = 0; c < 4; c++) acc[i][j][c] = 0.f;

    issue(0); issue(1); issue(2);

    for (int c = 0; c < nch; c++) {
        CPWAIT2();
        __syncthreads();
        issue(c + 3);

        const __half* As = smh + (c & 3) * STH;
        const __half* Bs = As + ASTH;
#pragma unroll
        for (int kk = 0; kk < 32; kk += 16) {
            unsigned af[2][4];
#pragma unroll
            for (int i = 0; i < 2; i++) {
                int r = wm * 32 + i * 16 + l4;
                af[i][0] = *(const uint32_t*)(As + r * 40 + kk + 2 * lm);
                af[i][1] = *(const uint32_t*)(As + (r + 8) * 40 + kk + 2 * lm);
                af[i][2] = *(const uint32_t*)(As + r * 40 + kk + 2 * lm + 8);
                af[i][3] = *(const uint32_t*)(As + (r + 8) * 40 + kk + 2 * lm + 8);
            }
            unsigned bf[NT][2];
#pragma unroll
            for (int j = 0; j < NT; j++) {
                int n = wn * (BN / 2) + j * 8 + l4;
                bf[j][0] = *(const uint32_t*)(Bs + n * 40 + kk + 2 * lm);
                bf[j][1] = *(const uint32_t*)(Bs + n * 40 + kk + 2 * lm + 8);
            }
#pragma unroll
            for (int i = 0; i < 2; i++)
#pragma unroll
                for (int j = 0; j < NT; j++) {
                    asm volatile(
                        "mma.sync.aligned.m16n8k16.row.col.f32.f16.f16.f32 "
                        "{%0,%1,%2,%3},{%4,%5,%6,%7},{%8,%9},{%0,%1,%2,%3};"
                        : "+f"(acc[i][j][0]), "+f"(acc[i][j][1]),
                          "+f"(acc[i][j][2]), "+f"(acc[i][j][3])
                        : "r"(af[i][0]), "r"(af[i][1]), "r"(af[i][2]), "r"(af[i][3]),
                          "r"(bf[j][0]), "r"(bf[j][1]));
                }
        }
    }

    // epilogue
    float*  Cf = (float*)Cv  + (long)(z / HZ) * sC + (long)(z % HZ) * hC;
    __half* Ch = (__half*)Cv + (long)(z / HZ) * sC + (long)(z % HZ) * hC;
#pragma unroll
    for (int i = 0; i < 2; i++)
#pragma unroll
        for (int j = 0; j < NT; j++)
#pragma unroll
            for (int h = 0; h < 2; h++) {
                int row = m0 + wm * 32 + i * 16 + l4 + h * 8;
                if (row >= M) continue;
                int col = n0 + wn * (BN / 2) + j * 8 + lm * 2;
                if (col >= Nlim) continue;
                float v0 = acc[i][j][h * 2 + 0];
                float v1 = acc[i][j][h * 2 + 1];
                bool has1 = (col + 1 < Nlim);
                if (flags & 1) {
                    v0 += bias[col];
                    if (has1) v1 += bias[col + 1];
                }
                if (flags & 2) { v0 = gelu_exact(v0); v1 = gelu_exact(v1); }
                if (flags & 16) {
                    __half* hp = Ch + (long)row * ldc + col;
                    if (has1) *(__half2*)hp = __floats2half2_rn(v0, v1);
                    else      hp[0] = __float2half_rn(v0);
                } else {
                    float* cp = Cf + (long)row * ldc + col;
                    if (has1) {
                        if (flags & 4) { float2 o = *(float2*)cp; v0 += o.x; v1 += o.y; }
                        float2 st; st.x = v0; st.y = v1;
                        *(float2*)cp = st;
                    } else {
                        if (flags & 4) v0 += cp[0];
                        cp[0] = v0;
                    }
                }
            }
}

// ---------------- weight transpose + half round: [K,N] -> [N,K] half --------
__global__ void wtrans_kernel(const float* __restrict__ src, int K, int N,
                              __half* __restrict__ dst)
{
    __shared__ float t[32][33];
    int n0 = blockIdx.x * 32, k0 = blockIdx.y * 32;
    int tx = threadIdx.x, ty = threadIdx.y;
#pragma unroll
    for (int i = 0; i < 32; i += 8)
        t[ty + i][tx] = src[(long)(k0 + ty + i) * N + n0 + tx];
    __syncthreads();
#pragma unroll
    for (int i = 0; i < 32; i += 8)
        dst[(long)(n0 + ty + i) * K + k0 + tx] = __float2half_rn(t[tx][ty + i]);
}

// ---------------- x (fp32) -> g_hh (half), contiguous ------------------------
__global__ void cvtx_kernel(const float* __restrict__ x)
{
    long i = ((long)blockIdx.x * 256 + threadIdx.x) * 2;
    if (i >= (long)B_ * NPATCH * D_) return;
    float2 v = *(const float2*)(x + i);
    *(__half2*)(g_hh + i) = __floats2half2_rn(v.x, v.y);
}

// ---------------- V transpose per batch -> half [768][SQ] -------------------
__global__ void vtrans_kernel()
{
    __shared__ float t[32][33];
    const int d0 = blockIdx.x * 32, s0 = blockIdx.y * 32, b = blockIdx.z;
    const int tx = threadIdx.x, ty = threadIdx.y;
#pragma unroll
    for (int i = 0; i < 32; i += 8) {
        int s = s0 + ty + i;
        t[ty + i][tx] = (s < S_) ? g_v[(long)(b * SQ + s) * D_ + d0 + tx] : 0.f;
    }
    __syncthreads();
#pragma unroll
    for (int i = 0; i < 32; i += 8)
        g_vth[(long)(b * D_ + d0 + ty + i) * SQ + s0 + tx] =
            __float2half_rn(t[tx][ty + i]);
}

// ---------------- zero pad cols [S_,SP) of g_attp live rows -----------------
__global__ void zpad_att_kernel()
{
    long idx = (long)blockIdx.x * 256 + threadIdx.x;
    if (idx >= (long)BHD * S_ * (SP - S_)) return;
    int c = (int)(idx % (SP - S_));
    long r = idx / (SP - S_);
    int row = (int)(r % S_);
    int z = (int)(r / S_);
    g_attp[(long)z * SLICE + (long)row * SP + S_ + c] = __float2half_rn(0.f);
}

// ---------------- per-head QKV projection (q scaled 1/8) --------------------
// q,k -> half (g_qh/g_kh, padded batch stride); v -> fp32 g_v
__global__ void __launch_bounds__(256) qkv_kernel(
    const float* __restrict__ h,
    const float* __restrict__ qW, const float* __restrict__ kW, const float* __restrict__ vW,
    const float* __restrict__ qb, const float* __restrict__ kb, const float* __restrict__ vb)
{
    __shared__ float in_s[64][65];
    __shared__ float w_s[64][64];
    const int hd = blockIdx.y;
    const int z = blockIdx.z;
    const float* W    = (z == 0 ? qW : z == 1 ? kW : vW) + hd * DH * DH;
    const float* bias = (z == 0 ? qb : z == 1 ? kb : vb) + hd * DH;
    const float scale = (z == 0) ? 0.125f : 1.f;
    const int m0 = blockIdx.x * 64;
    const int tid = threadIdx.x;

#pragma unroll
    for (int i = 0; i < 4; i++) {
        int f = i * 256 + tid;
        int row = f >> 4;
        int c4 = (f & 15) * 4;
        float4 v = make_float4(0.f, 0.f, 0.f, 0.f);
        int gm = m0 + row;
        if (gm < M_) v = *(const float4*)(h + (long)gm * D_ + hd * DH + c4);
        in_s[row][c4 + 0] = v.x; in_s[row][c4 + 1] = v.y;
        in_s[row][c4 + 2] = v.z; in_s[row][c4 + 3] = v.w;
        *(float4*)&w_s[row][c4] = *(const float4*)(W + row * DH + c4);
    }
    __syncthreads();

    const int tx = tid & 15, ty = tid >> 4;
    float acc[4][4];
#pragma unroll
    for (int i = 0; i < 4; i++)
#pragma unroll
        for (int j = 0; j < 4; j++) acc[i][j] = 0.f;

#pragma unroll 8
    for (int d = 0; d < 64; d++) {
        float a[4], b[4];
#pragma unroll
        for (int i = 0; i < 4; i++) a[i] = in_s[ty * 4 + i][d];
        *(float4*)&b[0] = *(const float4*)&w_s[d][tx * 4];
#pragma unroll
        for (int i = 0; i < 4; i++)
#pragma unroll
            for (int j = 0; j < 4; j++)
                acc[i][j] = fmaf(a[i], b[j], acc[i][j]);
    }

#pragma unroll
    for (int i = 0; i < 4; i++) {
        int gm = m0 + ty * 4 + i;
        if (gm >= M_) continue;
        int b = gm / S_;
        long orow = (long)gm + (long)b * (SQ - S_);
        if (z == 2) {
#pragma unroll
            for (int j = 0; j < 4; j++)
                g_v[orow * D_ + hd * DH + tx * 4 + j] = acc[i][j] + bias[tx * 4 + j];
        } else {
            __half* outp = (z == 0 ? g_qh : g_kh) + orow * D_ + hd * DH + tx * 4;
#pragma unroll
            for (int j2 = 0; j2 < 2; j2++) {
                float o0 = (acc[i][j2 * 2 + 0] + bias[tx * 4 + j2 * 2 + 0]) * scale;
                float o1 = (acc[i][j2 * 2 + 1] + bias[tx * 4 + j2 * 2 + 1]) * scale;
                *(__half2*)(outp + j2 * 2) = __floats2half2_rn(o0, o1);
            }
        }
    }
}

// ---------------- softmax: read fp32 scores, write half probs ---------------
__global__ void __launch_bounds__(256) softmax_kernel()
{
    __shared__ float row[S_];
    __shared__ float red[256];
    const int z = blockIdx.y;
    const float* p = g_att + (long)z * SLICE + (long)blockIdx.x * SP;
    __half* po = g_attp + (long)z * SLICE + (long)blockIdx.x * SP;
    const int tid = threadIdx.x;

    float m = -1e30f;
    for (int i = tid; i < S_; i += 256) {
        float v = p[i];
        row[i] = v;
        m = fmaxf(m, v);
    }
    red[tid] = m; __syncthreads();
    for (int s = 128; s > 0; s >>= 1) {
        if (tid < s) red[tid] = fmaxf(red[tid], red[tid + s]);
        __syncthreads();
    }
    m = red[0]; __syncthreads();

    float sum = 0.f;
    for (int i = tid; i < S_; i += 256) {
        float e = __expf(row[i] - m);
        row[i] = e;
        sum += e;
    }
    red[tid] = sum; __syncthreads();
    for (int s = 128; s > 0; s >>= 1) {
        if (tid < s) red[tid] += red[tid + s];
        __syncthreads();
    }
    float inv = 1.f / red[0];
    for (int i = tid; i < S_; i += 256) po[i] = __float2half_rn(row[i] * inv);
}

// ---------------- LayerNorm over d=768, fp32 out + optional half shadow -----
__global__ void __launch_bounds__(256) ln_kernel(
    const float* __restrict__ x, const float* __restrict__ g,
    const float* __restrict__ bta, float* __restrict__ out,
    __half* __restrict__ outh)
{
    const long r = blockIdx.x;
    const float* xr = x + r * D_;
    float* orow = out + r * D_;
    __shared__ float red[256];
    __shared__ float red2[256];
    const int tid = threadIdx.x;
    float v0 = xr[tid], v1 = xr[tid + 256], v2 = xr[tid + 512];
    red[tid]  = v0 + v1 + v2;
    red2[tid] = v0 * v0 + v1 * v1 + v2 * v2;
    __syncthreads();
    for (int s = 128; s > 0; s >>= 1) {
        if (tid < s) { red[tid] += red[tid + s]; red2[tid] += red2[tid + s]; }
        __syncthreads();
    }
    float mean = red[0] * (1.f / 768.f);
    float var  = red2[0] * (1.f / 768.f) - mean * mean;
    float inv  = rsqrtf(var + 1e-5f);
    float o0 = (v0 - mean) * inv * g[tid]       + bta[tid];
    float o1 = (v1 - mean) * inv * g[tid + 256] + bta[tid + 256];
    float o2 = (v2 - mean) * inv * g[tid + 512] + bta[tid + 512];
    orow[tid] = o0; orow[tid + 256] = o1; orow[tid + 512] = o2;
    if (outh) {
        __half* hrow = outh + r * D_;
        hrow[tid]       = __float2half_rn(o0);
        hrow[tid + 256] = __float2half_rn(o1);
        hrow[tid + 512] = __float2half_rn(o2);
    }
}

// ---------------- L2 row normalize (in place), d=768 ------------------------
__global__ void __launch_bounds__(256) l2norm_kernel(float* __restrict__ x)
{
    const long r = blockIdx.x;
    float* xr = x + r * D_;
    __shared__ float red[256];
    const int tid = threadIdx.x;
    float v0 = xr[tid], v1 = xr[tid + 256], v2 = xr[tid + 512];
    red[tid] = v0 * v0 + v1 * v1 + v2 * v2;
    __syncthreads();
    for (int s = 128; s > 0; s >>= 1) {
        if (tid < s) red[tid] += red[tid + s];
        __syncthreads();
    }
    float inv = rsqrtf(red[0]);
    xr[tid] = v0 * inv; xr[tid + 256] = v1 * inv; xr[tid + 512] = v2 * inv;
}

// ---------------- broadcast cls_emb into g_x cls rows -----------------------
__global__ void fill_cls_kernel(const float* __restrict__ cls_emb)
{
    int idx = blockIdx.x * 256 + threadIdx.x;
    if (idx >= NCLS * D_) return;
    float v = cls_emb[idx];
    int c = idx / D_, d = idx % D_;
#pragma unroll
    for (int b = 0; b < B_; b++)
        g_x[(long)(b * S_ + NPATCH + c) * D_ + d] = v;
}

// ---------------- masks[b,n,c] = patches[b,n,:] . cls[b,c,:] (fp32) ---------
__global__ void __launch_bounds__(256) masks_kernel()
{
    __shared__ float pt[64][128];
    __shared__ float cs[NCLS][128];
    const int b = blockIdx.y;
    const int t0 = blockIdx.x * 64;
    const int tid = threadIdx.x;
    float acc[5];
#pragma unroll
    for (int i = 0; i < 5; i++) acc[i] = 0.f;

    for (int d0 = 0; d0 < D_; d0 += 128) {
#pragma unroll
        for (int i = 0; i < 8; i++) {
            int f = i * 256 + tid;
            int row = f >> 5, c4 = (f & 31) * 4;
            *(float4*)&pt[row][c4] =
                *(const float4*)(g_patches + (long)(b * NPATCH + t0 + row) * D_ + d0 + c4);
        }
        for (int f = tid; f < NCLS * 32; f += 256) {
            int row = f >> 5, c4 = (f & 31) * 4;
            *(float4*)&cs[row][c4] =
                *(const float4*)(g_cls + (long)(b * NCLS + row) * D_ + d0 + c4);
        }
        __syncthreads();
#pragma unroll
        for (int i = 0; i < 5; i++) {
            int p = i * 256 + tid;
            if (p < 64 * NCLS) {
                int tok = p / NCLS, c = p % NCLS;
                float s = acc[i];
#pragma unroll 8
                for (int d = 0; d < 128; d++)
                    s = fmaf(pt[tok][d], cs[c][d], s);
                acc[i] = s;
            }
        }
        __syncthreads();
    }
#pragma unroll
    for (int i = 0; i < 5; i++) {
        int p = i * 256 + tid;
        if (p < 64 * NCLS) {
            int tok = p / NCLS, c = p % NCLS;
            g_masks[((long)b * NPATCH + t0 + tok) * NCLS + c] = acc[i];
        }
    }
}

// ---------------- mask LN + layout to [b,c,gy,gx] ---------------------------
__global__ void __launch_bounds__(256) maskln_kernel(
    const float* __restrict__ mg, const float* __restrict__ mb)
{
    const int warp = threadIdx.x >> 5, lane = threadIdx.x & 31;
    const int token = blockIdx.x * 8 + warp;
    const int b = token >> 10, n = token & 1023;
    float v = 0.f;
    if (lane < NCLS) v = g_masks[(long)token * NCLS + lane];
    float s = v;
#pragma unroll
    for (int o = 16; o > 0; o >>= 1) s += __shfl_xor_sync(0xffffffff, s, o);
    float mean = s * (1.f / (float)NCLS);
    float d = (lane < NCLS) ? v - mean : 0.f;
    float s2 = d * d;
#pragma unroll
    for (int o = 16; o > 0; o >>= 1) s2 += __shfl_xor_sync(0xffffffff, s2, o);
    float inv = rsqrtf(s2 * (1.f / (float)NCLS) + 1e-5f);
    if (lane < NCLS) {
        float o = d * inv * mg[lane] + mb[lane];
        int gy = n >> 5, gx = n & 31;
        g_mln[(((long)b * NCLS + lane) * GS + gy) * GS + gx] = o;
    }
}

// ---------------- bilinear 32x32 -> 512x512 ---------------------------------
__global__ void __launch_bounds__(256) resize_kernel(float* __restrict__ out)
{
    const int pix = blockIdx.x * 256 + threadIdx.x;
    const int c = blockIdx.y, b = blockIdx.z;
    const int ox = pix & 511, oy = pix >> 9;
    float fx = (ox + 0.5f) * 0.0625f - 0.5f;
    float fy = (oy + 0.5f) * 0.0625f - 0.5f;
    int ix0 = (int)floorf(fx), iy0 = (int)floorf(fy);
    float wx = fx - (float)ix0, wy = fy - (float)iy0;
    int x0 = max(ix0, 0), x1 = min(ix0 + 1, GS - 1);
    int y0 = max(iy0, 0), y1 = min(iy0 + 1, GS - 1);
    const float* m = g_mln + ((long)b * NCLS + c) * GS * GS;
    float v00 = m[y0 * GS + x0], v01 = m[y0 * GS + x1];
    float v10 = m[y1 * GS + x0], v11 = m[y1 * GS + x1];
    float v = (1.f - wy) * ((1.f - wx) * v00 + wx * v01)
            +        wy  * ((1.f - wx) * v10 + wx * v11);
    out[(((long)b * NCLS + c) * IMG + oy) * IMG + ox] = v;
}

// ---------------- host orchestration ----------------------------------------
static void* sym_addr(const void* sym)
{
    void* p = nullptr;
    cudaGetSymbolAddress(&p, sym);
    return p;
}

#define SMEM_H128 ((128 * 40 + 128 * 40) * 2 * 4)   // 81920
#define SMEM_H64  ((128 * 40 + 64 * 40) * 2 * 4)    // 61440

extern "C" void kernel_launch(void* const* d_in, const int* in_sizes, int n_in,
                              void* d_out, int out_size)
{
    (void)in_sizes; (void)n_in; (void)out_size;
    const float* x    = (const float*)d_in[0];
    const float* pdW  = (const float*)d_in[1];
    const float* pdb  = (const float*)d_in[2];
    const float* cls  = (const float*)d_in[3];
    const float* l1g  = (const float*)d_in[4];
    const float* l1b  = (const float*)d_in[5];
    const float* qW   = (const float*)d_in[6];
    const float* qb   = (const float*)d_in[7];
    const float* kW   = (const float*)d_in[8];
    const float* kb   = (const float*)d_in[9];
    const float* vW   = (const float*)d_in[10];
    const float* vb   = (const float*)d_in[11];
    const float* l2g  = (const float*)d_in[12];
    const float* l2b  = (const float*)d_in[13];
    const float* w1   = (const float*)d_in[14];
    const float* b1   = (const float*)d_in[15];
    const float* w2   = (const float*)d_in[16];
    const float* b2   = (const float*)d_in[17];
    const float* ppW  = (const float*)d_in[18];
    const float* pcW  = (const float*)d_in[19];
    const float* dg   = (const float*)d_in[20];
    const float* db   = (const float*)d_in[21];
    const float* mg   = (const float*)d_in[22];
    const float* mb   = (const float*)d_in[23];
    float* out = (float*)d_out;

    float*  gx   = (float*)sym_addr(g_x);
    float*  gh   = (float*)sym_addr(g_h);
    __half* ghh  = (__half*)sym_addr(g_hh);
    __half* gqh  = (__half*)sym_addr(g_qh);
    __half* gkh  = (__half*)sym_addr(g_kh);
    __half* gvth = (__half*)sym_addr(g_vth);
    float*  gatt = (float*)sym_addr(g_att);
    __half* gatp = (__half*)sym_addr(g_attp);
    __half* gff  = (__half*)sym_addr(g_ff);
    float*  gpt  = (float*)sym_addr(g_patches);
    float*  gcl  = (float*)sym_addr(g_cls);
    __half* wt   = (__half*)sym_addr(g_wt);

    cudaFuncSetAttribute(hgemm<128>,
                         cudaFuncAttributeMaxDynamicSharedMemorySize, SMEM_H128);
    cudaFuncSetAttribute(hgemm<64>,
                         cudaFuncAttributeMaxDynamicSharedMemorySize, SMEM_H64);

    const dim3 blk(256);
    const dim3 tsb(32, 8);
    const int mtiles = (M_ + 127) / 128;      // 66
    const int stiles = (S_ + 127) / 128;      // 9

    // ---- one-time: weights -> half [N,K]; zero prob pad cols; x -> half ----
    wtrans_kernel<<<dim3(FF / 32, D_ / 32), tsb>>>(w1,                 D_, FF, wt + OFF_W1_0);
    wtrans_kernel<<<dim3(FF / 32, D_ / 32), tsb>>>(w1 + (long)D_ * FF, D_, FF, wt + OFF_W1_1);
    wtrans_kernel<<<dim3(D_ / 32, FF / 32), tsb>>>(w2,                 FF, D_, wt + OFF_W2_0);
    wtrans_kernel<<<dim3(D_ / 32, FF / 32), tsb>>>(w2 + (long)FF * D_, FF, D_, wt + OFF_W2_1);
    wtrans_kernel<<<dim3(D_ / 32, D_ / 32), tsb>>>(pdW, D_, D_, wt + OFF_PD);
    wtrans_kernel<<<dim3(D_ / 32, D_ / 32), tsb>>>(ppW, D_, D_, wt + OFF_PP);
    wtrans_kernel<<<dim3(D_ / 32, D_ / 32), tsb>>>(pcW, D_, D_, wt + OFF_PC);
    {
        long n = (long)BHD * S_ * (SP - S_);
        zpad_att_kernel<<<(unsigned)((n + 255) / 256), 256>>>();
    }
    cvtx_kernel<<<(B_ * NPATCH * D_ / 2 + 255) / 256, 256>>>(x);

    // ---- x(half) @ proj_dec + b -> g_x patch rows (per batch) ----
    hgemm<128><<<dim3(6, 8, B_), blk, SMEM_H128>>>(
        ghh, wt + OFF_PD, pdb, gx,
        NPATCH, D_, D_, D_, D_, D_,
        1, (long)NPATCH * D_, 0, 0, 0, (long)S_ * D_, 0, 1);
    fill_cls_kernel<<<(NCLS * D_ + 255) / 256, 256>>>(cls);

    for (int l = 0; l < 2; l++) {
        ln_kernel<<<M_, blk>>>(gx, l1g + l * D_, l1b + l * D_, gh, nullptr);
        qkv_kernel<<<dim3((M_ + 63) / 64, NH, 3), blk>>>(
            gh,
            qW + (long)l * NH * DH * DH, kW + (long)l * NH * DH * DH, vW + (long)l * NH * DH * DH,
            qb + (long)l * NH * DH,      kb + (long)l * NH * DH,      vb + (long)l * NH * DH);
        vtrans_kernel<<<dim3(D_ / 32, SQ / 32, B_), tsb>>>();

        // scores: (Q/8) @ K^T -> g_att (fp32)
        hgemm<128><<<dim3(stiles, stiles, BHD), blk, SMEM_H128>>>(
            gqh, gkh, nullptr, gatt,
            S_, S_, DH, D_, D_, SP,
            NH, (long)SQ * D_, DH, (long)SQ * D_, DH,
            (long)NH * SLICE, SLICE, 0);

        softmax_kernel<<<dim3(S_, BHD), blk>>>();

        // AV: P(half) @ Vt^T -> += g_x head slice
        hgemm<64><<<dim3(1, stiles, BHD), blk, SMEM_H64>>>(
            gatp, gvth, nullptr, gx,
            S_, DH, SP, SP, SQ, D_,
            NH, (long)NH * SLICE, SLICE,
            (long)D_ * SQ, (long)DH * SQ,
            (long)S_ * D_, DH, 4);

        ln_kernel<<<M_, blk>>>(gx, l2g + l * D_, l2b + l * D_, gh, ghh);

        // MLP: W1 (bias+gelu -> half g_ff), W2 (bias+residual -> fp32 g_x)
        hgemm<128><<<dim3(FF / 128, mtiles, 1), blk, SMEM_H128>>>(
            ghh, wt + (l ? OFF_W1_1 : OFF_W1_0), b1 + (long)l * FF, gff,
            M_, FF, D_, D_, D_, FF,
            1, 0, 0, 0, 0, 0, 0, 1 | 2 | 16);
        hgemm<128><<<dim3(D_ / 128, mtiles, 1), blk, SMEM_H128>>>(
            gff, wt + (l ? OFF_W2_1 : OFF_W2_0), b2 + (long)l * D_, gx,
            M_, D_, FF, FF, FF, D_,
            1, 0, 0, 0, 0, 0, 0, 1 | 4);
    }

    // decoder LN (half shadow for projections)
    ln_kernel<<<M_, blk>>>(gx, dg, db, gh, ghh);

    hgemm<128><<<dim3(6, 8, B_), blk, SMEM_H128>>>(
        ghh, wt + OFF_PP, nullptr, gpt,
        NPATCH, D_, D_, D_, D_, D_,
        1, (long)S_ * D_, 0, 0, 0, (long)NPATCH * D_, 0, 0);
    hgemm<128><<<dim3(6, 1, B_), blk, SMEM_H128>>>(
        ghh + (long)NPATCH * D_, wt + OFF_PC, nullptr, gcl,
        NCLS, D_, D_, D_, D_, D_,
        1, (long)S_ * D_, 0, 0, 0, (long)NCLS * D_, 0, 0);

    l2norm_kernel<<<B_ * NPATCH, blk>>>(gpt);
    l2norm_kernel<<<B_ * NCLS, blk>>>(gcl);

    masks_kernel<<<dim3(NPATCH / 64, B_), blk>>>();
    maskln_kernel<<<(B_ * NPATCH) / 8, blk>>>(mg, mb);
    resize_kernel<<<dim3(IMG * IMG / 256, NCLS, B_), blk>>>(out);
}

// round 8
// speedup vs baseline: 5.2854x; 1.4780x over previous
#include <cuda_runtime.h>
#include <cuda_fp16.h>
#include <math.h>
#include <stdint.h>

// ---------------- problem constants ----------------
#define B_      8
#define S_      1043
#define SQ      1088            // padded token stride (17*64) for q/k/vt
#define NPATCH  1024
#define NCLS    19
#define D_      768
#define NH      12
#define DH      64
#define FF      3072
#define GS      32
#define IMG     512
#define M_      (B_*S_)         // 8344
#define BHD     (B_*NH)         // 96
#define MPAD    8576
#define TKV     64
#define NKT     (SQ / TKV)      // 17

// ---------------- scratch ----------------------------------------------------
__device__ float g_x[(size_t)M_ * D_];
__device__ float g_h[(size_t)MPAD * D_];
__device__ __align__(128) __half g_hh[(size_t)MPAD * D_];
__device__ __align__(128) __half g_qh[(size_t)B_ * SQ * D_ + 128 * D_];
__device__ __align__(128) __half g_kh[(size_t)B_ * SQ * D_ + 128 * D_];
__device__ float g_v[(size_t)B_ * SQ * D_];
__device__ __align__(128) __half g_vth[(size_t)B_ * D_ * SQ];
__device__ __align__(128) __half g_ff[(size_t)MPAD * FF];
__device__ float g_patches[(size_t)B_ * NPATCH * D_];
__device__ float g_cls[(size_t)B_ * NCLS * D_];
__device__ float g_masks[(size_t)B_ * NPATCH * NCLS];
__device__ float g_mln[(size_t)B_ * NCLS * GS * GS];

#define WTOT 11206656
__device__ __align__(128) __half g_wt[WTOT];
#define OFF_W1_0 0
#define OFF_W1_1 2359296
#define OFF_W2_0 4718592
#define OFF_W2_1 7077888
#define OFF_PD   9437184
#define OFF_PP   10027008
#define OFF_PC   10616832

// ---------------- helpers ----------------------------------------------------
__device__ __forceinline__ float gelu_exact(float v) {
    return 0.5f * v * (1.f + erff(v * 0.70710678118654752f));
}
__device__ __forceinline__ uint32_t smem_to_u32(const void* p) {
    uint32_t a;
    asm("{ .reg .u64 t; cvta.to.shared.u64 t, %1; cvt.u32.u64 %0, t; }"
        : "=r"(a) : "l"(p));
    return a;
}
__device__ __forceinline__ unsigned packh2(float a, float b) {
    __half2 h = __floats2half2_rn(a, b);
    return *(unsigned*)&h;
}
#define CP16(dst, src) \
    asm volatile("cp.async.cg.shared.global [%0], [%1], 16;" :: "r"(dst), "l"(src))
#define CPCOMMIT() asm volatile("cp.async.commit_group;")
#define CPWAIT0()  asm volatile("cp.async.wait_group 0;")
#define CPWAIT1()  asm volatile("cp.async.wait_group 1;")
#define CPWAIT2()  asm volatile("cp.async.wait_group 2;")

#define HMMA(acc, a0, a1, a2, a3, b0, b1) \
    asm volatile( \
        "mma.sync.aligned.m16n8k16.row.col.f32.f16.f16.f32 " \
        "{%0,%1,%2,%3},{%4,%5,%6,%7},{%8,%9},{%0,%1,%2,%3};" \
        : "+f"((acc)[0]), "+f"((acc)[1]), "+f"((acc)[2]), "+f"((acc)[3]) \
        : "r"(a0), "r"(a1), "r"(a2), "r"(a3), "r"(b0), "r"(b1))

// ---------------- fp16 tensor-core GEMM (MLP / projections) ------------------
// C[M,*] = A[M,K] @ B[N,K]^T. flags: 1 bias, 2 gelu, 4 +=C(fp32), 16 C half.
template<int BN>
__global__ void __launch_bounds__(256) hgemm(
    const __half* __restrict__ A, const __half* __restrict__ Bm,
    const float* __restrict__ bias, void* __restrict__ Cv,
    int M, int Nlim, int K, int lda, int ldb, int ldc,
    int HZ, long sA, long hA, long sB, long hB, long sC, long hC, int flags)
{
    constexpr int NT   = BN / 16;
    constexpr int ASTH = 128 * 40;
    constexpr int BSTH = BN * 40;
    constexpr int STH  = ASTH + BSTH;
    extern __shared__ __half smh[];

    const int z = blockIdx.z;
    A  += (long)(z / HZ) * sA + (long)(z % HZ) * hA;
    Bm += (long)(z / HZ) * sB + (long)(z % HZ) * hB;

    const int tid = threadIdx.x, warp = tid >> 5, lane = tid & 31;
    const int wm = warp & 3, wn = warp >> 2;
    const int l4 = lane >> 2, lm = lane & 3;
    const int m0 = blockIdx.y * 128, n0 = blockIdx.x * BN;
    const uint32_t sb = smem_to_u32(smh);
    const int nch = K >> 5;

    auto issue = [&](int kc) {
        if (kc < nch) {
            const int st = kc & 3;
            const uint32_t ab = sb + (uint32_t)(st * STH) * 2u;
            const uint32_t bb = ab + (uint32_t)ASTH * 2u;
            const int k0 = kc << 5;
            const __half* Ap = A + (long)m0 * lda + k0;
#pragma unroll
            for (int i = 0; i < 2; i++) {
                int q = i * 256 + tid;
                int row = q >> 2, seg = (q & 3) * 8;
                CP16(ab + (uint32_t)(row * 40 + seg) * 2u,
                     Ap + (long)row * lda + seg);
            }
            const __half* Bp = Bm + (long)n0 * ldb + k0;
#pragma unroll
            for (int i = 0; i < BN / 64; i++) {
                int q = i * 256 + tid;
                int row = q >> 2, seg = (q & 3) * 8;
                CP16(bb + (uint32_t)(row * 40 + seg) * 2u,
                     Bp + (long)row * ldb + seg);
            }
        }
        CPCOMMIT();
    };

    float acc[2][NT][4];
#pragma unroll
    for (int i = 0; i < 2; i++)
#pragma unroll
        for (int j = 0; j < NT; j++)
#pragma unroll
            for (int c = 0; c < 4; c++) acc[i][j][c] = 0.f;

    issue(0); issue(1); issue(2);

    for (int c = 0; c < nch; c++) {
        CPWAIT2();
        __syncthreads();
        issue(c + 3);

        const __half* As = smh + (c & 3) * STH;
        const __half* Bs = As + ASTH;
#pragma unroll
        for (int kk = 0; kk < 32; kk += 16) {
            unsigned af[2][4];
#pragma unroll
            for (int i = 0; i < 2; i++) {
                int r = wm * 32 + i * 16 + l4;
                af[i][0] = *(const uint32_t*)(As + r * 40 + kk + 2 * lm);
                af[i][1] = *(const uint32_t*)(As + (r + 8) * 40 + kk + 2 * lm);
                af[i][2] = *(const uint32_t*)(As + r * 40 + kk + 2 * lm + 8);
                af[i][3] = *(const uint32_t*)(As + (r + 8) * 40 + kk + 2 * lm + 8);
            }
#pragma unroll
            for (int j = 0; j < NT; j++) {
                int n = wn * (BN / 2) + j * 8 + l4;
                unsigned b0 = *(const uint32_t*)(Bs + n * 40 + kk + 2 * lm);
                unsigned b1 = *(const uint32_t*)(Bs + n * 40 + kk + 2 * lm + 8);
#pragma unroll
                for (int i = 0; i < 2; i++)
                    HMMA(acc[i][j], af[i][0], af[i][1], af[i][2], af[i][3], b0, b1);
            }
        }
    }

    float*  Cf = (float*)Cv  + (long)(z / HZ) * sC + (long)(z % HZ) * hC;
    __half* Ch = (__half*)Cv + (long)(z / HZ) * sC + (long)(z % HZ) * hC;
#pragma unroll
    for (int i = 0; i < 2; i++)
#pragma unroll
        for (int j = 0; j < NT; j++)
#pragma unroll
            for (int h = 0; h < 2; h++) {
                int row = m0 + wm * 32 + i * 16 + l4 + h * 8;
                if (row >= M) continue;
                int col = n0 + wn * (BN / 2) + j * 8 + lm * 2;
                if (col >= Nlim) continue;
                float v0 = acc[i][j][h * 2 + 0];
                float v1 = acc[i][j][h * 2 + 1];
                bool has1 = (col + 1 < Nlim);
                if (flags & 1) {
                    v0 += bias[col];
                    if (has1) v1 += bias[col + 1];
                }
                if (flags & 2) { v0 = gelu_exact(v0); v1 = gelu_exact(v1); }
                if (flags & 16) {
                    __half* hp = Ch + (long)row * ldc + col;
                    if (has1) *(__half2*)hp = __floats2half2_rn(v0, v1);
                    else      hp[0] = __float2half_rn(v0);
                } else {
                    float* cp = Cf + (long)row * ldc + col;
                    if (has1) {
                        if (flags & 4) { float2 o = *(float2*)cp; v0 += o.x; v1 += o.y; }
                        float2 st; st.x = v0; st.y = v1;
                        *(float2*)cp = st;
                    } else {
                        if (flags & 4) v0 += cp[0];
                        cp[0] = v0;
                    }
                }
            }
}

// ---------------- fused flash attention --------------------------------------
// grid = (9 q-tiles, 96 bh), 256 threads (8 warps x 16 q-rows).
// O = softmax(Q K^T) V accumulated online; += into g_x.
// smem (halfs): Q 128x72 | K 2x(64x72) | V^T 2x(64x72)
#define FA_QS 0
#define FA_KS (128 * 72)
#define FA_VS (128 * 72 + 2 * 64 * 72)
#define FA_SMEM ((128 * 72 + 4 * 64 * 72) * 2)   // 55296 B
__global__ void __launch_bounds__(256) fattn_kernel()
{
    extern __shared__ __half sh[];
    const int z = blockIdx.y;
    const int b = z / NH, hd = z % NH;
    const int m0 = blockIdx.x * 128;
    const int tid = threadIdx.x, warp = tid >> 5, lane = tid & 31;
    const int l4 = lane >> 2, lm = lane & 3;
    const uint32_t sb = smem_to_u32(sh);

    const __half* Qg = g_qh + ((long)b * SQ + m0) * D_ + hd * DH;
    const __half* Kg = g_kh + (long)b * SQ * D_ + hd * DH;
    const __half* Vg = g_vth + ((long)b * D_ + hd * DH) * SQ;

    auto loadKV = [&](int kt) {
        const int st = kt & 1;
        const __half* Kp = Kg + (long)(kt * TKV) * D_;
        const __half* Vp = Vg + kt * TKV;
        const uint32_t kb = sb + (uint32_t)(FA_KS + st * 64 * 72) * 2u;
        const uint32_t vb = sb + (uint32_t)(FA_VS + st * 64 * 72) * 2u;
#pragma unroll
        for (int i = 0; i < 2; i++) {
            int q = i * 256 + tid;
            int row = q >> 3, seg = (q & 7) * 8;
            CP16(kb + (uint32_t)(row * 72 + seg) * 2u, Kp + (long)row * D_ + seg);
        }
#pragma unroll
        for (int i = 0; i < 2; i++) {
            int q = i * 256 + tid;
            int row = q >> 3, seg = (q & 7) * 8;
            CP16(vb + (uint32_t)(row * 72 + seg) * 2u, Vp + (long)row * SQ + seg);
        }
    };

    // prologue: Q tile + KV tile 0 in one group
#pragma unroll
    for (int i = 0; i < 4; i++) {
        int q = i * 256 + tid;
        int row = q >> 3, seg = (q & 7) * 8;
        CP16(sb + (uint32_t)(FA_QS + row * 72 + seg) * 2u, Qg + (long)row * D_ + seg);
    }
    loadKV(0);
    CPCOMMIT();
    CPWAIT0();
    __syncthreads();

    // Q fragments (register-resident for whole loop)
    unsigned qa[4][4];
    {
        const __half* Qs = sh + FA_QS + (warp * 16) * 72;
#pragma unroll
        for (int kc = 0; kc < 4; kc++) {
            qa[kc][0] = *(const uint32_t*)(Qs + l4 * 72 + kc * 16 + 2 * lm);
            qa[kc][1] = *(const uint32_t*)(Qs + (l4 + 8) * 72 + kc * 16 + 2 * lm);
            qa[kc][2] = *(const uint32_t*)(Qs + l4 * 72 + kc * 16 + 2 * lm + 8);
            qa[kc][3] = *(const uint32_t*)(Qs + (l4 + 8) * 72 + kc * 16 + 2 * lm + 8);
        }
    }

    float oacc[8][4];
#pragma unroll
    for (int j = 0; j < 8; j++)
#pragma unroll
        for (int c = 0; c < 4; c++) oacc[j][c] = 0.f;
    float mr0 = -1e30f, mr1 = -1e30f, lr0 = 0.f, lr1 = 0.f;

    for (int kt = 0; kt < NKT; kt++) {
        __syncthreads();                      // WAR: stage (kt+1)&1 free
        if (kt + 1 < NKT) { loadKV(kt + 1); CPCOMMIT(); CPWAIT1(); }
        else              { CPWAIT0(); }
        __syncthreads();                      // RAW: stage kt&1 visible

        const __half* Ks = sh + FA_KS + (kt & 1) * 64 * 72;
        const __half* Vs = sh + FA_VS + (kt & 1) * 64 * 72;

        // S = Q @ K^T  (128 x 64 per block; 16 x 64 per warp)
        float sacc[8][4];
#pragma unroll
        for (int j = 0; j < 8; j++)
#pragma unroll
            for (int c = 0; c < 4; c++) sacc[j][c] = 0.f;
#pragma unroll
        for (int kc = 0; kc < 4; kc++)
#pragma unroll
            for (int j = 0; j < 8; j++) {
                int n = j * 8 + l4;
                unsigned b0 = *(const uint32_t*)(Ks + n * 72 + kc * 16 + 2 * lm);
                unsigned b1 = *(const uint32_t*)(Ks + n * 72 + kc * 16 + 2 * lm + 8);
                HMMA(sacc[j], qa[kc][0], qa[kc][1], qa[kc][2], qa[kc][3], b0, b1);
            }

        // mask pad kv columns (only last tile has any)
        const int base = kt * TKV;
        if (base + TKV > S_) {
#pragma unroll
            for (int j = 0; j < 8; j++) {
                int c0 = base + j * 8 + 2 * lm;
                if (c0 >= S_)     { sacc[j][0] = -1e30f; sacc[j][2] = -1e30f; }
                if (c0 + 1 >= S_) { sacc[j][1] = -1e30f; sacc[j][3] = -1e30f; }
            }
        }

        // online softmax update
        float tm0 = -1e30f, tm1 = -1e30f;
#pragma unroll
        for (int j = 0; j < 8; j++) {
            tm0 = fmaxf(tm0, fmaxf(sacc[j][0], sacc[j][1]));
            tm1 = fmaxf(tm1, fmaxf(sacc[j][2], sacc[j][3]));
        }
        tm0 = fmaxf(tm0, __shfl_xor_sync(0xffffffff, tm0, 1));
        tm0 = fmaxf(tm0, __shfl_xor_sync(0xffffffff, tm0, 2));
        tm1 = fmaxf(tm1, __shfl_xor_sync(0xffffffff, tm1, 1));
        tm1 = fmaxf(tm1, __shfl_xor_sync(0xffffffff, tm1, 2));
        float mn0 = fmaxf(mr0, tm0), mn1 = fmaxf(mr1, tm1);
        float sc0 = __expf(mr0 - mn0), sc1 = __expf(mr1 - mn1);
        float rs0 = 0.f, rs1 = 0.f;
#pragma unroll
        for (int j = 0; j < 8; j++) {
            sacc[j][0] = __expf(sacc[j][0] - mn0);
            sacc[j][1] = __expf(sacc[j][1] - mn0);
            sacc[j][2] = __expf(sacc[j][2] - mn1);
            sacc[j][3] = __expf(sacc[j][3] - mn1);
            rs0 += sacc[j][0] + sacc[j][1];
            rs1 += sacc[j][2] + sacc[j][3];
        }
        rs0 += __shfl_xor_sync(0xffffffff, rs0, 1);
        rs0 += __shfl_xor_sync(0xffffffff, rs0, 2);
        rs1 += __shfl_xor_sync(0xffffffff, rs1, 1);
        rs1 += __shfl_xor_sync(0xffffffff, rs1, 2);
        lr0 = lr0 * sc0 + rs0;
        lr1 = lr1 * sc1 + rs1;
        mr0 = mn0; mr1 = mn1;
#pragma unroll
        for (int j = 0; j < 8; j++) {
            oacc[j][0] *= sc0; oacc[j][1] *= sc0;
            oacc[j][2] *= sc1; oacc[j][3] *= sc1;
        }

        // O += P @ V   (V^T resident as [d][kv])
#pragma unroll
        for (int kc2 = 0; kc2 < 4; kc2++) {
            unsigned pa0 = packh2(sacc[2 * kc2][0],     sacc[2 * kc2][1]);
            unsigned pa1 = packh2(sacc[2 * kc2][2],     sacc[2 * kc2][3]);
            unsigned pa2 = packh2(sacc[2 * kc2 + 1][0], sacc[2 * kc2 + 1][1]);
            unsigned pa3 = packh2(sacc[2 * kc2 + 1][2], sacc[2 * kc2 + 1][3]);
#pragma unroll
            for (int jd = 0; jd < 8; jd++) {
                int n = jd * 8 + l4;
                unsigned b0 = *(const uint32_t*)(Vs + n * 72 + kc2 * 16 + 2 * lm);
                unsigned b1 = *(const uint32_t*)(Vs + n * 72 + kc2 * 16 + 2 * lm + 8);
                HMMA(oacc[jd], pa0, pa1, pa2, pa3, b0, b1);
            }
        }
    }

    // epilogue: O / l, += residual into g_x
    const int q0 = m0 + warp * 16 + l4;
    const int q1 = q0 + 8;
    const float inv0 = 1.f / lr0, inv1 = 1.f / lr1;
#pragma unroll
    for (int jd = 0; jd < 8; jd++) {
        int d = hd * DH + jd * 8 + 2 * lm;
        if (q0 < S_) {
            float* p = g_x + ((long)b * S_ + q0) * D_ + d;
            float2 o = *(float2*)p;
            o.x += oacc[jd][0] * inv0;
            o.y += oacc[jd][1] * inv0;
            *(float2*)p = o;
        }
        if (q1 < S_) {
            float* p = g_x + ((long)b * S_ + q1) * D_ + d;
            float2 o = *(float2*)p;
            o.x += oacc[jd][2] * inv1;
            o.y += oacc[jd][3] * inv1;
            *(float2*)p = o;
        }
    }
}

// ---------------- weight transpose + half round: [K,N] -> [N,K] half --------
__global__ void wtrans_kernel(const float* __restrict__ src, int K, int N,
                              __half* __restrict__ dst)
{
    __shared__ float t[32][33];
    int n0 = blockIdx.x * 32, k0 = blockIdx.y * 32;
    int tx = threadIdx.x, ty = threadIdx.y;
#pragma unroll
    for (int i = 0; i < 32; i += 8)
        t[ty + i][tx] = src[(long)(k0 + ty + i) * N + n0 + tx];
    __syncthreads();
#pragma unroll
    for (int i = 0; i < 32; i += 8)
        dst[(long)(n0 + ty + i) * K + k0 + tx] = __float2half_rn(t[tx][ty + i]);
}

// ---------------- x (fp32) -> g_hh (half) ------------------------------------
__global__ void cvtx_kernel(const float* __restrict__ x)
{
    long i = ((long)blockIdx.x * 256 + threadIdx.x) * 2;
    if (i >= (long)B_ * NPATCH * D_) return;
    float2 v = *(const float2*)(x + i);
    *(__half2*)(g_hh + i) = __floats2half2_rn(v.x, v.y);
}

// ---------------- V transpose per batch -> half [768][SQ], pads zero --------
__global__ void vtrans_kernel()
{
    __shared__ float t[32][33];
    const int d0 = blockIdx.x * 32, s0 = blockIdx.y * 32, b = blockIdx.z;
    const int tx = threadIdx.x, ty = threadIdx.y;
#pragma unroll
    for (int i = 0; i < 32; i += 8) {
        int s = s0 + ty + i;
        t[ty + i][tx] = (s < S_) ? g_v[(long)(b * SQ + s) * D_ + d0 + tx] : 0.f;
    }
    __syncthreads();
#pragma unroll
    for (int i = 0; i < 32; i += 8)
        g_vth[(long)(b * D_ + d0 + ty + i) * SQ + s0 + tx] =
            __float2half_rn(t[tx][ty + i]);
}

// ---------------- per-head QKV projection (q scaled 1/8) --------------------
__global__ void __launch_bounds__(256) qkv_kernel(
    const float* __restrict__ h,
    const float* __restrict__ qW, const float* __restrict__ kW, const float* __restrict__ vW,
    const float* __restrict__ qb, const float* __restrict__ kb, const float* __restrict__ vb)
{
    __shared__ float in_s[64][65];
    __shared__ float w_s[64][64];
    const int hd = blockIdx.y;
    const int z = blockIdx.z;
    const float* W    = (z == 0 ? qW : z == 1 ? kW : vW) + hd * DH * DH;
    const float* bias = (z == 0 ? qb : z == 1 ? kb : vb) + hd * DH;
    const float scale = (z == 0) ? 0.125f : 1.f;
    const int m0 = blockIdx.x * 64;
    const int tid = threadIdx.x;

#pragma unroll
    for (int i = 0; i < 4; i++) {
        int f = i * 256 + tid;
        int row = f >> 4;
        int c4 = (f & 15) * 4;
        float4 v = make_float4(0.f, 0.f, 0.f, 0.f);
        int gm = m0 + row;
        if (gm < M_) v = *(const float4*)(h + (long)gm * D_ + hd * DH + c4);
        in_s[row][c4 + 0] = v.x; in_s[row][c4 + 1] = v.y;
        in_s[row][c4 + 2] = v.z; in_s[row][c4 + 3] = v.w;
        *(float4*)&w_s[row][c4] = *(const float4*)(W + row * DH + c4);
    }
    __syncthreads();

    const int tx = tid & 15, ty = tid >> 4;
    float acc[4][4];
#pragma unroll
    for (int i = 0; i < 4; i++)
#pragma unroll
        for (int j = 0; j < 4; j++) acc[i][j] = 0.f;

#pragma unroll 8
    for (int d = 0; d < 64; d++) {
        float a[4], b[4];
#pragma unroll
        for (int i = 0; i < 4; i++) a[i] = in_s[ty * 4 + i][d];
        *(float4*)&b[0] = *(const float4*)&w_s[d][tx * 4];
#pragma unroll
        for (int i = 0; i < 4; i++)
#pragma unroll
            for (int j = 0; j < 4; j++)
                acc[i][j] = fmaf(a[i], b[j], acc[i][j]);
    }

#pragma unroll
    for (int i = 0; i < 4; i++) {
        int gm = m0 + ty * 4 + i;
        if (gm >= M_) continue;
        int b = gm / S_;
        long orow = (long)gm + (long)b * (SQ - S_);
        if (z == 2) {
#pragma unroll
            for (int j = 0; j < 4; j++)
                g_v[orow * D_ + hd * DH + tx * 4 + j] = acc[i][j] + bias[tx * 4 + j];
        } else {
            __half* outp = (z == 0 ? g_qh : g_kh) + orow * D_ + hd * DH + tx * 4;
#pragma unroll
            for (int j2 = 0; j2 < 2; j2++) {
                float o0 = (acc[i][j2 * 2 + 0] + bias[tx * 4 + j2 * 2 + 0]) * scale;
                float o1 = (acc[i][j2 * 2 + 1] + bias[tx * 4 + j2 * 2 + 1]) * scale;
                *(__half2*)(outp + j2 * 2) = __floats2half2_rn(o0, o1);
            }
        }
    }
}

// ---------------- LayerNorm over d=768, fp32 out + optional half shadow -----
__global__ void __launch_bounds__(256) ln_kernel(
    const float* __restrict__ x, const float* __restrict__ g,
    const float* __restrict__ bta, float* __restrict__ out,
    __half* __restrict__ outh)
{
    const long r = blockIdx.x;
    const float* xr = x + r * D_;
    float* orow = out + r * D_;
    __shared__ float red[256];
    __shared__ float red2[256];
    const int tid = threadIdx.x;
    float v0 = xr[tid], v1 = xr[tid + 256], v2 = xr[tid + 512];
    red[tid]  = v0 + v1 + v2;
    red2[tid] = v0 * v0 + v1 * v1 + v2 * v2;
    __syncthreads();
    for (int s = 128; s > 0; s >>= 1) {
        if (tid < s) { red[tid] += red[tid + s]; red2[tid] += red2[tid + s]; }
        __syncthreads();
    }
    float mean = red[0] * (1.f / 768.f);
    float var  = red2[0] * (1.f / 768.f) - mean * mean;
    float inv  = rsqrtf(var + 1e-5f);
    float o0 = (v0 - mean) * inv * g[tid]       + bta[tid];
    float o1 = (v1 - mean) * inv * g[tid + 256] + bta[tid + 256];
    float o2 = (v2 - mean) * inv * g[tid + 512] + bta[tid + 512];
    orow[tid] = o0; orow[tid + 256] = o1; orow[tid + 512] = o2;
    if (outh) {
        __half* hrow = outh + r * D_;
        hrow[tid]       = __float2half_rn(o0);
        hrow[tid + 256] = __float2half_rn(o1);
        hrow[tid + 512] = __float2half_rn(o2);
    }
}

// ---------------- L2 row normalize (in place), d=768 ------------------------
__global__ void __launch_bounds__(256) l2norm_kernel(float* __restrict__ x)
{
    const long r = blockIdx.x;
    float* xr = x + r * D_;
    __shared__ float red[256];
    const int tid = threadIdx.x;
    float v0 = xr[tid], v1 = xr[tid + 256], v2 = xr[tid + 512];
    red[tid] = v0 * v0 + v1 * v1 + v2 * v2;
    __syncthreads();
    for (int s = 128; s > 0; s >>= 1) {
        if (tid < s) red[tid] += red[tid + s];
        __syncthreads();
    }
    float inv = rsqrtf(red[0]);
    xr[tid] = v0 * inv; xr[tid + 256] = v1 * inv; xr[tid + 512] = v2 * inv;
}

// ---------------- broadcast cls_emb into g_x cls rows -----------------------
__global__ void fill_cls_kernel(const float* __restrict__ cls_emb)
{
    int idx = blockIdx.x * 256 + threadIdx.x;
    if (idx >= NCLS * D_) return;
    float v = cls_emb[idx];
    int c = idx / D_, d = idx % D_;
#pragma unroll
    for (int b = 0; b < B_; b++)
        g_x[(long)(b * S_ + NPATCH + c) * D_ + d] = v;
}

// ---------------- masks[b,n,c] = patches[b,n,:] . cls[b,c,:] (fp32) ---------
__global__ void __launch_bounds__(256) masks_kernel()
{
    __shared__ float pt[64][128];
    __shared__ float cs[NCLS][128];
    const int b = blockIdx.y;
    const int t0 = blockIdx.x * 64;
    const int tid = threadIdx.x;
    float acc[5];
#pragma unroll
    for (int i = 0; i < 5; i++) acc[i] = 0.f;

    for (int d0 = 0; d0 < D_; d0 += 128) {
#pragma unroll
        for (int i = 0; i < 8; i++) {
            int f = i * 256 + tid;
            int row = f >> 5, c4 = (f & 31) * 4;
            *(float4*)&pt[row][c4] =
                *(const float4*)(g_patches + (long)(b * NPATCH + t0 + row) * D_ + d0 + c4);
        }
        for (int f = tid; f < NCLS * 32; f += 256) {
            int row = f >> 5, c4 = (f & 31) * 4;
            *(float4*)&cs[row][c4] =
                *(const float4*)(g_cls + (long)(b * NCLS + row) * D_ + d0 + c4);
        }
        __syncthreads();
#pragma unroll
        for (int i = 0; i < 5; i++) {
            int p = i * 256 + tid;
            if (p < 64 * NCLS) {
                int tok = p / NCLS, c = p % NCLS;
                float s = acc[i];
#pragma unroll 8
                for (int d = 0; d < 128; d++)
                    s = fmaf(pt[tok][d], cs[c][d], s);
                acc[i] = s;
            }
        }
        __syncthreads();
    }
#pragma unroll
    for (int i = 0; i < 5; i++) {
        int p = i * 256 + tid;
        if (p < 64 * NCLS) {
            int tok = p / NCLS, c = p % NCLS;
            g_masks[((long)b * NPATCH + t0 + tok) * NCLS + c] = acc[i];
        }
    }
}

// ---------------- mask LN + layout to [b,c,gy,gx] ---------------------------
__global__ void __launch_bounds__(256) maskln_kernel(
    const float* __restrict__ mg, const float* __restrict__ mb)
{
    const int warp = threadIdx.x >> 5, lane = threadIdx.x & 31;
    const int token = blockIdx.x * 8 + warp;
    const int b = token >> 10, n = token & 1023;
    float v = 0.f;
    if (lane < NCLS) v = g_masks[(long)token * NCLS + lane];
    float s = v;
#pragma unroll
    for (int o = 16; o > 0; o >>= 1) s += __shfl_xor_sync(0xffffffff, s, o);
    float mean = s * (1.f / (float)NCLS);
    float d = (lane < NCLS) ? v - mean : 0.f;
    float s2 = d * d;
#pragma unroll
    for (int o = 16; o > 0; o >>= 1) s2 += __shfl_xor_sync(0xffffffff, s2, o);
    float inv = rsqrtf(s2 * (1.f / (float)NCLS) + 1e-5f);
    if (lane < NCLS) {
        float o = d * inv * mg[lane] + mb[lane];
        int gy = n >> 5, gx = n & 31;
        g_mln[(((long)b * NCLS + lane) * GS + gy) * GS + gx] = o;
    }
}

// ---------------- bilinear 32x32 -> 512x512 ---------------------------------
__global__ void __launch_bounds__(256) resize_kernel(float* __restrict__ out)
{
    const int pix = blockIdx.x * 256 + threadIdx.x;
    const int c = blockIdx.y, b = blockIdx.z;
    const int ox = pix & 511, oy = pix >> 9;
    float fx = (ox + 0.5f) * 0.0625f - 0.5f;
    float fy = (oy + 0.5f) * 0.0625f - 0.5f;
    int ix0 = (int)floorf(fx), iy0 = (int)floorf(fy);
    float wx = fx - (float)ix0, wy = fy - (float)iy0;
    int x0 = max(ix0, 0), x1 = min(ix0 + 1, GS - 1);
    int y0 = max(iy0, 0), y1 = min(iy0 + 1, GS - 1);
    const float* m = g_mln + ((long)b * NCLS + c) * GS * GS;
    float v00 = m[y0 * GS + x0], v01 = m[y0 * GS + x1];
    float v10 = m[y1 * GS + x0], v11 = m[y1 * GS + x1];
    float v = (1.f - wy) * ((1.f - wx) * v00 + wx * v01)
            +        wy  * ((1.f - wx) * v10 + wx * v11);
    out[(((long)b * NCLS + c) * IMG + oy) * IMG + ox] = v;
}

// ---------------- host orchestration ----------------------------------------
static void* sym_addr(const void* sym)
{
    void* p = nullptr;
    cudaGetSymbolAddress(&p, sym);
    return p;
}

#define SMEM_H128 ((128 * 40 + 128 * 40) * 2 * 4)   // 81920

extern "C" void kernel_launch(void* const* d_in, const int* in_sizes, int n_in,
                              void* d_out, int out_size)
{
    (void)in_sizes; (void)n_in; (void)out_size;
    const float* x    = (const float*)d_in[0];
    const float* pdW  = (const float*)d_in[1];
    const float* pdb  = (const float*)d_in[2];
    const float* cls  = (const float*)d_in[3];
    const float* l1g  = (const float*)d_in[4];
    const float* l1b  = (const float*)d_in[5];
    const float* qW   = (const float*)d_in[6];
    const float* qb   = (const float*)d_in[7];
    const float* kW   = (const float*)d_in[8];
    const float* kb   = (const float*)d_in[9];
    const float* vW   = (const float*)d_in[10];
    const float* vb   = (const float*)d_in[11];
    const float* l2g  = (const float*)d_in[12];
    const float* l2b  = (const float*)d_in[13];
    const float* w1   = (const float*)d_in[14];
    const float* b1   = (const float*)d_in[15];
    const float* w2   = (const float*)d_in[16];
    const float* b2   = (const float*)d_in[17];
    const float* ppW  = (const float*)d_in[18];
    const float* pcW  = (const float*)d_in[19];
    const float* dg   = (const float*)d_in[20];
    const float* db   = (const float*)d_in[21];
    const float* mg   = (const float*)d_in[22];
    const float* mb   = (const float*)d_in[23];
    float* out = (float*)d_out;

    float*  gx   = (float*)sym_addr(g_x);
    float*  gh   = (float*)sym_addr(g_h);
    __half* ghh  = (__half*)sym_addr(g_hh);
    __half* gff  = (__half*)sym_addr(g_ff);
    float*  gpt  = (float*)sym_addr(g_patches);
    float*  gcl  = (float*)sym_addr(g_cls);
    __half* wt   = (__half*)sym_addr(g_wt);

    cudaFuncSetAttribute(hgemm<128>,
                         cudaFuncAttributeMaxDynamicSharedMemorySize, SMEM_H128);
    cudaFuncSetAttribute(fattn_kernel,
                         cudaFuncAttributeMaxDynamicSharedMemorySize, FA_SMEM);

    const dim3 blk(256);
    const dim3 tsb(32, 8);
    const int mtiles = (M_ + 127) / 128;      // 66

    // ---- one-time: weights -> half [N,K]; x -> half ----
    wtrans_kernel<<<dim3(FF / 32, D_ / 32), tsb>>>(w1,                 D_, FF, wt + OFF_W1_0);
    wtrans_kernel<<<dim3(FF / 32, D_ / 32), tsb>>>(w1 + (long)D_ * FF, D_, FF, wt + OFF_W1_1);
    wtrans_kernel<<<dim3(D_ / 32, FF / 32), tsb>>>(w2,                 FF, D_, wt + OFF_W2_0);
    wtrans_kernel<<<dim3(D_ / 32, FF / 32), tsb>>>(w2 + (long)FF * D_, FF, D_, wt + OFF_W2_1);
    wtrans_kernel<<<dim3(D_ / 32, D_ / 32), tsb>>>(pdW, D_, D_, wt + OFF_PD);
    wtrans_kernel<<<dim3(D_ / 32, D_ / 32), tsb>>>(ppW, D_, D_, wt + OFF_PP);
    wtrans_kernel<<<dim3(D_ / 32, D_ / 32), tsb>>>(pcW, D_, D_, wt + OFF_PC);
    cvtx_kernel<<<(B_ * NPATCH * D_ / 2 + 255) / 256, 256>>>(x);

    // ---- x(half) @ proj_dec + b -> g_x patch rows ----
    hgemm<128><<<dim3(6, 8, B_), blk, SMEM_H128>>>(
        ghh, wt + OFF_PD, pdb, gx,
        NPATCH, D_, D_, D_, D_, D_,
        1, (long)NPATCH * D_, 0, 0, 0, (long)S_ * D_, 0, 1);
    fill_cls_kernel<<<(NCLS * D_ + 255) / 256, 256>>>(cls);

    for (int l = 0; l < 2; l++) {
        ln_kernel<<<M_, blk>>>(gx, l1g + l * D_, l1b + l * D_, gh, nullptr);
        qkv_kernel<<<dim3((M_ + 63) / 64, NH, 3), blk>>>(
            gh,
            qW + (long)l * NH * DH * DH, kW + (long)l * NH * DH * DH, vW + (long)l * NH * DH * DH,
            qb + (long)l * NH * DH,      kb + (long)l * NH * DH,      vb + (long)l * NH * DH);
        vtrans_kernel<<<dim3(D_ / 32, SQ / 32, B_), tsb>>>();

        // fused attention (QK^T + online softmax + PV, += residual)
        fattn_kernel<<<dim3((S_ + 127) / 128, BHD), blk, FA_SMEM>>>();

        ln_kernel<<<M_, blk>>>(gx, l2g + l * D_, l2b + l * D_, gh, ghh);

        // MLP: W1 (bias+gelu -> half g_ff), W2 (bias+residual -> fp32 g_x)
        hgemm<128><<<dim3(FF / 128, mtiles, 1), blk, SMEM_H128>>>(
            ghh, wt + (l ? OFF_W1_1 : OFF_W1_0), b1 + (long)l * FF, gff,
            M_, FF, D_, D_, D_, FF,
            1, 0, 0, 0, 0, 0, 0, 1 | 2 | 16);
        hgemm<128><<<dim3(D_ / 128, mtiles, 1), blk, SMEM_H128>>>(
            gff, wt + (l ? OFF_W2_1 : OFF_W2_0), b2 + (long)l * D_, gx,
            M_, D_, FF, FF, FF, D_,
            1, 0, 0, 0, 0, 0, 0, 1 | 4);
    }

    // decoder LN (half shadow for projections)
    ln_kernel<<<M_, blk>>>(gx, dg, db, gh, ghh);

    hgemm<128><<<dim3(6, 8, B_), blk, SMEM_H128>>>(
        ghh, wt + OFF_PP, nullptr, gpt,
        NPATCH, D_, D_, D_, D_, D_,
        1, (long)S_ * D_, 0, 0, 0, (long)NPATCH * D_, 0, 0);
    hgemm<128><<<dim3(6, 1, B_), blk, SMEM_H128>>>(
        ghh + (long)NPATCH * D_, wt + OFF_PC, nullptr, gcl,
        NCLS, D_, D_, D_, D_, D_,
        1, (long)S_ * D_, 0, 0, 0, (long)NCLS * D_, 0, 0);

    l2norm_kernel<<<B_ * NPATCH, blk>>>(gpt);
    l2norm_kernel<<<B_ * NCLS, blk>>>(gcl);

    masks_kernel<<<dim3(NPATCH / 64, B_), blk>>>();
    maskln_kernel<<<(B_ * NPATCH) / 8, blk>>>(mg, mb);
    resize_kernel<<<dim3(IMG * IMG / 256, NCLS, B_), blk>>>(out);
}

// round 9
// speedup vs baseline: 5.7643x; 1.0906x over previous
#include <cuda_runtime.h>
#include <cuda_fp16.h>
#include <math.h>
#include <stdint.h>

// ---------------- problem constants ----------------
#define B_      8
#define S_      1043
#define SQ      1088            // kv col stride of g_vth (17*64)
#define NPATCH  1024
#define NCLS    19
#define D_      768
#define NH      12
#define DH      64
#define FF      3072
#define GS      32
#define IMG     512
#define M_      (B_*S_)         // 8344
#define BHD     (B_*NH)         // 96
#define MPAD    8576
#define TKV     64
#define NKT     17              // ceil(S_/64)

// ---------------- scratch ----------------------------------------------------
__device__ float g_x[(size_t)M_ * D_];
__device__ float g_h[(size_t)MPAD * D_];
__device__ __align__(128) __half g_hh[(size_t)MPAD * D_];
__device__ __align__(128) __half g_qh[(size_t)M_ * D_ + 128 * D_];
__device__ __align__(128) __half g_kh[(size_t)M_ * D_ + 128 * D_];
__device__ __align__(128) __half g_vh[(size_t)M_ * D_ + 128 * D_];
__device__ __align__(128) __half g_vth[(size_t)B_ * D_ * SQ];
__device__ __align__(128) __half g_ff[(size_t)MPAD * FF];
__device__ float g_patches[(size_t)B_ * NPATCH * D_];
__device__ float g_cls[(size_t)B_ * NCLS * D_];
__device__ float g_masks[(size_t)B_ * NPATCH * NCLS];
__device__ float g_mln[(size_t)B_ * NCLS * GS * GS];

#define WTOT 11206656
__device__ __align__(128) __half g_wt[WTOT];
#define OFF_W1_0 0
#define OFF_W1_1 2359296
#define OFF_W2_0 4718592
#define OFF_W2_1 7077888
#define OFF_PD   9437184
#define OFF_PP   10027008
#define OFF_PC   10616832
// per-head transposed qkv weights: [(l*3+m)*12+h] x 64x64
__device__ __align__(128) __half g_wqkv[72 * 4096];

// ---------------- helpers ----------------------------------------------------
__device__ __forceinline__ float gelu_exact(float v) {
    return 0.5f * v * (1.f + erff(v * 0.70710678118654752f));
}
__device__ __forceinline__ uint32_t smem_to_u32(const void* p) {
    uint32_t a;
    asm("{ .reg .u64 t; cvta.to.shared.u64 t, %1; cvt.u32.u64 %0, t; }"
        : "=r"(a) : "l"(p));
    return a;
}
__device__ __forceinline__ unsigned packh2(float a, float b) {
    __half2 h = __floats2half2_rn(a, b);
    return *(unsigned*)&h;
}
#define CP16(dst, src) \
    asm volatile("cp.async.cg.shared.global [%0], [%1], 16;" :: "r"(dst), "l"(src))
#define CPCOMMIT() asm volatile("cp.async.commit_group;")
#define CPWAIT0()  asm volatile("cp.async.wait_group 0;")
#define CPWAIT1()  asm volatile("cp.async.wait_group 1;")
#define CPWAIT2()  asm volatile("cp.async.wait_group 2;")

#define HMMA(acc, a0, a1, a2, a3, b0, b1) \
    asm volatile( \
        "mma.sync.aligned.m16n8k16.row.col.f32.f16.f16.f32 " \
        "{%0,%1,%2,%3},{%4,%5,%6,%7},{%8,%9},{%0,%1,%2,%3};" \
        : "+f"((acc)[0]), "+f"((acc)[1]), "+f"((acc)[2]), "+f"((acc)[3]) \
        : "r"(a0), "r"(a1), "r"(a2), "r"(a3), "r"(b0), "r"(b1))

#define LDSM4(r0, r1, r2, r3, addr) \
    asm volatile("ldmatrix.sync.aligned.m8n8.x4.shared.b16 {%0,%1,%2,%3}, [%4];" \
        : "=r"(r0), "=r"(r1), "=r"(r2), "=r"(r3) : "r"(addr))

// ---------------- fp16 tensor-core GEMM --------------------------------------
// C[M,*] = A[M,K] @ B[N,K]^T. KC=32 halfs, 4-stage cp.async, ldmatrix frags.
// flags: 1 bias, 2 gelu, 4 +=C(fp32), 16 C half, 32 scale out by 1/8.
template<int BN>
__global__ void __launch_bounds__(256) hgemm(
    const __half* __restrict__ A, const __half* __restrict__ Bm,
    const float* __restrict__ bias, void* __restrict__ Cv,
    int M, int Nlim, int K, int lda, int ldb, int ldc,
    int HZ, long sA, long hA, long sB, long hB, long sC, long hC,
    long hBias, int flags)
{
    constexpr int NT   = BN / 16;
    constexpr int ASTH = 128 * 40;
    constexpr int BSTH = BN * 40;
    constexpr int STH  = ASTH + BSTH;
    extern __shared__ __half smh[];

    const int z = blockIdx.z;
    A  += (long)(z / HZ) * sA + (long)(z % HZ) * hA;
    Bm += (long)(z / HZ) * sB + (long)(z % HZ) * hB;
    if (bias) bias += (long)(z % HZ) * hBias;

    const int tid = threadIdx.x, warp = tid >> 5, lane = tid & 31;
    const int wm = warp & 3, wn = warp >> 2;
    const int l4 = lane >> 2, lm = lane & 3;
    const int m0 = blockIdx.y * 128, n0 = blockIdx.x * BN;
    const uint32_t sb = smem_to_u32(smh);
    const int nch = K >> 5;

    // ldmatrix lane offsets (elements within a stage)
    const int arow = (lane & 15), acol8 = (lane >> 4) * 8;
    const int bn_l = ((lane >> 4) & 1) * 8 + (lane & 7);
    const int bc_l = ((lane >> 3) & 1) * 8;

    auto issue = [&](int kc) {
        if (kc < nch) {
            const int st = kc & 3;
            const uint32_t ab = sb + (uint32_t)(st * STH) * 2u;
            const uint32_t bb = ab + (uint32_t)ASTH * 2u;
            const int k0 = kc << 5;
            const __half* Ap = A + (long)m0 * lda + k0;
#pragma unroll
            for (int i = 0; i < 2; i++) {
                int q = i * 256 + tid;
                int row = q >> 2, seg = (q & 3) * 8;
                CP16(ab + (uint32_t)(row * 40 + seg) * 2u,
                     Ap + (long)row * lda + seg);
            }
            const __half* Bp = Bm + (long)n0 * ldb + k0;
#pragma unroll
            for (int i = 0; i < BN / 64; i++) {
                int q = i * 256 + tid;
                int row = q >> 2, seg = (q & 3) * 8;
                CP16(bb + (uint32_t)(row * 40 + seg) * 2u,
                     Bp + (long)row * ldb + seg);
            }
        }
        CPCOMMIT();
    };

    float acc[2][NT][4];
#pragma unroll
    for (int i = 0; i < 2; i++)
#pragma unroll
        for (int j = 0; j < NT; j++)
#pragma unroll
            for (int c = 0; c < 4; c++) acc[i][j][c] = 0.f;

    issue(0); issue(1); issue(2);

    for (int c = 0; c < nch; c++) {
        CPWAIT2();
        __syncthreads();
        issue(c + 3);

        const uint32_t as = sb + (uint32_t)((c & 3) * STH) * 2u;
        const uint32_t bs = as + (uint32_t)ASTH * 2u;
#pragma unroll
        for (int kk = 0; kk < 32; kk += 16) {
            unsigned af[2][4];
#pragma unroll
            for (int i = 0; i < 2; i++) {
                uint32_t addr = as + (uint32_t)((wm * 32 + i * 16 + arow) * 40
                                                + kk + acol8) * 2u;
                LDSM4(af[i][0], af[i][1], af[i][2], af[i][3], addr);
            }
#pragma unroll
            for (int g = 0; g < NT / 2; g++) {
                unsigned b0, b1, b2, b3;
                uint32_t addr = bs + (uint32_t)((wn * (BN / 2) + g * 16 + bn_l) * 40
                                                + kk + bc_l) * 2u;
                LDSM4(b0, b1, b2, b3, addr);
#pragma unroll
                for (int i = 0; i < 2; i++) {
                    HMMA(acc[i][2 * g],     af[i][0], af[i][1], af[i][2], af[i][3], b0, b1);
                    HMMA(acc[i][2 * g + 1], af[i][0], af[i][1], af[i][2], af[i][3], b2, b3);
                }
            }
        }
    }

    float*  Cf = (float*)Cv  + (long)(z / HZ) * sC + (long)(z % HZ) * hC;
    __half* Ch = (__half*)Cv + (long)(z / HZ) * sC + (long)(z % HZ) * hC;
#pragma unroll
    for (int i = 0; i < 2; i++)
#pragma unroll
        for (int j = 0; j < NT; j++)
#pragma unroll
            for (int h = 0; h < 2; h++) {
                int row = m0 + wm * 32 + i * 16 + l4 + h * 8;
                if (row >= M) continue;
                int col = n0 + wn * (BN / 2) + j * 8 + lm * 2;
                if (col >= Nlim) continue;
                float v0 = acc[i][j][h * 2 + 0];
                float v1 = acc[i][j][h * 2 + 1];
                bool has1 = (col + 1 < Nlim);
                if (flags & 1) {
                    v0 += bias[col];
                    if (has1) v1 += bias[col + 1];
                }
                if (flags & 32) { v0 *= 0.125f; v1 *= 0.125f; }
                if (flags & 2)  { v0 = gelu_exact(v0); v1 = gelu_exact(v1); }
                if (flags & 16) {
                    __half* hp = Ch + (long)row * ldc + col;
                    if (has1) *(__half2*)hp = __floats2half2_rn(v0, v1);
                    else      hp[0] = __float2half_rn(v0);
                } else {
                    float* cp = Cf + (long)row * ldc + col;
                    if (has1) {
                        if (flags & 4) { float2 o = *(float2*)cp; v0 += o.x; v1 += o.y; }
                        float2 st; st.x = v0; st.y = v1;
                        *(float2*)cp = st;
                    } else {
                        if (flags & 4) v0 += cp[0];
                        cp[0] = v0;
                    }
                }
            }
}

// ---------------- fused flash attention (unpadded q/k, ldmatrix) ------------
#define FA_QS 0
#define FA_KS (128 * 72)
#define FA_VS (128 * 72 + 2 * 64 * 72)
#define FA_SMEM ((128 * 72 + 4 * 64 * 72) * 2)
__global__ void __launch_bounds__(256) fattn_kernel()
{
    extern __shared__ __half sh[];
    const int z = blockIdx.y;
    const int b = z / NH, hd = z % NH;
    const int m0 = blockIdx.x * 128;
    const int tid = threadIdx.x, warp = tid >> 5, lane = tid & 31;
    const int l4 = lane >> 2, lm = lane & 3;
    const uint32_t sb = smem_to_u32(sh);

    const __half* Qg = g_qh + ((long)b * S_ + m0) * D_ + hd * DH;
    const __half* Kg = g_kh + (long)b * S_ * D_ + hd * DH;
    const __half* Vg = g_vth + ((long)b * D_ + hd * DH) * SQ;

    const int arow = (lane & 15), acol8 = (lane >> 4) * 8;
    const int bn_l = ((lane >> 4) & 1) * 8 + (lane & 7);
    const int bc_l = ((lane >> 3) & 1) * 8;

    auto loadKV = [&](int kt) {
        const int st = kt & 1;
        const __half* Kp = Kg + (long)(kt * TKV) * D_;
        const __half* Vp = Vg + kt * TKV;
        const uint32_t kb = sb + (uint32_t)(FA_KS + st * 64 * 72) * 2u;
        const uint32_t vb = sb + (uint32_t)(FA_VS + st * 64 * 72) * 2u;
#pragma unroll
        for (int i = 0; i < 2; i++) {
            int q = i * 256 + tid;
            int row = q >> 3, seg = (q & 7) * 8;
            CP16(kb + (uint32_t)(row * 72 + seg) * 2u, Kp + (long)row * D_ + seg);
        }
#pragma unroll
        for (int i = 0; i < 2; i++) {
            int q = i * 256 + tid;
            int row = q >> 3, seg = (q & 7) * 8;
            CP16(vb + (uint32_t)(row * 72 + seg) * 2u, Vp + (long)row * SQ + seg);
        }
    };

#pragma unroll
    for (int i = 0; i < 4; i++) {
        int q = i * 256 + tid;
        int row = q >> 3, seg = (q & 7) * 8;
        CP16(sb + (uint32_t)(FA_QS + row * 72 + seg) * 2u, Qg + (long)row * D_ + seg);
    }
    loadKV(0);
    CPCOMMIT();
    CPWAIT0();
    __syncthreads();

    unsigned qa[4][4];
#pragma unroll
    for (int kc = 0; kc < 4; kc++) {
        uint32_t addr = sb + (uint32_t)(FA_QS + (warp * 16 + arow) * 72
                                        + kc * 16 + acol8) * 2u;
        LDSM4(qa[kc][0], qa[kc][1], qa[kc][2], qa[kc][3], addr);
    }

    float oacc[8][4];
#pragma unroll
    for (int j = 0; j < 8; j++)
#pragma unroll
        for (int c = 0; c < 4; c++) oacc[j][c] = 0.f;
    float mr0 = -1e30f, mr1 = -1e30f, lr0 = 0.f, lr1 = 0.f;

    for (int kt = 0; kt < NKT; kt++) {
        __syncthreads();
        if (kt + 1 < NKT) { loadKV(kt + 1); CPCOMMIT(); CPWAIT1(); }
        else              { CPWAIT0(); }
        __syncthreads();

        const uint32_t ks = sb + (uint32_t)(FA_KS + (kt & 1) * 64 * 72) * 2u;
        const uint32_t vs = sb + (uint32_t)(FA_VS + (kt & 1) * 64 * 72) * 2u;

        float sacc[8][4];
#pragma unroll
        for (int j = 0; j < 8; j++)
#pragma unroll
            for (int c = 0; c < 4; c++) sacc[j][c] = 0.f;
#pragma unroll
        for (int kc = 0; kc < 4; kc++)
#pragma unroll
            for (int g = 0; g < 4; g++) {
                unsigned b0, b1, b2, b3;
                uint32_t addr = ks + (uint32_t)((g * 16 + bn_l) * 72
                                                + kc * 16 + bc_l) * 2u;
                LDSM4(b0, b1, b2, b3, addr);
                HMMA(sacc[2 * g],     qa[kc][0], qa[kc][1], qa[kc][2], qa[kc][3], b0, b1);
                HMMA(sacc[2 * g + 1], qa[kc][0], qa[kc][1], qa[kc][2], qa[kc][3], b2, b3);
            }

        const int base = kt * TKV;
        if (base + TKV > S_) {
#pragma unroll
            for (int j = 0; j < 8; j++) {
                int c0 = base + j * 8 + 2 * lm;
                if (c0 >= S_)     { sacc[j][0] = -1e30f; sacc[j][2] = -1e30f; }
                if (c0 + 1 >= S_) { sacc[j][1] = -1e30f; sacc[j][3] = -1e30f; }
            }
        }

        float tm0 = -1e30f, tm1 = -1e30f;
#pragma unroll
        for (int j = 0; j < 8; j++) {
            tm0 = fmaxf(tm0, fmaxf(sacc[j][0], sacc[j][1]));
            tm1 = fmaxf(tm1, fmaxf(sacc[j][2], sacc[j][3]));
        }
        tm0 = fmaxf(tm0, __shfl_xor_sync(0xffffffff, tm0, 1));
        tm0 = fmaxf(tm0, __shfl_xor_sync(0xffffffff, tm0, 2));
        tm1 = fmaxf(tm1, __shfl_xor_sync(0xffffffff, tm1, 1));
        tm1 = fmaxf(tm1, __shfl_xor_sync(0xffffffff, tm1, 2));
        float mn0 = fmaxf(mr0, tm0), mn1 = fmaxf(mr1, tm1);
        float sc0 = __expf(mr0 - mn0), sc1 = __expf(mr1 - mn1);
        float rs0 = 0.f, rs1 = 0.f;
#pragma unroll
        for (int j = 0; j < 8; j++) {
            sacc[j][0] = __expf(sacc[j][0] - mn0);
            sacc[j][1] = __expf(sacc[j][1] - mn0);
            sacc[j][2] = __expf(sacc[j][2] - mn1);
            sacc[j][3] = __expf(sacc[j][3] - mn1);
            rs0 += sacc[j][0] + sacc[j][1];
            rs1 += sacc[j][2] + sacc[j][3];
        }
        rs0 += __shfl_xor_sync(0xffffffff, rs0, 1);
        rs0 += __shfl_xor_sync(0xffffffff, rs0, 2);
        rs1 += __shfl_xor_sync(0xffffffff, rs1, 1);
        rs1 += __shfl_xor_sync(0xffffffff, rs1, 2);
        lr0 = lr0 * sc0 + rs0;
        lr1 = lr1 * sc1 + rs1;
        mr0 = mn0; mr1 = mn1;
#pragma unroll
        for (int j = 0; j < 8; j++) {
            oacc[j][0] *= sc0; oacc[j][1] *= sc0;
            oacc[j][2] *= sc1; oacc[j][3] *= sc1;
        }

#pragma unroll
        for (int kc2 = 0; kc2 < 4; kc2++) {
            unsigned pa0 = packh2(sacc[2 * kc2][0],     sacc[2 * kc2][1]);
            unsigned pa1 = packh2(sacc[2 * kc2][2],     sacc[2 * kc2][3]);
            unsigned pa2 = packh2(sacc[2 * kc2 + 1][0], sacc[2 * kc2 + 1][1]);
            unsigned pa3 = packh2(sacc[2 * kc2 + 1][2], sacc[2 * kc2 + 1][3]);
#pragma unroll
            for (int g = 0; g < 4; g++) {
                unsigned b0, b1, b2, b3;
                uint32_t addr = vs + (uint32_t)((g * 16 + bn_l) * 72
                                                + kc2 * 16 + bc_l) * 2u;
                LDSM4(b0, b1, b2, b3, addr);
                HMMA(oacc[2 * g],     pa0, pa1, pa2, pa3, b0, b1);
                HMMA(oacc[2 * g + 1], pa0, pa1, pa2, pa3, b2, b3);
            }
        }
    }

    const int q0 = m0 + warp * 16 + l4;
    const int q1 = q0 + 8;
    const float inv0 = 1.f / lr0, inv1 = 1.f / lr1;
#pragma unroll
    for (int jd = 0; jd < 8; jd++) {
        int d = hd * DH + jd * 8 + 2 * lm;
        if (q0 < S_) {
            float* p = g_x + ((long)b * S_ + q0) * D_ + d;
            float2 o = *(float2*)p;
            o.x += oacc[jd][0] * inv0;
            o.y += oacc[jd][1] * inv0;
            *(float2*)p = o;
        }
        if (q1 < S_) {
            float* p = g_x + ((long)b * S_ + q1) * D_ + d;
            float2 o = *(float2*)p;
            o.x += oacc[jd][2] * inv1;
            o.y += oacc[jd][3] * inv1;
            *(float2*)p = o;
        }
    }
}

// ---------------- weight transpose + half: [K,N] -> [N,K] -------------------
__global__ void wtrans_kernel(const float* __restrict__ src, int K, int N,
                              __half* __restrict__ dst)
{
    __shared__ float t[32][33];
    int n0 = blockIdx.x * 32, k0 = blockIdx.y * 32;
    int tx = threadIdx.x, ty = threadIdx.y;
#pragma unroll
    for (int i = 0; i < 32; i += 8)
        t[ty + i][tx] = src[(long)(k0 + ty + i) * N + n0 + tx];
    __syncthreads();
#pragma unroll
    for (int i = 0; i < 32; i += 8)
        dst[(long)(n0 + ty + i) * K + k0 + tx] = __float2half_rn(t[tx][ty + i]);
}

// ---------------- qkv per-head weight transpose [d,e]->[e,d] half -----------
__global__ void qkvw_kernel(const float* __restrict__ qW,
                            const float* __restrict__ kW,
                            const float* __restrict__ vW)
{
    __shared__ float t[32][33];
    const int z = blockIdx.z;          // 0..71
    const int l = z / 36, rr = z % 36, m = rr / 12, h = rr % 12;
    const float* src = (m == 0 ? qW : m == 1 ? kW : vW) + ((long)(l * 12 + h) * 64) * 64;
    __half* dst = g_wqkv + (long)z * 4096;
    const int e0 = blockIdx.x * 32, d0 = blockIdx.y * 32;
    const int tx = threadIdx.x, ty = threadIdx.y;
#pragma unroll
    for (int i = 0; i < 32; i += 8)
        t[ty + i][tx] = src[(d0 + ty + i) * 64 + e0 + tx];   // t[d][e]
    __syncthreads();
#pragma unroll
    for (int i = 0; i < 32; i += 8)
        dst[(e0 + ty + i) * 64 + d0 + tx] = __float2half_rn(t[tx][ty + i]);
}

// ---------------- x (fp32) -> g_hh (half) ------------------------------------
__global__ void cvtx_kernel(const float* __restrict__ x)
{
    long i = ((long)blockIdx.x * 256 + threadIdx.x) * 2;
    if (i >= (long)B_ * NPATCH * D_) return;
    float2 v = *(const float2*)(x + i);
    *(__half2*)(g_hh + i) = __floats2half2_rn(v.x, v.y);
}

// ---------------- V transpose per batch -> half [768][SQ], pads zero --------
__global__ void vtrans_kernel()
{
    __shared__ float t[32][33];
    const int d0 = blockIdx.x * 32, s0 = blockIdx.y * 32, b = blockIdx.z;
    const int tx = threadIdx.x, ty = threadIdx.y;
#pragma unroll
    for (int i = 0; i < 32; i += 8) {
        int s = s0 + ty + i;
        t[ty + i][tx] = (s < S_)
            ? __half2float(g_vh[((long)b * S_ + s) * D_ + d0 + tx]) : 0.f;
    }
    __syncthreads();
#pragma unroll
    for (int i = 0; i < 32; i += 8)
        g_vth[(long)(b * D_ + d0 + ty + i) * SQ + s0 + tx] =
            __float2half_rn(t[tx][ty + i]);
}

// ---------------- LayerNorm over d=768, fp32 out + optional half shadow -----
__global__ void __launch_bounds__(256) ln_kernel(
    const float* __restrict__ x, const float* __restrict__ g,
    const float* __restrict__ bta, float* __restrict__ out,
    __half* __restrict__ outh)
{
    const long r = blockIdx.x;
    const float* xr = x + r * D_;
    float* orow = out + r * D_;
    __shared__ float red[256];
    __shared__ float red2[256];
    const int tid = threadIdx.x;
    float v0 = xr[tid], v1 = xr[tid + 256], v2 = xr[tid + 512];
    red[tid]  = v0 + v1 + v2;
    red2[tid] = v0 * v0 + v1 * v1 + v2 * v2;
    __syncthreads();
    for (int s = 128; s > 0; s >>= 1) {
        if (tid < s) { red[tid] += red[tid + s]; red2[tid] += red2[tid + s]; }
        __syncthreads();
    }
    float mean = red[0] * (1.f / 768.f);
    float var  = red2[0] * (1.f / 768.f) - mean * mean;
    float inv  = rsqrtf(var + 1e-5f);
    float o0 = (v0 - mean) * inv * g[tid]       + bta[tid];
    float o1 = (v1 - mean) * inv * g[tid + 256] + bta[tid + 256];
    float o2 = (v2 - mean) * inv * g[tid + 512] + bta[tid + 512];
    orow[tid] = o0; orow[tid + 256] = o1; orow[tid + 512] = o2;
    if (outh) {
        __half* hrow = outh + r * D_;
        hrow[tid]       = __float2half_rn(o0);
        hrow[tid + 256] = __float2half_rn(o1);
        hrow[tid + 512] = __float2half_rn(o2);
    }
}

// ---------------- L2 row normalize (in place), d=768 ------------------------
__global__ void __launch_bounds__(256) l2norm_kernel(float* __restrict__ x)
{
    const long r = blockIdx.x;
    float* xr = x + r * D_;
    __shared__ float red[256];
    const int tid = threadIdx.x;
    float v0 = xr[tid], v1 = xr[tid + 256], v2 = xr[tid + 512];
    red[tid] = v0 * v0 + v1 * v1 + v2 * v2;
    __syncthreads();
    for (int s = 128; s > 0; s >>= 1) {
        if (tid < s) red[tid] += red[tid + s];
        __syncthreads();
    }
    float inv = rsqrtf(red[0]);
    xr[tid] = v0 * inv; xr[tid + 256] = v1 * inv; xr[tid + 512] = v2 * inv;
}

// ---------------- broadcast cls_emb into g_x cls rows -----------------------
__global__ void fill_cls_kernel(const float* __restrict__ cls_emb)
{
    int idx = blockIdx.x * 256 + threadIdx.x;
    if (idx >= NCLS * D_) return;
    float v = cls_emb[idx];
    int c = idx / D_, d = idx % D_;
#pragma unroll
    for (int b = 0; b < B_; b++)
        g_x[(long)(b * S_ + NPATCH + c) * D_ + d] = v;
}

// ---------------- masks[b,n,c] = patches[b,n,:] . cls[b,c,:] (fp32) ---------
__global__ void __launch_bounds__(256) masks_kernel()
{
    __shared__ float pt[64][128];
    __shared__ float cs[NCLS][128];
    const int b = blockIdx.y;
    const int t0 = blockIdx.x * 64;
    const int tid = threadIdx.x;
    float acc[5];
#pragma unroll
    for (int i = 0; i < 5; i++) acc[i] = 0.f;

    for (int d0 = 0; d0 < D_; d0 += 128) {
#pragma unroll
        for (int i = 0; i < 8; i++) {
            int f = i * 256 + tid;
            int row = f >> 5, c4 = (f & 31) * 4;
            *(float4*)&pt[row][c4] =
                *(const float4*)(g_patches + (long)(b * NPATCH + t0 + row) * D_ + d0 + c4);
        }
        for (int f = tid; f < NCLS * 32; f += 256) {
            int row = f >> 5, c4 = (f & 31) * 4;
            *(float4*)&cs[row][c4] =
                *(const float4*)(g_cls + (long)(b * NCLS + row) * D_ + d0 + c4);
        }
        __syncthreads();
#pragma unroll
        for (int i = 0; i < 5; i++) {
            int p = i * 256 + tid;
            if (p < 64 * NCLS) {
                int tok = p / NCLS, c = p % NCLS;
                float s = acc[i];
#pragma unroll 8
                for (int d = 0; d < 128; d++)
                    s = fmaf(pt[tok][d], cs[c][d], s);
                acc[i] = s;
            }
        }
        __syncthreads();
    }
#pragma unroll
    for (int i = 0; i < 5; i++) {
        int p = i * 256 + tid;
        if (p < 64 * NCLS) {
            int tok = p / NCLS, c = p % NCLS;
            g_masks[((long)b * NPATCH + t0 + tok) * NCLS + c] = acc[i];
        }
    }
}

// ---------------- mask LN + layout to [b,c,gy,gx] ---------------------------
__global__ void __launch_bounds__(256) maskln_kernel(
    const float* __restrict__ mg, const float* __restrict__ mb)
{
    const int warp = threadIdx.x >> 5, lane = threadIdx.x & 31;
    const int token = blockIdx.x * 8 + warp;
    const int b = token >> 10, n = token & 1023;
    float v = 0.f;
    if (lane < NCLS) v = g_masks[(long)token * NCLS + lane];
    float s = v;
#pragma unroll
    for (int o = 16; o > 0; o >>= 1) s += __shfl_xor_sync(0xffffffff, s, o);
    float mean = s * (1.f / (float)NCLS);
    float d = (lane < NCLS) ? v - mean : 0.f;
    float s2 = d * d;
#pragma unroll
    for (int o = 16; o > 0; o >>= 1) s2 += __shfl_xor_sync(0xffffffff, s2, o);
    float inv = rsqrtf(s2 * (1.f / (float)NCLS) + 1e-5f);
    if (lane < NCLS) {
        float o = d * inv * mg[lane] + mb[lane];
        int gy = n >> 5, gx = n & 31;
        g_mln[(((long)b * NCLS + lane) * GS + gy) * GS + gx] = o;
    }
}

// ---------------- bilinear 32x32 -> 512x512 ---------------------------------
__global__ void __launch_bounds__(256) resize_kernel(float* __restrict__ out)
{
    const int pix = blockIdx.x * 256 + threadIdx.x;
    const int c = blockIdx.y, b = blockIdx.z;
    const int ox = pix & 511, oy = pix >> 9;
    float fx = (ox + 0.5f) * 0.0625f - 0.5f;
    float fy = (oy + 0.5f) * 0.0625f - 0.5f;
    int ix0 = (int)floorf(fx), iy0 = (int)floorf(fy);
    float wx = fx - (float)ix0, wy = fy - (float)iy0;
    int x0 = max(ix0, 0), x1 = min(ix0 + 1, GS - 1);
    int y0 = max(iy0, 0), y1 = min(iy0 + 1, GS - 1);
    const float* m = g_mln + ((long)b * NCLS + c) * GS * GS;
    float v00 = m[y0 * GS + x0], v01 = m[y0 * GS + x1];
    float v10 = m[y1 * GS + x0], v11 = m[y1 * GS + x1];
    float v = (1.f - wy) * ((1.f - wx) * v00 + wx * v01)
            +        wy  * ((1.f - wx) * v10 + wx * v11);
    out[(((long)b * NCLS + c) * IMG + oy) * IMG + ox] = v;
}

// ---------------- host orchestration ----------------------------------------
static void* sym_addr(const void* sym)
{
    void* p = nullptr;
    cudaGetSymbolAddress(&p, sym);
    return p;
}

#define SMEM_H128 ((128 * 40 + 128 * 40) * 2 * 4)   // 81920
#define SMEM_H64  ((128 * 40 + 64 * 40) * 2 * 4)    // 61440

extern "C" void kernel_launch(void* const* d_in, const int* in_sizes, int n_in,
                              void* d_out, int out_size)
{
    (void)in_sizes; (void)n_in; (void)out_size;
    const float* x    = (const float*)d_in[0];
    const float* pdW  = (const float*)d_in[1];
    const float* pdb  = (const float*)d_in[2];
    const float* cls  = (const float*)d_in[3];
    const float* l1g  = (const float*)d_in[4];
    const float* l1b  = (const float*)d_in[5];
    const float* qW   = (const float*)d_in[6];
    const float* qb   = (const float*)d_in[7];
    const float* kW   = (const float*)d_in[8];
    const float* kb   = (const float*)d_in[9];
    const float* vW   = (const float*)d_in[10];
    const float* vb   = (const float*)d_in[11];
    const float* l2g  = (const float*)d_in[12];
    const float* l2b  = (const float*)d_in[13];
    const float* w1   = (const float*)d_in[14];
    const float* b1   = (const float*)d_in[15];
    const float* w2   = (const float*)d_in[16];
    const float* b2   = (const float*)d_in[17];
    const float* ppW  = (const float*)d_in[18];
    const float* pcW  = (const float*)d_in[19];
    const float* dg   = (const float*)d_in[20];
    const float* db   = (const float*)d_in[21];
    const float* mg   = (const float*)d_in[22];
    const float* mb   = (const float*)d_in[23];
    float* out = (float*)d_out;

    float*  gx   = (float*)sym_addr(g_x);
    float*  gh   = (float*)sym_addr(g_h);
    __half* ghh  = (__half*)sym_addr(g_hh);
    __half* gqh  = (__half*)sym_addr(g_qh);
    __half* gkh  = (__half*)sym_addr(g_kh);
    __half* gvh  = (__half*)sym_addr(g_vh);
    __half* gff  = (__half*)sym_addr(g_ff);
    float*  gpt  = (float*)sym_addr(g_patches);
    float*  gcl  = (float*)sym_addr(g_cls);
    __half* wt   = (__half*)sym_addr(g_wt);
    __half* wqkv = (__half*)sym_addr(g_wqkv);

    cudaFuncSetAttribute(hgemm<128>,
                         cudaFuncAttributeMaxDynamicSharedMemorySize, SMEM_H128);
    cudaFuncSetAttribute(hgemm<64>,
                         cudaFuncAttributeMaxDynamicSharedMemorySize, SMEM_H64);
    cudaFuncSetAttribute(fattn_kernel,
                         cudaFuncAttributeMaxDynamicSharedMemorySize, FA_SMEM);

    const dim3 blk(256);
    const dim3 tsb(32, 8);
    const int mtiles = (M_ + 127) / 128;      // 66

    // ---- one-time prep ----
    wtrans_kernel<<<dim3(FF / 32, D_ / 32), tsb>>>(w1,                 D_, FF, wt + OFF_W1_0);
    wtrans_kernel<<<dim3(FF / 32, D_ / 32), tsb>>>(w1 + (long)D_ * FF, D_, FF, wt + OFF_W1_1);
    wtrans_kernel<<<dim3(D_ / 32, FF / 32), tsb>>>(w2,                 FF, D_, wt + OFF_W2_0);
    wtrans_kernel<<<dim3(D_ / 32, FF / 32), tsb>>>(w2 + (long)FF * D_, FF, D_, wt + OFF_W2_1);
    wtrans_kernel<<<dim3(D_ / 32, D_ / 32), tsb>>>(pdW, D_, D_, wt + OFF_PD);
    wtrans_kernel<<<dim3(D_ / 32, D_ / 32), tsb>>>(ppW, D_, D_, wt + OFF_PP);
    wtrans_kernel<<<dim3(D_ / 32, D_ / 32), tsb>>>(pcW, D_, D_, wt + OFF_PC);
    qkvw_kernel<<<dim3(2, 2, 72), tsb>>>(qW, kW, vW);
    cvtx_kernel<<<(B_ * NPATCH * D_ / 2 + 255) / 256, 256>>>(x);

    // ---- x(half) @ proj_dec + b -> g_x patch rows ----
    hgemm<128><<<dim3(6, 8, B_), blk, SMEM_H128>>>(
        ghh, wt + OFF_PD, pdb, gx,
        NPATCH, D_, D_, D_, D_, D_,
        1, (long)NPATCH * D_, 0, 0, 0, (long)S_ * D_, 0, 0, 1);
    fill_cls_kernel<<<(NCLS * D_ + 255) / 256, 256>>>(cls);

    for (int l = 0; l < 2; l++) {
        ln_kernel<<<M_, blk>>>(gx, l1g + l * D_, l1b + l * D_, gh, ghh);

        // qkv via batched per-head tensor-core GEMM (12 heads in z)
        const long wq = (long)(l * 3 + 0) * 12 * 4096;
        const long wk = (long)(l * 3 + 1) * 12 * 4096;
        const long wv = (long)(l * 3 + 2) * 12 * 4096;
        hgemm<64><<<dim3(1, mtiles, NH), blk, SMEM_H64>>>(
            ghh, wqkv + wq, qb + (long)l * NH * DH, gqh,
            M_, DH, DH, D_, DH, D_,
            NH, 0, DH, 0, 4096, 0, DH, DH, 1 | 16 | 32);
        hgemm<64><<<dim3(1, mtiles, NH), blk, SMEM_H64>>>(
            ghh, wqkv + wk, kb + (long)l * NH * DH, gkh,
            M_, DH, DH, D_, DH, D_,
            NH, 0, DH, 0, 4096, 0, DH, DH, 1 | 16);
        hgemm<64><<<dim3(1, mtiles, NH), blk, SMEM_H64>>>(
            ghh, wqkv + wv, vb + (long)l * NH * DH, gvh,
            M_, DH, DH, D_, DH, D_,
            NH, 0, DH, 0, 4096, 0, DH, DH, 1 | 16);
        vtrans_kernel<<<dim3(D_ / 32, SQ / 32, B_), tsb>>>();

        fattn_kernel<<<dim3((S_ + 127) / 128, BHD), blk, FA_SMEM>>>();

        ln_kernel<<<M_, blk>>>(gx, l2g + l * D_, l2b + l * D_, gh, ghh);

        hgemm<128><<<dim3(FF / 128, mtiles, 1), blk, SMEM_H128>>>(
            ghh, wt + (l ? OFF_W1_1 : OFF_W1_0), b1 + (long)l * FF, gff,
            M_, FF, D_, D_, D_, FF,
            1, 0, 0, 0, 0, 0, 0, 0, 1 | 2 | 16);
        hgemm<128><<<dim3(D_ / 128, mtiles, 1), blk, SMEM_H128>>>(
            gff, wt + (l ? OFF_W2_1 : OFF_W2_0), b2 + (long)l * D_, gx,
            M_, D_, FF, FF, FF, D_,
            1, 0, 0, 0, 0, 0, 0, 0, 1 | 4);
    }

    ln_kernel<<<M_, blk>>>(gx, dg, db, gh, ghh);

    hgemm<128><<<dim3(6, 8, B_), blk, SMEM_H128>>>(
        ghh, wt + OFF_PP, nullptr, gpt,
        NPATCH, D_, D_, D_, D_, D_,
        1, (long)S_ * D_, 0, 0, 0, (long)NPATCH * D_, 0, 0, 0);
    hgemm<128><<<dim3(6, 1, B_), blk, SMEM_H128>>>(
        ghh + (long)NPATCH * D_, wt + OFF_PC, nullptr, gcl,
        NCLS, D_, D_, D_, D_, D_,
        1, (long)S_ * D_, 0, 0, 0, (long)NCLS * D_, 0, 0, 0);

    l2norm_kernel<<<B_ * NPATCH, blk>>>(gpt);
    l2norm_kernel<<<B_ * NCLS, blk>>>(gcl);

    masks_kernel<<<dim3(NPATCH / 64, B_), blk>>>();
    maskln_kernel<<<(B_ * NPATCH) / 8, blk>>>(mg, mb);
    resize_kernel<<<dim3(IMG * IMG / 256, NCLS, B_), blk>>>(out);
}

// round 11
// speedup vs baseline: 6.1972x; 1.0751x over previous
#include <cuda_runtime.h>
#include <cuda_fp16.h>
#include <math.h>
#include <stdint.h>

// ---------------- problem constants ----------------
#define B_      8
#define S_      1043
#define NPATCH  1024
#define NCLS    19
#define D_      768
#define NH      12
#define DH      64
#define FF      3072
#define GS      32
#define IMG     512
#define M_      (B_*S_)         // 8344
#define BHD     (B_*NH)         // 96
#define MPAD    8576
#define TKV     64
#define NKT     17              // ceil(S_/64)

// ---------------- scratch ----------------------------------------------------
__device__ float g_x[(size_t)M_ * D_];
__device__ __align__(128) __half g_hh[(size_t)MPAD * D_];
#define MDSEG ((size_t)M_ * D_ + 128 * D_)
__device__ __align__(128) __half g_qkvh[3 * MDSEG];   // q | k | v segments
__device__ __align__(128) __half g_ff[(size_t)MPAD * FF];
__device__ float g_patches[(size_t)B_ * NPATCH * D_];
__device__ float g_cls[(size_t)B_ * NCLS * D_];
__device__ float g_masks[(size_t)B_ * NPATCH * NCLS];
__device__ float g_mln[(size_t)B_ * NCLS * GS * GS];

#define WTOT 11206656
__device__ __align__(128) __half g_wt[WTOT];
#define OFF_W1_0 0
#define OFF_W1_1 2359296
#define OFF_W2_0 4718592
#define OFF_W2_1 7077888
#define OFF_PD   9437184
#define OFF_PP   10027008
#define OFF_PC   10616832
// per-head transposed qkv weights: [(l*3+m)*12+h] x [e][d] 64x64
__device__ __align__(128) __half g_wqkv[72 * 4096];

// ---------------- helpers ----------------------------------------------------
__device__ __forceinline__ float gelu_exact(float v) {
    return 0.5f * v * (1.f + erff(v * 0.70710678118654752f));
}
__device__ __forceinline__ uint32_t smem_to_u32(const void* p) {
    uint32_t a;
    asm("{ .reg .u64 t; cvta.to.shared.u64 t, %1; cvt.u32.u64 %0, t; }"
        : "=r"(a) : "l"(p));
    return a;
}
__device__ __forceinline__ unsigned packh2(float a, float b) {
    __half2 h = __floats2half2_rn(a, b);
    return *(unsigned*)&h;
}
#define CP16(dst, src) \
    asm volatile("cp.async.cg.shared.global [%0], [%1], 16;" :: "r"(dst), "l"(src))
#define CPCOMMIT() asm volatile("cp.async.commit_group;")
#define CPWAIT0()  asm volatile("cp.async.wait_group 0;")
#define CPWAIT1()  asm volatile("cp.async.wait_group 1;")
#define CPWAIT2()  asm volatile("cp.async.wait_group 2;")

#define HMMA(acc, a0, a1, a2, a3, b0, b1) \
    asm volatile( \
        "mma.sync.aligned.m16n8k16.row.col.f32.f16.f16.f32 " \
        "{%0,%1,%2,%3},{%4,%5,%6,%7},{%8,%9},{%0,%1,%2,%3};" \
        : "+f"((acc)[0]), "+f"((acc)[1]), "+f"((acc)[2]), "+f"((acc)[3]) \
        : "r"(a0), "r"(a1), "r"(a2), "r"(a3), "r"(b0), "r"(b1))

#define LDSM4(r0, r1, r2, r3, addr) \
    asm volatile("ldmatrix.sync.aligned.m8n8.x4.shared.b16 {%0,%1,%2,%3}, [%4];" \
        : "=r"(r0), "=r"(r1), "=r"(r2), "=r"(r3) : "r"(addr))
#define LDSM4T(r0, r1, r2, r3, addr) \
    asm volatile("ldmatrix.sync.aligned.m8n8.x4.trans.shared.b16 {%0,%1,%2,%3}, [%4];" \
        : "=r"(r0), "=r"(r1), "=r"(r2), "=r"(r3) : "r"(addr))

// ---------------- fp16 tensor-core GEMM (MLP / projections) ------------------
// C[M,*] = A[M,K] @ B[N,K]^T. flags: 1 bias, 2 gelu, 4 +=C(fp32), 16 C half.
template<int BN>
__global__ void __launch_bounds__(256) hgemm(
    const __half* __restrict__ A, const __half* __restrict__ Bm,
    const float* __restrict__ bias, void* __restrict__ Cv,
    int M, int Nlim, int K, int lda, int ldb, int ldc,
    int HZ, long sA, long hA, long sB, long hB, long sC, long hC,
    int flags)
{
    constexpr int NT   = BN / 16;
    constexpr int ASTH = 128 * 40;
    constexpr int BSTH = BN * 40;
    constexpr int STH  = ASTH + BSTH;
    extern __shared__ __half smh[];

    const int z = blockIdx.z;
    A  += (long)(z / HZ) * sA + (long)(z % HZ) * hA;
    Bm += (long)(z / HZ) * sB + (long)(z % HZ) * hB;

    const int tid = threadIdx.x, warp = tid >> 5, lane = tid & 31;
    const int wm = warp & 3, wn = warp >> 2;
    const int l4 = lane >> 2, lm = lane & 3;
    const int m0 = blockIdx.y * 128, n0 = blockIdx.x * BN;
    const uint32_t sb = smem_to_u32(smh);
    const int nch = K >> 5;

    const int arow = (lane & 15), acol8 = (lane >> 4) * 8;
    const int bn_l = ((lane >> 4) & 1) * 8 + (lane & 7);
    const int bc_l = ((lane >> 3) & 1) * 8;

    auto issue = [&](int kc) {
        if (kc < nch) {
            const int st = kc & 3;
            const uint32_t ab = sb + (uint32_t)(st * STH) * 2u;
            const uint32_t bb = ab + (uint32_t)ASTH * 2u;
            const int k0 = kc << 5;
            const __half* Ap = A + (long)m0 * lda + k0;
#pragma unroll
            for (int i = 0; i < 2; i++) {
                int q = i * 256 + tid;
                int row = q >> 2, seg = (q & 3) * 8;
                CP16(ab + (uint32_t)(row * 40 + seg) * 2u,
                     Ap + (long)row * lda + seg);
            }
            const __half* Bp = Bm + (long)n0 * ldb + k0;
#pragma unroll
            for (int i = 0; i < BN / 64; i++) {
                int q = i * 256 + tid;
                int row = q >> 2, seg = (q & 3) * 8;
                CP16(bb + (uint32_t)(row * 40 + seg) * 2u,
                     Bp + (long)row * ldb + seg);
            }
        }
        CPCOMMIT();
    };

    float acc[2][NT][4];
#pragma unroll
    for (int i = 0; i < 2; i++)
#pragma unroll
        for (int j = 0; j < NT; j++)
#pragma unroll
            for (int c = 0; c < 4; c++) acc[i][j][c] = 0.f;

    issue(0); issue(1); issue(2);

    for (int c = 0; c < nch; c++) {
        CPWAIT2();
        __syncthreads();
        issue(c + 3);

        const uint32_t as = sb + (uint32_t)((c & 3) * STH) * 2u;
        const uint32_t bs = as + (uint32_t)ASTH * 2u;
#pragma unroll
        for (int kk = 0; kk < 32; kk += 16) {
            unsigned af[2][4];
#pragma unroll
            for (int i = 0; i < 2; i++) {
                uint32_t addr = as + (uint32_t)((wm * 32 + i * 16 + arow) * 40
                                                + kk + acol8) * 2u;
                LDSM4(af[i][0], af[i][1], af[i][2], af[i][3], addr);
            }
#pragma unroll
            for (int g = 0; g < NT / 2; g++) {
                unsigned b0, b1, b2, b3;
                uint32_t addr = bs + (uint32_t)((wn * (BN / 2) + g * 16 + bn_l) * 40
                                                + kk + bc_l) * 2u;
                LDSM4(b0, b1, b2, b3, addr);
#pragma unroll
                for (int i = 0; i < 2; i++) {
                    HMMA(acc[i][2 * g],     af[i][0], af[i][1], af[i][2], af[i][3], b0, b1);
                    HMMA(acc[i][2 * g + 1], af[i][0], af[i][1], af[i][2], af[i][3], b2, b3);
                }
            }
        }
    }

    float*  Cf = (float*)Cv  + (long)(z / HZ) * sC + (long)(z % HZ) * hC;
    __half* Ch = (__half*)Cv + (long)(z / HZ) * sC + (long)(z % HZ) * hC;
#pragma unroll
    for (int i = 0; i < 2; i++)
#pragma unroll
        for (int j = 0; j < NT; j++)
#pragma unroll
            for (int h = 0; h < 2; h++) {
                int row = m0 + wm * 32 + i * 16 + l4 + h * 8;
                if (row >= M) continue;
                int col = n0 + wn * (BN / 2) + j * 8 + lm * 2;
                if (col >= Nlim) continue;
                float v0 = acc[i][j][h * 2 + 0];
                float v1 = acc[i][j][h * 2 + 1];
                bool has1 = (col + 1 < Nlim);
                if (flags & 1) {
                    v0 += bias[col];
                    if (has1) v1 += bias[col + 1];
                }
                if (flags & 2)  { v0 = gelu_exact(v0); v1 = gelu_exact(v1); }
                if (flags & 16) {
                    __half* hp = Ch + (long)row * ldc + col;
                    if (has1) *(__half2*)hp = __floats2half2_rn(v0, v1);
                    else      hp[0] = __float2half_rn(v0);
                } else {
                    float* cp = Cf + (long)row * ldc + col;
                    if (has1) {
                        if (flags & 4) { float2 o = *(float2*)cp; v0 += o.x; v1 += o.y; }
                        float2 st; st.x = v0; st.y = v1;
                        *(float2*)cp = st;
                    } else {
                        if (flags & 4) v0 += cp[0];
                        cp[0] = v0;
                    }
                }
            }
}

// ---------------- fused qkv GEMM: one launch for q,k,v x 12 heads -----------
// grid (1, 66, 36): z = m*12+h. C[m-seg][row][h*64+col] = LN(x)[.., h*64+d] @ W^T + b
#define QKV_ASTH (128 * 40)
#define QKV_BSTH (64 * 40)
#define QKV_STH  (QKV_ASTH + QKV_BSTH)
__global__ void __launch_bounds__(256) qkv_gemm(
    const __half* __restrict__ A, const __half* __restrict__ Wl,
    const float* __restrict__ qb, const float* __restrict__ kb,
    const float* __restrict__ vb)
{
    extern __shared__ __half smh[];
    const int z = blockIdx.z;
    const int m = z / NH, h = z % NH;
    const __half* Bm = Wl + (long)z * 4096;      // [64 e][64 d]
    const float* bias = (m == 0 ? qb : m == 1 ? kb : vb) + h * DH;
    const float scale = (m == 0) ? 0.125f : 1.f;
    __half* C = g_qkvh + (size_t)m * MDSEG + h * DH;

    const int tid = threadIdx.x, warp = tid >> 5, lane = tid & 31;
    const int wm = warp & 3, wn = warp >> 2;
    const int l4 = lane >> 2, lm = lane & 3;
    const int m0 = blockIdx.y * 128;
    const uint32_t sb = smem_to_u32(smh);

    const int arow = (lane & 15), acol8 = (lane >> 4) * 8;
    const int bn_l = ((lane >> 4) & 1) * 8 + (lane & 7);
    const int bc_l = ((lane >> 3) & 1) * 8;

    auto issue = [&](int kc) {
        if (kc < 2) {
            const int st = kc & 3;
            const uint32_t ab = sb + (uint32_t)(st * QKV_STH) * 2u;
            const uint32_t bb = ab + (uint32_t)QKV_ASTH * 2u;
            const int k0 = kc << 5;
            // FIX (R10 bug): A reduction slice is this head's own 64 dims.
            const __half* Ap = A + (long)m0 * D_ + h * DH + k0;
#pragma unroll
            for (int i = 0; i < 2; i++) {
                int q = i * 256 + tid;
                int row = q >> 2, seg = (q & 3) * 8;
                CP16(ab + (uint32_t)(row * 40 + seg) * 2u,
                     Ap + (long)row * D_ + seg);
            }
            {
                int row = tid >> 2, seg = (tid & 3) * 8;
                CP16(bb + (uint32_t)(row * 40 + seg) * 2u,
                     Bm + (long)row * DH + k0 + seg);
            }
        }
        CPCOMMIT();
    };

    float acc[2][4][4];
#pragma unroll
    for (int i = 0; i < 2; i++)
#pragma unroll
        for (int j = 0; j < 4; j++)
#pragma unroll
            for (int c = 0; c < 4; c++) acc[i][j][c] = 0.f;

    issue(0); issue(1); issue(2);

    for (int c = 0; c < 2; c++) {
        CPWAIT2();
        __syncthreads();
        issue(c + 3);
        const uint32_t as = sb + (uint32_t)((c & 3) * QKV_STH) * 2u;
        const uint32_t bs = as + (uint32_t)QKV_ASTH * 2u;
#pragma unroll
        for (int kk = 0; kk < 32; kk += 16) {
            unsigned af[2][4];
#pragma unroll
            for (int i = 0; i < 2; i++) {
                uint32_t addr = as + (uint32_t)((wm * 32 + i * 16 + arow) * 40
                                                + kk + acol8) * 2u;
                LDSM4(af[i][0], af[i][1], af[i][2], af[i][3], addr);
            }
#pragma unroll
            for (int g = 0; g < 2; g++) {
                unsigned b0, b1, b2, b3;
                uint32_t addr = bs + (uint32_t)((wn * 32 + g * 16 + bn_l) * 40
                                                + kk + bc_l) * 2u;
                LDSM4(b0, b1, b2, b3, addr);
#pragma unroll
                for (int i = 0; i < 2; i++) {
                    HMMA(acc[i][2 * g],     af[i][0], af[i][1], af[i][2], af[i][3], b0, b1);
                    HMMA(acc[i][2 * g + 1], af[i][0], af[i][1], af[i][2], af[i][3], b2, b3);
                }
            }
        }
    }

#pragma unroll
    for (int i = 0; i < 2; i++)
#pragma unroll
        for (int j = 0; j < 4; j++)
#pragma unroll
            for (int hh = 0; hh < 2; hh++) {
                int row = m0 + wm * 32 + i * 16 + l4 + hh * 8;
                if (row >= M_) continue;
                int col = wn * 32 + j * 8 + lm * 2;
                float v0 = (acc[i][j][hh * 2 + 0] + bias[col])     * scale;
                float v1 = (acc[i][j][hh * 2 + 1] + bias[col + 1]) * scale;
                *(__half2*)(C + (long)row * D_ + col) = __floats2half2_rn(v0, v1);
            }
}

// ---------------- fused flash attention (V via trans-ldmatrix) --------------
#define FA_QS 0
#define FA_KS (128 * 72)
#define FA_VS (128 * 72 + 2 * 64 * 72)
#define FA_SMEM ((128 * 72 + 4 * 64 * 72) * 2)
__global__ void __launch_bounds__(256) fattn_kernel()
{
    extern __shared__ __half sh[];
    const int z = blockIdx.y;
    const int b = z / NH, hd = z % NH;
    const int m0 = blockIdx.x * 128;
    const int tid = threadIdx.x, warp = tid >> 5, lane = tid & 31;
    const int l4 = lane >> 2, lm = lane & 3;
    const uint32_t sb = smem_to_u32(sh);

    const __half* Qg = g_qkvh + 0 * MDSEG + ((long)b * S_ + m0) * D_ + hd * DH;
    const __half* Kg = g_qkvh + 1 * MDSEG + (long)b * S_ * D_ + hd * DH;
    const __half* Vg = g_qkvh + 2 * MDSEG + (long)b * S_ * D_ + hd * DH;

    const int arow = (lane & 15), acol8 = (lane >> 4) * 8;
    const int bn_l = ((lane >> 4) & 1) * 8 + (lane & 7);
    const int bc_l = ((lane >> 3) & 1) * 8;
    const int tvr = ((lane >> 3) & 1) * 8 + (lane & 7);   // kv offset
    const int tvc = ((lane >> 4) & 1) * 8;                // d offset

    auto loadKV = [&](int kt) {
        const int st = kt & 1;
        const __half* Kp = Kg + (long)(kt * TKV) * D_;
        const __half* Vp = Vg + (long)(kt * TKV) * D_;
        const uint32_t kb = sb + (uint32_t)(FA_KS + st * 64 * 72) * 2u;
        const uint32_t vb = sb + (uint32_t)(FA_VS + st * 64 * 72) * 2u;
#pragma unroll
        for (int i = 0; i < 2; i++) {
            int q = i * 256 + tid;
            int row = q >> 3, seg = (q & 7) * 8;
            CP16(kb + (uint32_t)(row * 72 + seg) * 2u, Kp + (long)row * D_ + seg);
        }
#pragma unroll
        for (int i = 0; i < 2; i++) {
            int q = i * 256 + tid;
            int row = q >> 3, seg = (q & 7) * 8;
            CP16(vb + (uint32_t)(row * 72 + seg) * 2u, Vp + (long)row * D_ + seg);
        }
    };

#pragma unroll
    for (int i = 0; i < 4; i++) {
        int q = i * 256 + tid;
        int row = q >> 3, seg = (q & 7) * 8;
        CP16(sb + (uint32_t)(FA_QS + row * 72 + seg) * 2u, Qg + (long)row * D_ + seg);
    }
    loadKV(0);
    CPCOMMIT();
    CPWAIT0();
    __syncthreads();

    unsigned qa[4][4];
#pragma unroll
    for (int kc = 0; kc < 4; kc++) {
        uint32_t addr = sb + (uint32_t)(FA_QS + (warp * 16 + arow) * 72
                                        + kc * 16 + acol8) * 2u;
        LDSM4(qa[kc][0], qa[kc][1], qa[kc][2], qa[kc][3], addr);
    }

    float oacc[8][4];
#pragma unroll
    for (int j = 0; j < 8; j++)
#pragma unroll
        for (int c = 0; c < 4; c++) oacc[j][c] = 0.f;
    float mr0 = -1e30f, mr1 = -1e30f, lr0 = 0.f, lr1 = 0.f;

    for (int kt = 0; kt < NKT; kt++) {
        __syncthreads();
        if (kt + 1 < NKT) { loadKV(kt + 1); CPCOMMIT(); CPWAIT1(); }
        else              { CPWAIT0(); }
        __syncthreads();

        const uint32_t ks = sb + (uint32_t)(FA_KS + (kt & 1) * 64 * 72) * 2u;
        const uint32_t vs = sb + (uint32_t)(FA_VS + (kt & 1) * 64 * 72) * 2u;

        float sacc[8][4];
#pragma unroll
        for (int j = 0; j < 8; j++)
#pragma unroll
            for (int c = 0; c < 4; c++) sacc[j][c] = 0.f;
#pragma unroll
        for (int kc = 0; kc < 4; kc++)
#pragma unroll
            for (int g = 0; g < 4; g++) {
                unsigned b0, b1, b2, b3;
                uint32_t addr = ks + (uint32_t)((g * 16 + bn_l) * 72
                                                + kc * 16 + bc_l) * 2u;
                LDSM4(b0, b1, b2, b3, addr);
                HMMA(sacc[2 * g],     qa[kc][0], qa[kc][1], qa[kc][2], qa[kc][3], b0, b1);
                HMMA(sacc[2 * g + 1], qa[kc][0], qa[kc][1], qa[kc][2], qa[kc][3], b2, b3);
            }

        const int base = kt * TKV;
        if (base + TKV > S_) {
#pragma unroll
            for (int j = 0; j < 8; j++) {
                int c0 = base + j * 8 + 2 * lm;
                if (c0 >= S_)     { sacc[j][0] = -1e30f; sacc[j][2] = -1e30f; }
                if (c0 + 1 >= S_) { sacc[j][1] = -1e30f; sacc[j][3] = -1e30f; }
            }
        }

        float tm0 = -1e30f, tm1 = -1e30f;
#pragma unroll
        for (int j = 0; j < 8; j++) {
            tm0 = fmaxf(tm0, fmaxf(sacc[j][0], sacc[j][1]));
            tm1 = fmaxf(tm1, fmaxf(sacc[j][2], sacc[j][3]));
        }
        tm0 = fmaxf(tm0, __shfl_xor_sync(0xffffffff, tm0, 1));
        tm0 = fmaxf(tm0, __shfl_xor_sync(0xffffffff, tm0, 2));
        tm1 = fmaxf(tm1, __shfl_xor_sync(0xffffffff, tm1, 1));
        tm1 = fmaxf(tm1, __shfl_xor_sync(0xffffffff, tm1, 2));
        float mn0 = fmaxf(mr0, tm0), mn1 = fmaxf(mr1, tm1);
        float sc0 = __expf(mr0 - mn0), sc1 = __expf(mr1 - mn1);
        float rs0 = 0.f, rs1 = 0.f;
#pragma unroll
        for (int j = 0; j < 8; j++) {
            sacc[j][0] = __expf(sacc[j][0] - mn0);
            sacc[j][1] = __expf(sacc[j][1] - mn0);
            sacc[j][2] = __expf(sacc[j][2] - mn1);
            sacc[j][3] = __expf(sacc[j][3] - mn1);
            rs0 += sacc[j][0] + sacc[j][1];
            rs1 += sacc[j][2] + sacc[j][3];
        }
        rs0 += __shfl_xor_sync(0xffffffff, rs0, 1);
        rs0 += __shfl_xor_sync(0xffffffff, rs0, 2);
        rs1 += __shfl_xor_sync(0xffffffff, rs1, 1);
        rs1 += __shfl_xor_sync(0xffffffff, rs1, 2);
        lr0 = lr0 * sc0 + rs0;
        lr1 = lr1 * sc1 + rs1;
        mr0 = mn0; mr1 = mn1;
#pragma unroll
        for (int j = 0; j < 8; j++) {
            oacc[j][0] *= sc0; oacc[j][1] *= sc0;
            oacc[j][2] *= sc1; oacc[j][3] *= sc1;
        }

        // O += P @ V ; V stored [kv][d], fragments via ldmatrix.trans
#pragma unroll
        for (int kc2 = 0; kc2 < 4; kc2++) {
            unsigned pa0 = packh2(sacc[2 * kc2][0],     sacc[2 * kc2][1]);
            unsigned pa1 = packh2(sacc[2 * kc2][2],     sacc[2 * kc2][3]);
            unsigned pa2 = packh2(sacc[2 * kc2 + 1][0], sacc[2 * kc2 + 1][1]);
            unsigned pa3 = packh2(sacc[2 * kc2 + 1][2], sacc[2 * kc2 + 1][3]);
#pragma unroll
            for (int g = 0; g < 4; g++) {
                unsigned b0, b1, b2, b3;
                uint32_t addr = vs + (uint32_t)((kc2 * 16 + tvr) * 72
                                                + g * 16 + tvc) * 2u;
                LDSM4T(b0, b1, b2, b3, addr);
                HMMA(oacc[2 * g],     pa0, pa1, pa2, pa3, b0, b1);
                HMMA(oacc[2 * g + 1], pa0, pa1, pa2, pa3, b2, b3);
            }
        }
    }

    const int q0 = m0 + warp * 16 + l4;
    const int q1 = q0 + 8;
    const float inv0 = 1.f / lr0, inv1 = 1.f / lr1;
#pragma unroll
    for (int jd = 0; jd < 8; jd++) {
        int d = hd * DH + jd * 8 + 2 * lm;
        if (q0 < S_) {
            float* p = g_x + ((long)b * S_ + q0) * D_ + d;
            float2 o = *(float2*)p;
            o.x += oacc[jd][0] * inv0;
            o.y += oacc[jd][1] * inv0;
            *(float2*)p = o;
        }
        if (q1 < S_) {
            float* p = g_x + ((long)b * S_ + q1) * D_ + d;
            float2 o = *(float2*)p;
            o.x += oacc[jd][2] * inv1;
            o.y += oacc[jd][3] * inv1;
            *(float2*)p = o;
        }
    }
}

// ---------------- weight transpose + half: [K,N] -> [N,K] -------------------
__global__ void wtrans_kernel(const float* __restrict__ src, int K, int N,
                              __half* __restrict__ dst)
{
    __shared__ float t[32][33];
    int n0 = blockIdx.x * 32, k0 = blockIdx.y * 32;
    int tx = threadIdx.x, ty = threadIdx.y;
#pragma unroll
    for (int i = 0; i < 32; i += 8)
        t[ty + i][tx] = src[(long)(k0 + ty + i) * N + n0 + tx];
    __syncthreads();
#pragma unroll
    for (int i = 0; i < 32; i += 8)
        dst[(long)(n0 + ty + i) * K + k0 + tx] = __float2half_rn(t[tx][ty + i]);
}

// ---------------- qkv per-head weight transpose [d,e]->[e,d] half -----------
__global__ void qkvw_kernel(const float* __restrict__ qW,
                            const float* __restrict__ kW,
                            const float* __restrict__ vW)
{
    __shared__ float t[32][33];
    const int z = blockIdx.z;          // 0..71
    const int l = z / 36, rr = z % 36, m = rr / 12, h = rr % 12;
    const float* src = (m == 0 ? qW : m == 1 ? kW : vW) + ((long)(l * 12 + h) * 64) * 64;
    __half* dst = g_wqkv + (long)z * 4096;
    const int e0 = blockIdx.x * 32, d0 = blockIdx.y * 32;
    const int tx = threadIdx.x, ty = threadIdx.y;
#pragma unroll
    for (int i = 0; i < 32; i += 8)
        t[ty + i][tx] = src[(d0 + ty + i) * 64 + e0 + tx];   // t[d][e]
    __syncthreads();
#pragma unroll
    for (int i = 0; i < 32; i += 8)
        dst[(e0 + ty + i) * 64 + d0 + tx] = __float2half_rn(t[tx][ty + i]);
}

// ---------------- x (fp32) -> g_hh (half) ------------------------------------
__global__ void cvtx_kernel(const float* __restrict__ x)
{
    long i = ((long)blockIdx.x * 256 + threadIdx.x) * 2;
    if (i >= (long)B_ * NPATCH * D_) return;
    float2 v = *(const float2*)(x + i);
    *(__half2*)(g_hh + i) = __floats2half2_rn(v.x, v.y);
}

// ---------------- LayerNorm, warp-per-row, half output only -----------------
__global__ void __launch_bounds__(256) ln_kernel(
    const float* __restrict__ x, const float* __restrict__ g,
    const float* __restrict__ bta, __half* __restrict__ outh)
{
    const int warp = threadIdx.x >> 5, lane = threadIdx.x & 31;
    const long r = (long)blockIdx.x * 8 + warp;
    const float* xr = x + r * D_;
    float v[24];
    float s = 0.f, s2 = 0.f;
#pragma unroll
    for (int i = 0; i < 6; i++) {
        float4 t = *(const float4*)(xr + i * 128 + lane * 4);
        v[i * 4 + 0] = t.x; v[i * 4 + 1] = t.y;
        v[i * 4 + 2] = t.z; v[i * 4 + 3] = t.w;
        s  += t.x + t.y + t.z + t.w;
        s2 += t.x * t.x + t.y * t.y + t.z * t.z + t.w * t.w;
    }
#pragma unroll
    for (int o = 16; o > 0; o >>= 1) {
        s  += __shfl_xor_sync(0xffffffff, s, o);
        s2 += __shfl_xor_sync(0xffffffff, s2, o);
    }
    float mean = s * (1.f / 768.f);
    float var  = s2 * (1.f / 768.f) - mean * mean;
    float inv  = rsqrtf(var + 1e-5f);
    __half* hrow = outh + r * D_;
#pragma unroll
    for (int i = 0; i < 6; i++) {
        int c = i * 128 + lane * 4;
        float4 gg = *(const float4*)(g + c);
        float4 bb = *(const float4*)(bta + c);
        float o0 = (v[i * 4 + 0] - mean) * inv * gg.x + bb.x;
        float o1 = (v[i * 4 + 1] - mean) * inv * gg.y + bb.y;
        float o2 = (v[i * 4 + 2] - mean) * inv * gg.z + bb.z;
        float o3 = (v[i * 4 + 3] - mean) * inv * gg.w + bb.w;
        uint2 st;
        st.x = packh2(o0, o1);
        st.y = packh2(o2, o3);
        *(uint2*)(hrow + c) = st;
    }
}

// ---------------- L2 row normalize (in place), warp-per-row -----------------
__global__ void __launch_bounds__(256) l2norm_kernel(float* __restrict__ x)
{
    const int warp = threadIdx.x >> 5, lane = threadIdx.x & 31;
    const long r = (long)blockIdx.x * 8 + warp;
    float* xr = x + r * D_;
    float v[24];
    float s2 = 0.f;
#pragma unroll
    for (int i = 0; i < 6; i++) {
        float4 t = *(const float4*)(xr + i * 128 + lane * 4);
        v[i * 4 + 0] = t.x; v[i * 4 + 1] = t.y;
        v[i * 4 + 2] = t.z; v[i * 4 + 3] = t.w;
        s2 += t.x * t.x + t.y * t.y + t.z * t.z + t.w * t.w;
    }
#pragma unroll
    for (int o = 16; o > 0; o >>= 1)
        s2 += __shfl_xor_sync(0xffffffff, s2, o);
    float inv = rsqrtf(s2);
#pragma unroll
    for (int i = 0; i < 6; i++) {
        float4 t;
        t.x = v[i * 4 + 0] * inv; t.y = v[i * 4 + 1] * inv;
        t.z = v[i * 4 + 2] * inv; t.w = v[i * 4 + 3] * inv;
        *(float4*)(xr + i * 128 + lane * 4) = t;
    }
}

// ---------------- broadcast cls_emb into g_x cls rows -----------------------
__global__ void fill_cls_kernel(const float* __restrict__ cls_emb)
{
    int idx = blockIdx.x * 256 + threadIdx.x;
    if (idx >= NCLS * D_) return;
    float v = cls_emb[idx];
    int c = idx / D_, d = idx % D_;
#pragma unroll
    for (int b = 0; b < B_; b++)
        g_x[(long)(b * S_ + NPATCH + c) * D_ + d] = v;
}

// ---------------- masks[b,n,c] = patches[b,n,:] . cls[b,c,:] (fp32) ---------
__global__ void __launch_bounds__(256) masks_kernel()
{
    __shared__ float pt[64][128];
    __shared__ float cs[NCLS][128];
    const int b = blockIdx.y;
    const int t0 = blockIdx.x * 64;
    const int tid = threadIdx.x;
    float acc[5];
#pragma unroll
    for (int i = 0; i < 5; i++) acc[i] = 0.f;

    for (int d0 = 0; d0 < D_; d0 += 128) {
#pragma unroll
        for (int i = 0; i < 8; i++) {
            int f = i * 256 + tid;
            int row = f >> 5, c4 = (f & 31) * 4;
            *(float4*)&pt[row][c4] =
                *(const float4*)(g_patches + (long)(b * NPATCH + t0 + row) * D_ + d0 + c4);
        }
        for (int f = tid; f < NCLS * 32; f += 256) {
            int row = f >> 5, c4 = (f & 31) * 4;
            *(float4*)&cs[row][c4] =
                *(const float4*)(g_cls + (long)(b * NCLS + row) * D_ + d0 + c4);
        }
        __syncthreads();
#pragma unroll
        for (int i = 0; i < 5; i++) {
            int p = i * 256 + tid;
            if (p < 64 * NCLS) {
                int tok = p / NCLS, c = p % NCLS;
                float s = acc[i];
#pragma unroll 8
                for (int d = 0; d < 128; d++)
                    s = fmaf(pt[tok][d], cs[c][d], s);
                acc[i] = s;
            }
        }
        __syncthreads();
    }
#pragma unroll
    for (int i = 0; i < 5; i++) {
        int p = i * 256 + tid;
        if (p < 64 * NCLS) {
            int tok = p / NCLS, c = p % NCLS;
            g_masks[((long)b * NPATCH + t0 + tok) * NCLS + c] = acc[i];
        }
    }
}

// ---------------- mask LN + layout to [b,c,gy,gx] ---------------------------
__global__ void __launch_bounds__(256) maskln_kernel(
    const float* __restrict__ mg, const float* __restrict__ mb)
{
    const int warp = threadIdx.x >> 5, lane = threadIdx.x & 31;
    const int token = blockIdx.x * 8 + warp;
    const int b = token >> 10, n = token & 1023;
    float v = 0.f;
    if (lane < NCLS) v = g_masks[(long)token * NCLS + lane];
    float s = v;
#pragma unroll
    for (int o = 16; o > 0; o >>= 1) s += __shfl_xor_sync(0xffffffff, s, o);
    float mean = s * (1.f / (float)NCLS);
    float d = (lane < NCLS) ? v - mean : 0.f;
    float s2 = d * d;
#pragma unroll
    for (int o = 16; o > 0; o >>= 1) s2 += __shfl_xor_sync(0xffffffff, s2, o);
    float inv = rsqrtf(s2 * (1.f / (float)NCLS) + 1e-5f);
    if (lane < NCLS) {
        float o = d * inv * mg[lane] + mb[lane];
        int gy = n >> 5, gx = n & 31;
        g_mln[(((long)b * NCLS + lane) * GS + gy) * GS + gx] = o;
    }
}

// ---------------- bilinear 32x32 -> 512x512 ---------------------------------
__global__ void __launch_bounds__(256) resize_kernel(float* __restrict__ out)
{
    const int pix = blockIdx.x * 256 + threadIdx.x;
    const int c = blockIdx.y, b = blockIdx.z;
    const int ox = pix & 511, oy = pix >> 9;
    float fx = (ox + 0.5f) * 0.0625f - 0.5f;
    float fy = (oy + 0.5f) * 0.0625f - 0.5f;
    int ix0 = (int)floorf(fx), iy0 = (int)floorf(fy);
    float wx = fx - (float)ix0, wy = fy - (float)iy0;
    int x0 = max(ix0, 0), x1 = min(ix0 + 1, GS - 1);
    int y0 = max(iy0, 0), y1 = min(iy0 + 1, GS - 1);
    const float* m = g_mln + ((long)b * NCLS + c) * GS * GS;
    float v00 = m[y0 * GS + x0], v01 = m[y0 * GS + x1];
    float v10 = m[y1 * GS + x0], v11 = m[y1 * GS + x1];
    float v = (1.f - wy) * ((1.f - wx) * v00 + wx * v01)
            +        wy  * ((1.f - wx) * v10 + wx * v11);
    out[(((long)b * NCLS + c) * IMG + oy) * IMG + ox] = v;
}

// ---------------- host orchestration ----------------------------------------
static void* sym_addr(const void* sym)
{
    void* p = nullptr;
    cudaGetSymbolAddress(&p, sym);
    return p;
}

#define SMEM_H128 ((128 * 40 + 128 * 40) * 2 * 4)   // 81920
#define SMEM_QKV  ((128 * 40 + 64 * 40) * 2 * 4)    // 61440

extern "C" void kernel_launch(void* const* d_in, const int* in_sizes, int n_in,
                              void* d_out, int out_size)
{
    (void)in_sizes; (void)n_in; (void)out_size;
    const float* x    = (const float*)d_in[0];
    const float* pdW  = (const float*)d_in[1];
    const float* pdb  = (const float*)d_in[2];
    const float* cls  = (const float*)d_in[3];
    const float* l1g  = (const float*)d_in[4];
    const float* l1b  = (const float*)d_in[5];
    const float* qW   = (const float*)d_in[6];
    const float* qb   = (const float*)d_in[7];
    const float* kW   = (const float*)d_in[8];
    const float* kb   = (const float*)d_in[9];
    const float* vW   = (const float*)d_in[10];
    const float* vb   = (const float*)d_in[11];
    const float* l2g  = (const float*)d_in[12];
    const float* l2b  = (const float*)d_in[13];
    const float* w1   = (const float*)d_in[14];
    const float* b1   = (const float*)d_in[15];
    const float* w2   = (const float*)d_in[16];
    const float* b2   = (const float*)d_in[17];
    const float* ppW  = (const float*)d_in[18];
    const float* pcW  = (const float*)d_in[19];
    const float* dg   = (const float*)d_in[20];
    const float* db   = (const float*)d_in[21];
    const float* mg   = (const float*)d_in[22];
    const float* mb   = (const float*)d_in[23];
    float* out = (float*)d_out;

    float*  gx   = (float*)sym_addr(g_x);
    __half* ghh  = (__half*)sym_addr(g_hh);
    __half* gff  = (__half*)sym_addr(g_ff);
    float*  gpt  = (float*)sym_addr(g_patches);
    float*  gcl  = (float*)sym_addr(g_cls);
    __half* wt   = (__half*)sym_addr(g_wt);
    __half* wqkv = (__half*)sym_addr(g_wqkv);

    cudaFuncSetAttribute(hgemm<128>,
                         cudaFuncAttributeMaxDynamicSharedMemorySize, SMEM_H128);
    cudaFuncSetAttribute(qkv_gemm,
                         cudaFuncAttributeMaxDynamicSharedMemorySize, SMEM_QKV);
    cudaFuncSetAttribute(fattn_kernel,
                         cudaFuncAttributeMaxDynamicSharedMemorySize, FA_SMEM);

    const dim3 blk(256);
    const dim3 tsb(32, 8);
    const int mtiles = (M_ + 127) / 128;      // 66

    // ---- one-time prep ----
    wtrans_kernel<<<dim3(FF / 32, D_ / 32), tsb>>>(w1,                 D_, FF, wt + OFF_W1_0);
    wtrans_kernel<<<dim3(FF / 32, D_ / 32), tsb>>>(w1 + (long)D_ * FF, D_, FF, wt + OFF_W1_1);
    wtrans_kernel<<<dim3(D_ / 32, FF / 32), tsb>>>(w2,                 FF, D_, wt + OFF_W2_0);
    wtrans_kernel<<<dim3(D_ / 32, FF / 32), tsb>>>(w2 + (long)FF * D_, FF, D_, wt + OFF_W2_1);
    wtrans_kernel<<<dim3(D_ / 32, D_ / 32), tsb>>>(pdW, D_, D_, wt + OFF_PD);
    wtrans_kernel<<<dim3(D_ / 32, D_ / 32), tsb>>>(ppW, D_, D_, wt + OFF_PP);
    wtrans_kernel<<<dim3(D_ / 32, D_ / 32), tsb>>>(pcW, D_, D_, wt + OFF_PC);
    qkvw_kernel<<<dim3(2, 2, 72), tsb>>>(qW, kW, vW);
    cvtx_kernel<<<(B_ * NPATCH * D_ / 2 + 255) / 256, 256>>>(x);

    // ---- x(half) @ proj_dec + b -> g_x patch rows ----
    hgemm<128><<<dim3(6, 8, B_), blk, SMEM_H128>>>(
        ghh, wt + OFF_PD, pdb, gx,
        NPATCH, D_, D_, D_, D_, D_,
        1, (long)NPATCH * D_, 0, 0, 0, (long)S_ * D_, 0, 1);
    fill_cls_kernel<<<(NCLS * D_ + 255) / 256, 256>>>(cls);

    for (int l = 0; l < 2; l++) {
        ln_kernel<<<M_ / 8, blk>>>(gx, l1g + l * D_, l1b + l * D_, ghh);

        qkv_gemm<<<dim3(1, mtiles, 36), blk, SMEM_QKV>>>(
            ghh, wqkv + (long)l * 36 * 4096,
            qb + (long)l * NH * DH, kb + (long)l * NH * DH, vb + (long)l * NH * DH);

        fattn_kernel<<<dim3((S_ + 127) / 128, BHD), blk, FA_SMEM>>>();

        ln_kernel<<<M_ / 8, blk>>>(gx, l2g + l * D_, l2b + l * D_, ghh);

        hgemm<128><<<dim3(FF / 128, mtiles, 1), blk, SMEM_H128>>>(
            ghh, wt + (l ? OFF_W1_1 : OFF_W1_0), b1 + (long)l * FF, gff,
            M_, FF, D_, D_, D_, FF,
            1, 0, 0, 0, 0, 0, 0, 1 | 2 | 16);
        hgemm<128><<<dim3(D_ / 128, mtiles, 1), blk, SMEM_H128>>>(
            gff, wt + (l ? OFF_W2_1 : OFF_W2_0), b2 + (long)l * D_, gx,
            M_, D_, FF, FF, FF, D_,
            1, 0, 0, 0, 0, 0, 0, 1 | 4);
    }

    ln_kernel<<<M_ / 8, blk>>>(gx, dg, db, ghh);

    hgemm<128><<<dim3(6, 8, B_), blk, SMEM_H128>>>(
        ghh, wt + OFF_PP, nullptr, gpt,
        NPATCH, D_, D_, D_, D_, D_,
        1, (long)S_ * D_, 0, 0, 0, (long)NPATCH * D_, 0, 0);
    hgemm<128><<<dim3(6, 1, B_), blk, SMEM_H128>>>(
        ghh + (long)NPATCH * D_, wt + OFF_PC, nullptr, gcl,
        NCLS, D_, D_, D_, D_, D_,
        1, (long)S_ * D_, 0, 0, 0, (long)NCLS * D_, 0, 0);

    l2norm_kernel<<<B_ * NPATCH / 8, blk>>>(gpt);
    l2norm_kernel<<<B_ * NCLS / 8, blk>>>(gcl);

    masks_kernel<<<dim3(NPATCH / 64, B_), blk>>>();
    maskln_kernel<<<(B_ * NPATCH) / 8, blk>>>(mg, mb);
    resize_kernel<<<dim3(IMG * IMG / 256, NCLS, B_), blk>>>(out);
}

// round 14
// speedup vs baseline: 6.2897x; 1.0149x over previous
// R14: bisection of R12's failure — keep prep_kernel + fused masks, revert
// qkv3_kernel (static-45KB-smem suspect) to R11's proven dynamic-smem qkv_gemm.
#include <cuda_runtime.h>
#include <cuda_fp16.h>
#include <math.h>
#include <stdint.h>

// ---------------- problem constants ----------------
#define B_      8
#define S_      1043
#define NPATCH  1024
#define NCLS    19
#define D_      768
#define NH      12
#define DH      64
#define FF      3072
#define GS      32
#define IMG     512
#define M_      (B_*S_)         // 8344
#define BHD     (B_*NH)         // 96
#define MPAD    8576
#define TKV     64
#define NKT     17              // ceil(S_/64)

// ---------------- scratch ----------------------------------------------------
__device__ float g_x[(size_t)M_ * D_];
__device__ __align__(128) __half g_hh[(size_t)MPAD * D_];
#define MDSEG ((size_t)M_ * D_ + 128 * D_)
__device__ __align__(128) __half g_qkvh[3 * MDSEG];   // q | k | v segments
__device__ __align__(128) __half g_ff[(size_t)MPAD * FF];
__device__ float g_patches[(size_t)B_ * NPATCH * D_];
__device__ float g_cls[(size_t)B_ * NCLS * D_];
__device__ float g_mln[(size_t)B_ * NCLS * GS * GS];

#define WTOT 11206656
__device__ __align__(128) __half g_wt[WTOT];
#define OFF_W1_0 0
#define OFF_W1_1 2359296
#define OFF_W2_0 4718592
#define OFF_W2_1 7077888
#define OFF_PD   9437184
#define OFF_PP   10027008
#define OFF_PC   10616832
// per-head transposed qkv weights: [(l*3+m)*12+h] x [e][d] 64x64
__device__ __align__(128) __half g_wqkv[72 * 4096];

// ---------------- helpers ----------------------------------------------------
__device__ __forceinline__ float gelu_exact(float v) {
    return 0.5f * v * (1.f + erff(v * 0.70710678118654752f));
}
__device__ __forceinline__ uint32_t smem_to_u32(const void* p) {
    uint32_t a;
    asm("{ .reg .u64 t; cvta.to.shared.u64 t, %1; cvt.u32.u64 %0, t; }"
        : "=r"(a) : "l"(p));
    return a;
}
__device__ __forceinline__ unsigned packh2(float a, float b) {
    __half2 h = __floats2half2_rn(a, b);
    return *(unsigned*)&h;
}
#define CP16(dst, src) \
    asm volatile("cp.async.cg.shared.global [%0], [%1], 16;" :: "r"(dst), "l"(src))
#define CPCOMMIT() asm volatile("cp.async.commit_group;")
#define CPWAIT0()  asm volatile("cp.async.wait_group 0;")
#define CPWAIT1()  asm volatile("cp.async.wait_group 1;")
#define CPWAIT2()  asm volatile("cp.async.wait_group 2;")

#define HMMA(acc, a0, a1, a2, a3, b0, b1) \
    asm volatile( \
        "mma.sync.aligned.m16n8k16.row.col.f32.f16.f16.f32 " \
        "{%0,%1,%2,%3},{%4,%5,%6,%7},{%8,%9},{%0,%1,%2,%3};" \
        : "+f"((acc)[0]), "+f"((acc)[1]), "+f"((acc)[2]), "+f"((acc)[3]) \
        : "r"(a0), "r"(a1), "r"(a2), "r"(a3), "r"(b0), "r"(b1))

#define LDSM4(r0, r1, r2, r3, addr) \
    asm volatile("ldmatrix.sync.aligned.m8n8.x4.shared.b16 {%0,%1,%2,%3}, [%4];" \
        : "=r"(r0), "=r"(r1), "=r"(r2), "=r"(r3) : "r"(addr))
#define LDSM4T(r0, r1, r2, r3, addr) \
    asm volatile("ldmatrix.sync.aligned.m8n8.x4.trans.shared.b16 {%0,%1,%2,%3}, [%4];" \
        : "=r"(r0), "=r"(r1), "=r"(r2), "=r"(r3) : "r"(addr))

// ---------------- fp16 tensor-core GEMM (MLP / projections) ------------------
// C[M,*] = A[M,K] @ B[N,K]^T. flags: 1 bias, 2 gelu, 4 +=C(fp32), 16 C half.
template<int BN>
__global__ void __launch_bounds__(256) hgemm(
    const __half* __restrict__ A, const __half* __restrict__ Bm,
    const float* __restrict__ bias, void* __restrict__ Cv,
    int M, int Nlim, int K, int lda, int ldb, int ldc,
    int HZ, long sA, long hA, long sB, long hB, long sC, long hC,
    int flags)
{
    constexpr int NT   = BN / 16;
    constexpr int ASTH = 128 * 40;
    constexpr int BSTH = BN * 40;
    constexpr int STH  = ASTH + BSTH;
    extern __shared__ __half smh[];

    const int z = blockIdx.z;
    A  += (long)(z / HZ) * sA + (long)(z % HZ) * hA;
    Bm += (long)(z / HZ) * sB + (long)(z % HZ) * hB;

    const int tid = threadIdx.x, warp = tid >> 5, lane = tid & 31;
    const int wm = warp & 3, wn = warp >> 2;
    const int l4 = lane >> 2, lm = lane & 3;
    const int m0 = blockIdx.y * 128, n0 = blockIdx.x * BN;
    const uint32_t sb = smem_to_u32(smh);
    const int nch = K >> 5;

    const int arow = (lane & 15), acol8 = (lane >> 4) * 8;
    const int bn_l = ((lane >> 4) & 1) * 8 + (lane & 7);
    const int bc_l = ((lane >> 3) & 1) * 8;

    auto issue = [&](int kc) {
        if (kc < nch) {
            const int st = kc & 3;
            const uint32_t ab = sb + (uint32_t)(st * STH) * 2u;
            const uint32_t bb = ab + (uint32_t)ASTH * 2u;
            const int k0 = kc << 5;
            const __half* Ap = A + (long)m0 * lda + k0;
#pragma unroll
            for (int i = 0; i < 2; i++) {
                int q = i * 256 + tid;
                int row = q >> 2, seg = (q & 3) * 8;
                CP16(ab + (uint32_t)(row * 40 + seg) * 2u,
                     Ap + (long)row * lda + seg);
            }
            const __half* Bp = Bm + (long)n0 * ldb + k0;
#pragma unroll
            for (int i = 0; i < BN / 64; i++) {
                int q = i * 256 + tid;
                int row = q >> 2, seg = (q & 3) * 8;
                CP16(bb + (uint32_t)(row * 40 + seg) * 2u,
                     Bp + (long)row * ldb + seg);
            }
        }
        CPCOMMIT();
    };

    float acc[2][NT][4];
#pragma unroll
    for (int i = 0; i < 2; i++)
#pragma unroll
        for (int j = 0; j < NT; j++)
#pragma unroll
            for (int c = 0; c < 4; c++) acc[i][j][c] = 0.f;

    issue(0); issue(1); issue(2);

    for (int c = 0; c < nch; c++) {
        CPWAIT2();
        __syncthreads();
        issue(c + 3);

        const uint32_t as = sb + (uint32_t)((c & 3) * STH) * 2u;
        const uint32_t bs = as + (uint32_t)ASTH * 2u;
#pragma unroll
        for (int kk = 0; kk < 32; kk += 16) {
            unsigned af[2][4];
#pragma unroll
            for (int i = 0; i < 2; i++) {
                uint32_t addr = as + (uint32_t)((wm * 32 + i * 16 + arow) * 40
                                                + kk + acol8) * 2u;
                LDSM4(af[i][0], af[i][1], af[i][2], af[i][3], addr);
            }
#pragma unroll
            for (int g = 0; g < NT / 2; g++) {
                unsigned b0, b1, b2, b3;
                uint32_t addr = bs + (uint32_t)((wn * (BN / 2) + g * 16 + bn_l) * 40
                                                + kk + bc_l) * 2u;
                LDSM4(b0, b1, b2, b3, addr);
#pragma unroll
                for (int i = 0; i < 2; i++) {
                    HMMA(acc[i][2 * g],     af[i][0], af[i][1], af[i][2], af[i][3], b0, b1);
                    HMMA(acc[i][2 * g + 1], af[i][0], af[i][1], af[i][2], af[i][3], b2, b3);
                }
            }
        }
    }

    float*  Cf = (float*)Cv  + (long)(z / HZ) * sC + (long)(z % HZ) * hC;
    __half* Ch = (__half*)Cv + (long)(z / HZ) * sC + (long)(z % HZ) * hC;
#pragma unroll
    for (int i = 0; i < 2; i++)
#pragma unroll
        for (int j = 0; j < NT; j++)
#pragma unroll
            for (int h = 0; h < 2; h++) {
                int row = m0 + wm * 32 + i * 16 + l4 + h * 8;
                if (row >= M) continue;
                int col = n0 + wn * (BN / 2) + j * 8 + lm * 2;
                if (col >= Nlim) continue;
                float v0 = acc[i][j][h * 2 + 0];
                float v1 = acc[i][j][h * 2 + 1];
                bool has1 = (col + 1 < Nlim);
                if (flags & 1) {
                    v0 += bias[col];
                    if (has1) v1 += bias[col + 1];
                }
                if (flags & 2)  { v0 = gelu_exact(v0); v1 = gelu_exact(v1); }
                if (flags & 16) {
                    __half* hp = Ch + (long)row * ldc + col;
                    if (has1) *(__half2*)hp = __floats2half2_rn(v0, v1);
                    else      hp[0] = __float2half_rn(v0);
                } else {
                    float* cp = Cf + (long)row * ldc + col;
                    if (has1) {
                        if (flags & 4) { float2 o = *(float2*)cp; v0 += o.x; v1 += o.y; }
                        float2 st; st.x = v0; st.y = v1;
                        *(float2*)cp = st;
                    } else {
                        if (flags & 4) v0 += cp[0];
                        cp[0] = v0;
                    }
                }
            }
}

// ---------------- fused qkv GEMM (R11-proven): z = m*12+h --------------------
#define QKV_ASTH (128 * 40)
#define QKV_BSTH (64 * 40)
#define QKV_STH  (QKV_ASTH + QKV_BSTH)
__global__ void __launch_bounds__(256) qkv_gemm(
    const __half* __restrict__ A, const __half* __restrict__ Wl,
    const float* __restrict__ qb, const float* __restrict__ kb,
    const float* __restrict__ vb)
{
    extern __shared__ __half smh[];
    const int z = blockIdx.z;
    const int m = z / NH, h = z % NH;
    const __half* Bm = Wl + (long)z * 4096;      // [64 e][64 d]
    const float* bias = (m == 0 ? qb : m == 1 ? kb : vb) + h * DH;
    const float scale = (m == 0) ? 0.125f : 1.f;
    __half* C = g_qkvh + (size_t)m * MDSEG + h * DH;

    const int tid = threadIdx.x, warp = tid >> 5, lane = tid & 31;
    const int wm = warp & 3, wn = warp >> 2;
    const int l4 = lane >> 2, lm = lane & 3;
    const int m0 = blockIdx.y * 128;
    const uint32_t sb = smem_to_u32(smh);

    const int arow = (lane & 15), acol8 = (lane >> 4) * 8;
    const int bn_l = ((lane >> 4) & 1) * 8 + (lane & 7);
    const int bc_l = ((lane >> 3) & 1) * 8;

    auto issue = [&](int kc) {
        if (kc < 2) {
            const int st = kc & 3;
            const uint32_t ab = sb + (uint32_t)(st * QKV_STH) * 2u;
            const uint32_t bb = ab + (uint32_t)QKV_ASTH * 2u;
            const int k0 = kc << 5;
            const __half* Ap = A + (long)m0 * D_ + h * DH + k0;   // head slice
#pragma unroll
            for (int i = 0; i < 2; i++) {
                int q = i * 256 + tid;
                int row = q >> 2, seg = (q & 3) * 8;
                CP16(ab + (uint32_t)(row * 40 + seg) * 2u,
                     Ap + (long)row * D_ + seg);
            }
            {
                int row = tid >> 2, seg = (tid & 3) * 8;
                CP16(bb + (uint32_t)(row * 40 + seg) * 2u,
                     Bm + (long)row * DH + k0 + seg);
            }
        }
        CPCOMMIT();
    };

    float acc[2][4][4];
#pragma unroll
    for (int i = 0; i < 2; i++)
#pragma unroll
        for (int j = 0; j < 4; j++)
#pragma unroll
            for (int c = 0; c < 4; c++) acc[i][j][c] = 0.f;

    issue(0); issue(1); issue(2);

    for (int c = 0; c < 2; c++) {
        CPWAIT2();
        __syncthreads();
        issue(c + 3);
        const uint32_t as = sb + (uint32_t)((c & 3) * QKV_STH) * 2u;
        const uint32_t bs = as + (uint32_t)QKV_ASTH * 2u;
#pragma unroll
        for (int kk = 0; kk < 32; kk += 16) {
            unsigned af[2][4];
#pragma unroll
            for (int i = 0; i < 2; i++) {
                uint32_t addr = as + (uint32_t)((wm * 32 + i * 16 + arow) * 40
                                                + kk + acol8) * 2u;
                LDSM4(af[i][0], af[i][1], af[i][2], af[i][3], addr);
            }
#pragma unroll
            for (int g = 0; g < 2; g++) {
                unsigned b0, b1, b2, b3;
                uint32_t addr = bs + (uint32_t)((wn * 32 + g * 16 + bn_l) * 40
                                                + kk + bc_l) * 2u;
                LDSM4(b0, b1, b2, b3, addr);
#pragma unroll
                for (int i = 0; i < 2; i++) {
                    HMMA(acc[i][2 * g],     af[i][0], af[i][1], af[i][2], af[i][3], b0, b1);
                    HMMA(acc[i][2 * g + 1], af[i][0], af[i][1], af[i][2], af[i][3], b2, b3);
                }
            }
        }
    }

#pragma unroll
    for (int i = 0; i < 2; i++)
#pragma unroll
        for (int j = 0; j < 4; j++)
#pragma unroll
            for (int hh = 0; hh < 2; hh++) {
                int row = m0 + wm * 32 + i * 16 + l4 + hh * 8;
                if (row >= M_) continue;
                int col = wn * 32 + j * 8 + lm * 2;
                float v0 = (acc[i][j][hh * 2 + 0] + bias[col])     * scale;
                float v1 = (acc[i][j][hh * 2 + 1] + bias[col + 1]) * scale;
                *(__half2*)(C + (long)row * D_ + col) = __floats2half2_rn(v0, v1);
            }
}

// ---------------- fused flash attention (V via trans-ldmatrix) --------------
#define FA_QS 0
#define FA_KS (128 * 72)
#define FA_VS (128 * 72 + 2 * 64 * 72)
#define FA_SMEM ((128 * 72 + 4 * 64 * 72) * 2)
__global__ void __launch_bounds__(256) fattn_kernel()
{
    extern __shared__ __half sh[];
    const int z = blockIdx.y;
    const int b = z / NH, hd = z % NH;
    const int m0 = blockIdx.x * 128;
    const int tid = threadIdx.x, warp = tid >> 5, lane = tid & 31;
    const int l4 = lane >> 2, lm = lane & 3;
    const uint32_t sb = smem_to_u32(sh);

    const __half* Qg = g_qkvh + 0 * MDSEG + ((long)b * S_ + m0) * D_ + hd * DH;
    const __half* Kg = g_qkvh + 1 * MDSEG + (long)b * S_ * D_ + hd * DH;
    const __half* Vg = g_qkvh + 2 * MDSEG + (long)b * S_ * D_ + hd * DH;

    const int arow = (lane & 15), acol8 = (lane >> 4) * 8;
    const int bn_l = ((lane >> 4) & 1) * 8 + (lane & 7);
    const int bc_l = ((lane >> 3) & 1) * 8;
    const int tvr = ((lane >> 3) & 1) * 8 + (lane & 7);
    const int tvc = ((lane >> 4) & 1) * 8;

    auto loadKV = [&](int kt) {
        const int st = kt & 1;
        const __half* Kp = Kg + (long)(kt * TKV) * D_;
        const __half* Vp = Vg + (long)(kt * TKV) * D_;
        const uint32_t kb = sb + (uint32_t)(FA_KS + st * 64 * 72) * 2u;
        const uint32_t vb = sb + (uint32_t)(FA_VS + st * 64 * 72) * 2u;
#pragma unroll
        for (int i = 0; i < 2; i++) {
            int q = i * 256 + tid;
            int row = q >> 3, seg = (q & 7) * 8;
            CP16(kb + (uint32_t)(row * 72 + seg) * 2u, Kp + (long)row * D_ + seg);
        }
#pragma unroll
        for (int i = 0; i < 2; i++) {
            int q = i * 256 + tid;
            int row = q >> 3, seg = (q & 7) * 8;
            CP16(vb + (uint32_t)(row * 72 + seg) * 2u, Vp + (long)row * D_ + seg);
        }
    };

#pragma unroll
    for (int i = 0; i < 4; i++) {
        int q = i * 256 + tid;
        int row = q >> 3, seg = (q & 7) * 8;
        CP16(sb + (uint32_t)(FA_QS + row * 72 + seg) * 2u, Qg + (long)row * D_ + seg);
    }
    loadKV(0);
    CPCOMMIT();
    CPWAIT0();
    __syncthreads();

    unsigned qa[4][4];
#pragma unroll
    for (int kc = 0; kc < 4; kc++) {
        uint32_t addr = sb + (uint32_t)(FA_QS + (warp * 16 + arow) * 72
                                        + kc * 16 + acol8) * 2u;
        LDSM4(qa[kc][0], qa[kc][1], qa[kc][2], qa[kc][3], addr);
    }

    float oacc[8][4];
#pragma unroll
    for (int j = 0; j < 8; j++)
#pragma unroll
        for (int c = 0; c < 4; c++) oacc[j][c] = 0.f;
    float mr0 = -1e30f, mr1 = -1e30f, lr0 = 0.f, lr1 = 0.f;

    for (int kt = 0; kt < NKT; kt++) {
        __syncthreads();
        if (kt + 1 < NKT) { loadKV(kt + 1); CPCOMMIT(); CPWAIT1(); }
        else              { CPWAIT0(); }
        __syncthreads();

        const uint32_t ks = sb + (uint32_t)(FA_KS + (kt & 1) * 64 * 72) * 2u;
        const uint32_t vs = sb + (uint32_t)(FA_VS + (kt & 1) * 64 * 72) * 2u;

        float sacc[8][4];
#pragma unroll
        for (int j = 0; j < 8; j++)
#pragma unroll
            for (int c = 0; c < 4; c++) sacc[j][c] = 0.f;
#pragma unroll
        for (int kc = 0; kc < 4; kc++)
#pragma unroll
            for (int g = 0; g < 4; g++) {
                unsigned b0, b1, b2, b3;
                uint32_t addr = ks + (uint32_t)((g * 16 + bn_l) * 72
                                                + kc * 16 + bc_l) * 2u;
                LDSM4(b0, b1, b2, b3, addr);
                HMMA(sacc[2 * g],     qa[kc][0], qa[kc][1], qa[kc][2], qa[kc][3], b0, b1);
                HMMA(sacc[2 * g + 1], qa[kc][0], qa[kc][1], qa[kc][2], qa[kc][3], b2, b3);
            }

        const int base = kt * TKV;
        if (base + TKV > S_) {
#pragma unroll
            for (int j = 0; j < 8; j++) {
                int c0 = base + j * 8 + 2 * lm;
                if (c0 >= S_)     { sacc[j][0] = -1e30f; sacc[j][2] = -1e30f; }
                if (c0 + 1 >= S_) { sacc[j][1] = -1e30f; sacc[j][3] = -1e30f; }
            }
        }

        float tm0 = -1e30f, tm1 = -1e30f;
#pragma unroll
        for (int j = 0; j < 8; j++) {
            tm0 = fmaxf(tm0, fmaxf(sacc[j][0], sacc[j][1]));
            tm1 = fmaxf(tm1, fmaxf(sacc[j][2], sacc[j][3]));
        }
        tm0 = fmaxf(tm0, __shfl_xor_sync(0xffffffff, tm0, 1));
        tm0 = fmaxf(tm0, __shfl_xor_sync(0xffffffff, tm0, 2));
        tm1 = fmaxf(tm1, __shfl_xor_sync(0xffffffff, tm1, 1));
        tm1 = fmaxf(tm1, __shfl_xor_sync(0xffffffff, tm1, 2));
        float mn0 = fmaxf(mr0, tm0), mn1 = fmaxf(mr1, tm1);
        float sc0 = __expf(mr0 - mn0), sc1 = __expf(mr1 - mn1);
        float rs0 = 0.f, rs1 = 0.f;
#pragma unroll
        for (int j = 0; j < 8; j++) {
            sacc[j][0] = __expf(sacc[j][0] - mn0);
            sacc[j][1] = __expf(sacc[j][1] - mn0);
            sacc[j][2] = __expf(sacc[j][2] - mn1);
            sacc[j][3] = __expf(sacc[j][3] - mn1);
            rs0 += sacc[j][0] + sacc[j][1];
            rs1 += sacc[j][2] + sacc[j][3];
        }
        rs0 += __shfl_xor_sync(0xffffffff, rs0, 1);
        rs0 += __shfl_xor_sync(0xffffffff, rs0, 2);
        rs1 += __shfl_xor_sync(0xffffffff, rs1, 1);
        rs1 += __shfl_xor_sync(0xffffffff, rs1, 2);
        lr0 = lr0 * sc0 + rs0;
        lr1 = lr1 * sc1 + rs1;
        mr0 = mn0; mr1 = mn1;
#pragma unroll
        for (int j = 0; j < 8; j++) {
            oacc[j][0] *= sc0; oacc[j][1] *= sc0;
            oacc[j][2] *= sc1; oacc[j][3] *= sc1;
        }

#pragma unroll
        for (int kc2 = 0; kc2 < 4; kc2++) {
            unsigned pa0 = packh2(sacc[2 * kc2][0],     sacc[2 * kc2][1]);
            unsigned pa1 = packh2(sacc[2 * kc2][2],     sacc[2 * kc2][3]);
            unsigned pa2 = packh2(sacc[2 * kc2 + 1][0], sacc[2 * kc2 + 1][1]);
            unsigned pa3 = packh2(sacc[2 * kc2 + 1][2], sacc[2 * kc2 + 1][3]);
#pragma unroll
            for (int g = 0; g < 4; g++) {
                unsigned b0, b1, b2, b3;
                uint32_t addr = vs + (uint32_t)((kc2 * 16 + tvr) * 72
                                                + g * 16 + tvc) * 2u;
                LDSM4T(b0, b1, b2, b3, addr);
                HMMA(oacc[2 * g],     pa0, pa1, pa2, pa3, b0, b1);
                HMMA(oacc[2 * g + 1], pa0, pa1, pa2, pa3, b2, b3);
            }
        }
    }

    const int q0 = m0 + warp * 16 + l4;
    const int q1 = q0 + 8;
    const float inv0 = 1.f / lr0, inv1 = 1.f / lr1;
#pragma unroll
    for (int jd = 0; jd < 8; jd++) {
        int d = hd * DH + jd * 8 + 2 * lm;
        if (q0 < S_) {
            float* p = g_x + ((long)b * S_ + q0) * D_ + d;
            float2 o = *(float2*)p;
            o.x += oacc[jd][0] * inv0;
            o.y += oacc[jd][1] * inv0;
            *(float2*)p = o;
        }
        if (q1 < S_) {
            float* p = g_x + ((long)b * S_ + q1) * D_ + d;
            float2 o = *(float2*)p;
            o.x += oacc[jd][2] * inv1;
            o.y += oacc[jd][3] * inv1;
            *(float2*)p = o;
        }
    }
}

// ---------------- one-shot weight prep (all transposes) ---------------------
__global__ void prep_kernel(
    const float* __restrict__ w1, const float* __restrict__ w2,
    const float* __restrict__ pdW, const float* __restrict__ ppW,
    const float* __restrict__ pcW,
    const float* __restrict__ qW, const float* __restrict__ kW,
    const float* __restrict__ vW)
{
    __shared__ float t[32][33];
    const int bid = blockIdx.x;
    const int tx = threadIdx.x, ty = threadIdx.y;

    if (bid < 10944) {
        const float* src; __half* dst; int K, N, local;
        if (bid < 2304)       { src = w1;                 dst = g_wt + OFF_W1_0; K = 768;  N = 3072; local = bid; }
        else if (bid < 4608)  { src = w1 + (long)D_ * FF; dst = g_wt + OFF_W1_1; K = 768;  N = 3072; local = bid - 2304; }
        else if (bid < 6912)  { src = w2;                 dst = g_wt + OFF_W2_0; K = 3072; N = 768;  local = bid - 4608; }
        else if (bid < 9216)  { src = w2 + (long)FF * D_; dst = g_wt + OFF_W2_1; K = 3072; N = 768;  local = bid - 6912; }
        else if (bid < 9792)  { src = pdW;                dst = g_wt + OFF_PD;   K = 768;  N = 768;  local = bid - 9216; }
        else if (bid < 10368) { src = ppW;                dst = g_wt + OFF_PP;   K = 768;  N = 768;  local = bid - 9792; }
        else                  { src = pcW;                dst = g_wt + OFF_PC;   K = 768;  N = 768;  local = bid - 10368; }
        const int nb = N / 32;
        const int n0 = (local % nb) * 32, k0 = (local / nb) * 32;
#pragma unroll
        for (int i = 0; i < 32; i += 8)
            t[ty + i][tx] = src[(long)(k0 + ty + i) * N + n0 + tx];
        __syncthreads();
#pragma unroll
        for (int i = 0; i < 32; i += 8)
            dst[(long)(n0 + ty + i) * K + k0 + tx] = __float2half_rn(t[tx][ty + i]);
    } else {
        const int local = bid - 10944;           // 0..287
        const int z = local >> 2, tile = local & 3;
        const int l = z / 36, rr = z % 36, m = rr / 12, h = rr % 12;
        const float* src = (m == 0 ? qW : m == 1 ? kW : vW)
                           + ((long)(l * 12 + h) * 64) * 64;
        __half* dst = g_wqkv + (long)z * 4096;
        const int e0 = (tile & 1) * 32, d0 = (tile >> 1) * 32;
#pragma unroll
        for (int i = 0; i < 32; i += 8)
            t[ty + i][tx] = src[(d0 + ty + i) * 64 + e0 + tx];
        __syncthreads();
#pragma unroll
        for (int i = 0; i < 32; i += 8)
            dst[(e0 + ty + i) * 64 + d0 + tx] = __float2half_rn(t[tx][ty + i]);
    }
}

// ---------------- x (fp32) -> g_hh (half) ------------------------------------
__global__ void cvtx_kernel(const float* __restrict__ x)
{
    long i = ((long)blockIdx.x * 256 + threadIdx.x) * 2;
    if (i >= (long)B_ * NPATCH * D_) return;
    float2 v = *(const float2*)(x + i);
    *(__half2*)(g_hh + i) = __floats2half2_rn(v.x, v.y);
}

// ---------------- LayerNorm, warp-per-row, half output only -----------------
__global__ void __launch_bounds__(256) ln_kernel(
    const float* __restrict__ x, const float* __restrict__ g,
    const float* __restrict__ bta, __half* __restrict__ outh)
{
    const int warp = threadIdx.x >> 5, lane = threadIdx.x & 31;
    const long r = (long)blockIdx.x * 8 + warp;
    const float* xr = x + r * D_;
    float v[24];
    float s = 0.f, s2 = 0.f;
#pragma unroll
    for (int i = 0; i < 6; i++) {
        float4 t = *(const float4*)(xr + i * 128 + lane * 4);
        v[i * 4 + 0] = t.x; v[i * 4 + 1] = t.y;
        v[i * 4 + 2] = t.z; v[i * 4 + 3] = t.w;
        s  += t.x + t.y + t.z + t.w;
        s2 += t.x * t.x + t.y * t.y + t.z * t.z + t.w * t.w;
    }
#pragma unroll
    for (int o = 16; o > 0; o >>= 1) {
        s  += __shfl_xor_sync(0xffffffff, s, o);
        s2 += __shfl_xor_sync(0xffffffff, s2, o);
    }
    float mean = s * (1.f / 768.f);
    float var  = s2 * (1.f / 768.f) - mean * mean;
    float inv  = rsqrtf(var + 1e-5f);
    __half* hrow = outh + r * D_;
#pragma unroll
    for (int i = 0; i < 6; i++) {
        int c = i * 128 + lane * 4;
        float4 gg = *(const float4*)(g + c);
        float4 bb = *(const float4*)(bta + c);
        float o0 = (v[i * 4 + 0] - mean) * inv * gg.x + bb.x;
        float o1 = (v[i * 4 + 1] - mean) * inv * gg.y + bb.y;
        float o2 = (v[i * 4 + 2] - mean) * inv * gg.z + bb.z;
        float o3 = (v[i * 4 + 3] - mean) * inv * gg.w + bb.w;
        uint2 st;
        st.x = packh2(o0, o1);
        st.y = packh2(o2, o3);
        *(uint2*)(hrow + c) = st;
    }
}

// ---------------- L2 row normalize (in place), warp-per-row -----------------
__global__ void __launch_bounds__(256) l2norm_kernel(float* __restrict__ x)
{
    const int warp = threadIdx.x >> 5, lane = threadIdx.x & 31;
    const long r = (long)blockIdx.x * 8 + warp;
    float* xr = x + r * D_;
    float v[24];
    float s2 = 0.f;
#pragma unroll
    for (int i = 0; i < 6; i++) {
        float4 t = *(const float4*)(xr + i * 128 + lane * 4);
        v[i * 4 + 0] = t.x; v[i * 4 + 1] = t.y;
        v[i * 4 + 2] = t.z; v[i * 4 + 3] = t.w;
        s2 += t.x * t.x + t.y * t.y + t.z * t.z + t.w * t.w;
    }
#pragma unroll
    for (int o = 16; o > 0; o >>= 1)
        s2 += __shfl_xor_sync(0xffffffff, s2, o);
    float inv = rsqrtf(s2);
#pragma unroll
    for (int i = 0; i < 6; i++) {
        float4 t;
        t.x = v[i * 4 + 0] * inv; t.y = v[i * 4 + 1] * inv;
        t.z = v[i * 4 + 2] * inv; t.w = v[i * 4 + 3] * inv;
        *(float4*)(xr + i * 128 + lane * 4) = t;
    }
}

// ---------------- broadcast cls_emb into g_x cls rows -----------------------
__global__ void fill_cls_kernel(const float* __restrict__ cls_emb)
{
    int idx = blockIdx.x * 256 + threadIdx.x;
    if (idx >= NCLS * D_) return;
    float v = cls_emb[idx];
    int c = idx / D_, d = idx % D_;
#pragma unroll
    for (int b = 0; b < B_; b++)
        g_x[(long)(b * S_ + NPATCH + c) * D_ + d] = v;
}

// ---------------- masks + mask-LN fused -------------------------------------
__global__ void __launch_bounds__(256) masks_kernel(
    const float* __restrict__ mg, const float* __restrict__ mb)
{
    __shared__ float pt[64][128];
    __shared__ float cs[NCLS][128];
    __shared__ float sm_m[64][20];
    const int b = blockIdx.y;
    const int t0 = blockIdx.x * 64;
    const int tid = threadIdx.x;
    float acc[5];
#pragma unroll
    for (int i = 0; i < 5; i++) acc[i] = 0.f;

    for (int d0 = 0; d0 < D_; d0 += 128) {
#pragma unroll
        for (int i = 0; i < 8; i++) {
            int f = i * 256 + tid;
            int row = f >> 5, c4 = (f & 31) * 4;
            *(float4*)&pt[row][c4] =
                *(const float4*)(g_patches + (long)(b * NPATCH + t0 + row) * D_ + d0 + c4);
        }
        for (int f = tid; f < NCLS * 32; f += 256) {
            int row = f >> 5, c4 = (f & 31) * 4;
            *(float4*)&cs[row][c4] =
                *(const float4*)(g_cls + (long)(b * NCLS + row) * D_ + d0 + c4);
        }
        __syncthreads();
#pragma unroll
        for (int i = 0; i < 5; i++) {
            int p = i * 256 + tid;
            if (p < 64 * NCLS) {
                int tok = p / NCLS, c = p % NCLS;
                float s = acc[i];
#pragma unroll 8
                for (int d = 0; d < 128; d++)
                    s = fmaf(pt[tok][d], cs[c][d], s);
                acc[i] = s;
            }
        }
        __syncthreads();
    }
#pragma unroll
    for (int i = 0; i < 5; i++) {
        int p = i * 256 + tid;
        if (p < 64 * NCLS) sm_m[p / NCLS][p % NCLS] = acc[i];
    }
    __syncthreads();

    if (tid < 64) {
        const int n = t0 + tid;
        float mean = 0.f;
#pragma unroll
        for (int c = 0; c < NCLS; c++) mean += sm_m[tid][c];
        mean *= (1.f / (float)NCLS);
        float var = 0.f;
#pragma unroll
        for (int c = 0; c < NCLS; c++) {
            float d = sm_m[tid][c] - mean;
            var += d * d;
        }
        var *= (1.f / (float)NCLS);
        float inv = rsqrtf(var + 1e-5f);
        const int gy = n >> 5, gx = n & 31;
#pragma unroll
        for (int c = 0; c < NCLS; c++)
            g_mln[(((long)b * NCLS + c) * GS + gy) * GS + gx] =
                (sm_m[tid][c] - mean) * inv * mg[c] + mb[c];
    }
}

// ---------------- bilinear 32x32 -> 512x512 ---------------------------------
__global__ void __launch_bounds__(256) resize_kernel(float* __restrict__ out)
{
    const int pix = blockIdx.x * 256 + threadIdx.x;
    const int c = blockIdx.y, b = blockIdx.z;
    const int ox = pix & 511, oy = pix >> 9;
    float fx = (ox + 0.5f) * 0.0625f - 0.5f;
    float fy = (oy + 0.5f) * 0.0625f - 0.5f;
    int ix0 = (int)floorf(fx), iy0 = (int)floorf(fy);
    float wx = fx - (float)ix0, wy = fy - (float)iy0;
    int x0 = max(ix0, 0), x1 = min(ix0 + 1, GS - 1);
    int y0 = max(iy0, 0), y1 = min(iy0 + 1, GS - 1);
    const float* m = g_mln + ((long)b * NCLS + c) * GS * GS;
    float v00 = m[y0 * GS + x0], v01 = m[y0 * GS + x1];
    float v10 = m[y1 * GS + x0], v11 = m[y1 * GS + x1];
    float v = (1.f - wy) * ((1.f - wx) * v00 + wx * v01)
            +        wy  * ((1.f - wx) * v10 + wx * v11);
    out[(((long)b * NCLS + c) * IMG + oy) * IMG + ox] = v;
}

// ---------------- host orchestration ----------------------------------------
static void* sym_addr(const void* sym)
{
    void* p = nullptr;
    cudaGetSymbolAddress(&p, sym);
    return p;
}

#define SMEM_H128 ((128 * 40 + 128 * 40) * 2 * 4)   // 81920
#define SMEM_QKV  ((128 * 40 + 64 * 40) * 2 * 4)    // 61440

extern "C" void kernel_launch(void* const* d_in, const int* in_sizes, int n_in,
                              void* d_out, int out_size)
{
    (void)in_sizes; (void)n_in; (void)out_size;
    const float* x    = (const float*)d_in[0];
    const float* pdW  = (const float*)d_in[1];
    const float* pdb  = (const float*)d_in[2];
    const float* cls  = (const float*)d_in[3];
    const float* l1g  = (const float*)d_in[4];
    const float* l1b  = (const float*)d_in[5];
    const float* qW   = (const float*)d_in[6];
    const float* qb   = (const float*)d_in[7];
    const float* kW   = (const float*)d_in[8];
    const float* kb   = (const float*)d_in[9];
    const float* vW   = (const float*)d_in[10];
    const float* vb   = (const float*)d_in[11];
    const float* l2g  = (const float*)d_in[12];
    const float* l2b  = (const float*)d_in[13];
    const float* w1   = (const float*)d_in[14];
    const float* b1   = (const float*)d_in[15];
    const float* w2   = (const float*)d_in[16];
    const float* b2   = (const float*)d_in[17];
    const float* ppW  = (const float*)d_in[18];
    const float* pcW  = (const float*)d_in[19];
    const float* dg   = (const float*)d_in[20];
    const float* db   = (const float*)d_in[21];
    const float* mg   = (const float*)d_in[22];
    const float* mb   = (const float*)d_in[23];
    float* out = (float*)d_out;

    float*  gx   = (float*)sym_addr(g_x);
    __half* ghh  = (__half*)sym_addr(g_hh);
    __half* gff  = (__half*)sym_addr(g_ff);
    float*  gpt  = (float*)sym_addr(g_patches);
    float*  gcl  = (float*)sym_addr(g_cls);
    __half* wt   = (__half*)sym_addr(g_wt);
    __half* wqkv = (__half*)sym_addr(g_wqkv);

    cudaFuncSetAttribute(hgemm<128>,
                         cudaFuncAttributeMaxDynamicSharedMemorySize, SMEM_H128);
    cudaFuncSetAttribute(qkv_gemm,
                         cudaFuncAttributeMaxDynamicSharedMemorySize, SMEM_QKV);
    cudaFuncSetAttribute(fattn_kernel,
                         cudaFuncAttributeMaxDynamicSharedMemorySize, FA_SMEM);

    const dim3 blk(256);
    const dim3 tsb(32, 8);
    const int mtiles = (M_ + 127) / 128;      // 66

    // ---- one-shot prep: all weight transposes + x->half ----
    prep_kernel<<<11232, tsb>>>(w1, w2, pdW, ppW, pcW, qW, kW, vW);
    cvtx_kernel<<<(B_ * NPATCH * D_ / 2 + 255) / 256, 256>>>(x);

    // ---- x(half) @ proj_dec + b -> g_x patch rows ----
    hgemm<128><<<dim3(6, 8, B_), blk, SMEM_H128>>>(
        ghh, wt + OFF_PD, pdb, gx,
        NPATCH, D_, D_, D_, D_, D_,
        1, (long)NPATCH * D_, 0, 0, 0, (long)S_ * D_, 0, 1);
    fill_cls_kernel<<<(NCLS * D_ + 255) / 256, 256>>>(cls);

    for (int l = 0; l < 2; l++) {
        ln_kernel<<<M_ / 8, blk>>>(gx, l1g + l * D_, l1b + l * D_, ghh);

        qkv_gemm<<<dim3(1, mtiles, 36), blk, SMEM_QKV>>>(
            ghh, wqkv + (long)l * 36 * 4096,
            qb + (long)l * NH * DH, kb + (long)l * NH * DH, vb + (long)l * NH * DH);

        fattn_kernel<<<dim3((S_ + 127) / 128, BHD), blk, FA_SMEM>>>();

        ln_kernel<<<M_ / 8, blk>>>(gx, l2g + l * D_, l2b + l * D_, ghh);

        hgemm<128><<<dim3(FF / 128, mtiles, 1), blk, SMEM_H128>>>(
            ghh, wt + (l ? OFF_W1_1 : OFF_W1_0), b1 + (long)l * FF, gff,
            M_, FF, D_, D_, D_, FF,
            1, 0, 0, 0, 0, 0, 0, 1 | 2 | 16);
        hgemm<128><<<dim3(D_ / 128, mtiles, 1), blk, SMEM_H128>>>(
            gff, wt + (l ? OFF_W2_1 : OFF_W2_0), b2 + (long)l * D_, gx,
            M_, D_, FF, FF, FF, D_,
            1, 0, 0, 0, 0, 0, 0, 1 | 4);
    }

    ln_kernel<<<M_ / 8, blk>>>(gx, dg, db, ghh);

    hgemm<128><<<dim3(6, 8, B_), blk, SMEM_H128>>>(
        ghh, wt + OFF_PP, nullptr, gpt,
        NPATCH, D_, D_, D_, D_, D_,
        1, (long)S_ * D_, 0, 0, 0, (long)NPATCH * D_, 0, 0);
    hgemm<128><<<dim3(6, 1, B_), blk, SMEM_H128>>>(
        ghh + (long)NPATCH * D_, wt + OFF_PC, nullptr, gcl,
        NCLS, D_, D_, D_, D_, D_,
        1, (long)S_ * D_, 0, 0, 0, (long)NCLS * D_, 0, 0);

    l2norm_kernel<<<B_ * NPATCH / 8, blk>>>(gpt);
    l2norm_kernel<<<B_ * NCLS / 8, blk>>>(gcl);

    masks_kernel<<<dim3(NPATCH / 64, B_), blk>>>(mg, mb);
    resize_kernel<<<dim3(IMG * IMG / 256, NCLS, B_), blk>>>(out);
}